// round 7
// baseline (speedup 1.0000x reference)
#include <cuda_runtime.h>
#include <math.h>

// ---------------------------------------------------------------------------
// DeformationTrajectoryAttentionBlock — fp32; f32x2 FMA GEMMs, conflict-free.
// B=1, F=4, H=6, D=384, G=16, S=256, N=1024, HD=64, IMG=32, MLP_HID=1536
// ---------------------------------------------------------------------------

#define SCALE 0.125f
#define LN_EPS 1e-5f
typedef unsigned long long ull;

#define OFF_TOK    0LL          // 1024*384
#define OFF_XN     393216LL
#define OFF_QKV    786432LL     // 1024*1152
#define OFF_VW     1966080LL    // 6*1024*768 (6144 x 768)
#define OFF_QK     6684672LL    // 6*1024*1024 ; reused as Lg[hg=0] after ta
#define OFF_TA     12976128LL   // 1024*256*24
#define OFF_XD     19267584LL
#define OFF_Q2     19660800LL
#define OFF_LG     20054016LL   // 1024*6144 ; Lg[hg=1]
#define LG_STRIDE  13369344LL   // OFF_LG - OFF_QK
#define OFF_OPART  26345472LL   // 24 * 1024*64
#define OFF_O      27918336LL
#define OFF_H1     28311552LL
#define OFF_HN     28704768LL
#define OFF_MLP    29097984LL   // 1024*1536
#define OFF_H2     30670848LL
#define SCRATCH_FLOATS 31064064LL

static __device__ float g_scratch[SCRATCH_FLOATS];

__device__ __forceinline__ void fma2(ull& acc, ull a, ull b)
{
    asm("fma.rn.f32x2 %0, %1, %2, %0;" : "+l"(acc) : "l"(a), "l"(b));
}
__device__ __forceinline__ void unpack2(ull v, float& x, float& y)
{
    asm("mov.b64 {%0, %1}, %2;" : "=f"(x), "=f"(y) : "l"(v));
}

// ---------------------------------------------------------------------------
__global__ void pool_kernel(const float* __restrict__ x)
{
    float* tok = g_scratch + OFF_TOK;
    int fd = blockIdx.x;
    int f = fd / 384;
    const float* xp = x + (size_t)fd * 1024;
    int t = threadIdx.x;
    int gy = t >> 4, gx = t & 15;
    const float* p = xp + (gy * 2) * 32 + gx * 2;
    float m = fmaxf(fmaxf(p[0], p[1]), fmaxf(p[32], p[33]));
    tok[(size_t)(f * 256 + t) * 384 + (fd % 384)] = m;
}

// ---------------------------------------------------------------------------
__global__ void ln_kernel(long long inOff, const float* __restrict__ g,
                          const float* __restrict__ b, long long outOff)
{
    const float* in = g_scratch + inOff;
    float* out = g_scratch + outOff;
    int n = blockIdx.x, t = threadIdx.x;
    float x = in[(size_t)n * 384 + t];
    __shared__ float red[12];
    __shared__ float mv[2];
    float s = x;
    #pragma unroll
    for (int o = 16; o; o >>= 1) s += __shfl_xor_sync(0xffffffffu, s, o);
    if ((t & 31) == 0) red[t >> 5] = s;
    __syncthreads();
    if (t == 0) { float tt = 0.f; for (int i = 0; i < 12; i++) tt += red[i]; mv[0] = tt * (1.0f / 384.0f); }
    __syncthreads();
    float mean = mv[0];
    float d = x - mean;
    s = d * d;
    #pragma unroll
    for (int o = 16; o; o >>= 1) s += __shfl_xor_sync(0xffffffffu, s, o);
    if ((t & 31) == 0) red[t >> 5] = s;
    __syncthreads();
    if (t == 0) { float tt = 0.f; for (int i = 0; i < 12; i++) tt += red[i]; mv[1] = rsqrtf(tt * (1.0f / 384.0f) + LN_EPS); }
    __syncthreads();
    out[(size_t)n * 384 + t] = d * mv[1] * g[t] + b[t];
}

// ---------------------------------------------------------------------------
// gemm128: 128x128x16, 256 thr, 8x8 microtile (f32x2), A pre-duplicated pairs.
// flags: 1=bias 4=gelu 8=NT. Thread owns cols {tx*4..+3} and {64+tx*4..+3}.
// ---------------------------------------------------------------------------
__global__ void __launch_bounds__(256, 2) gemm128_kernel(
    long long aOff, const float* __restrict__ Bp, long long bOff,
    const float* __restrict__ bias, long long cOff,
    int K, int lda, int ldb, int ldc,
    long long sA, long long sB, long long sC,
    float alpha, int flags)
{
    int z = blockIdx.z;
    const float* A = g_scratch + aOff + (long long)z * sA;
    const float* B = (Bp ? Bp : g_scratch + bOff) + (long long)z * sB;
    float* C = g_scratch + cOff + (long long)z * sC;

    __shared__ __align__(16) float As2[2][16][256];   // duplicated pairs
    __shared__ __align__(16) float Bs[2][16][128];

    int bm = blockIdx.y * 128, bn = blockIdx.x * 128;
    int tid = threadIdx.x;
    int r2 = tid >> 1, k8 = (tid & 1) * 8;
    int bk = tid >> 4, c8 = (tid & 15) * 8;
    int ty = tid >> 4, tx = tid & 15;

    int nt = K / 16;
    float4 ar0, ar1, br0, br1;

    {
        const float* ap = A + (long long)(bm + r2) * lda + k8;
        ar0 = *(const float4*)ap; ar1 = *(const float4*)(ap + 4);
        *(float2*)&As2[0][k8 + 0][2 * r2] = make_float2(ar0.x, ar0.x);
        *(float2*)&As2[0][k8 + 1][2 * r2] = make_float2(ar0.y, ar0.y);
        *(float2*)&As2[0][k8 + 2][2 * r2] = make_float2(ar0.z, ar0.z);
        *(float2*)&As2[0][k8 + 3][2 * r2] = make_float2(ar0.w, ar0.w);
        *(float2*)&As2[0][k8 + 4][2 * r2] = make_float2(ar1.x, ar1.x);
        *(float2*)&As2[0][k8 + 5][2 * r2] = make_float2(ar1.y, ar1.y);
        *(float2*)&As2[0][k8 + 6][2 * r2] = make_float2(ar1.z, ar1.z);
        *(float2*)&As2[0][k8 + 7][2 * r2] = make_float2(ar1.w, ar1.w);
        if (flags & 8) {
            const float* bp = B + (long long)(bn + r2) * ldb + k8;
            br0 = *(const float4*)bp; br1 = *(const float4*)(bp + 4);
            Bs[0][k8 + 0][r2] = br0.x; Bs[0][k8 + 1][r2] = br0.y;
            Bs[0][k8 + 2][r2] = br0.z; Bs[0][k8 + 3][r2] = br0.w;
            Bs[0][k8 + 4][r2] = br1.x; Bs[0][k8 + 5][r2] = br1.y;
            Bs[0][k8 + 6][r2] = br1.z; Bs[0][k8 + 7][r2] = br1.w;
        } else {
            const float* bp = B + (long long)bk * ldb + bn + c8;
            br0 = *(const float4*)bp; br1 = *(const float4*)(bp + 4);
            *(float4*)&Bs[0][bk][c8] = br0;
            *(float4*)&Bs[0][bk][c8 + 4] = br1;
        }
    }
    __syncthreads();

    ull acc2[8][4];
    #pragma unroll
    for (int i = 0; i < 8; i++)
        #pragma unroll
        for (int j = 0; j < 4; j++) acc2[i][j] = 0ULL;

    for (int kt = 0; kt < nt; kt++) {
        int cur = kt & 1;
        bool pf = (kt + 1 < nt);
        if (pf) {
            int k0 = (kt + 1) * 16;
            const float* ap = A + (long long)(bm + r2) * lda + k0 + k8;
            ar0 = *(const float4*)ap; ar1 = *(const float4*)(ap + 4);
            if (flags & 8) {
                const float* bp = B + (long long)(bn + r2) * ldb + k0 + k8;
                br0 = *(const float4*)bp; br1 = *(const float4*)(bp + 4);
            } else {
                const float* bp = B + (long long)(k0 + bk) * ldb + bn + c8;
                br0 = *(const float4*)bp; br1 = *(const float4*)(bp + 4);
            }
        }
        #pragma unroll
        for (int kk = 0; kk < 16; kk++) {
            float a2[16];
            *(float4*)&a2[0]  = *(const float4*)&As2[cur][kk][ty * 16];
            *(float4*)&a2[4]  = *(const float4*)&As2[cur][kk][ty * 16 + 4];
            *(float4*)&a2[8]  = *(const float4*)&As2[cur][kk][ty * 16 + 8];
            *(float4*)&a2[12] = *(const float4*)&As2[cur][kk][ty * 16 + 12];
            const ull* pa = (const ull*)a2;
            float bv[8];
            *(float4*)&bv[0] = *(const float4*)&Bs[cur][kk][tx * 4];
            *(float4*)&bv[4] = *(const float4*)&Bs[cur][kk][64 + tx * 4];
            const ull* pb = (const ull*)bv;
            #pragma unroll
            for (int i = 0; i < 8; i++) {
                fma2(acc2[i][0], pa[i], pb[0]);
                fma2(acc2[i][1], pa[i], pb[1]);
                fma2(acc2[i][2], pa[i], pb[2]);
                fma2(acc2[i][3], pa[i], pb[3]);
            }
        }
        if (pf) {
            int nx = 1 - cur;
            *(float2*)&As2[nx][k8 + 0][2 * r2] = make_float2(ar0.x, ar0.x);
            *(float2*)&As2[nx][k8 + 1][2 * r2] = make_float2(ar0.y, ar0.y);
            *(float2*)&As2[nx][k8 + 2][2 * r2] = make_float2(ar0.z, ar0.z);
            *(float2*)&As2[nx][k8 + 3][2 * r2] = make_float2(ar0.w, ar0.w);
            *(float2*)&As2[nx][k8 + 4][2 * r2] = make_float2(ar1.x, ar1.x);
            *(float2*)&As2[nx][k8 + 5][2 * r2] = make_float2(ar1.y, ar1.y);
            *(float2*)&As2[nx][k8 + 6][2 * r2] = make_float2(ar1.z, ar1.z);
            *(float2*)&As2[nx][k8 + 7][2 * r2] = make_float2(ar1.w, ar1.w);
            if (flags & 8) {
                Bs[nx][k8 + 0][r2] = br0.x; Bs[nx][k8 + 1][r2] = br0.y;
                Bs[nx][k8 + 2][r2] = br0.z; Bs[nx][k8 + 3][r2] = br0.w;
                Bs[nx][k8 + 4][r2] = br1.x; Bs[nx][k8 + 5][r2] = br1.y;
                Bs[nx][k8 + 6][r2] = br1.z; Bs[nx][k8 + 7][r2] = br1.w;
            } else {
                *(float4*)&Bs[nx][bk][c8] = br0;
                *(float4*)&Bs[nx][bk][c8 + 4] = br1;
            }
            __syncthreads();
        }
    }

    int row0 = bm + ty * 8;
    int colA = bn + tx * 4, colB = bn + 64 + tx * 4;
    #pragma unroll
    for (int i = 0; i < 8; i++) {
        float v[4], w[4];
        unpack2(acc2[i][0], v[0], v[1]);
        unpack2(acc2[i][1], v[2], v[3]);
        unpack2(acc2[i][2], w[0], w[1]);
        unpack2(acc2[i][3], w[2], w[3]);
        #pragma unroll
        for (int j = 0; j < 4; j++) {
            float t = alpha * v[j];
            if (flags & 1) t += bias[colA + j];
            if (flags & 4) t = 0.5f * t * (1.0f + erff(t * 0.7071067811865476f));
            v[j] = t;
            float u = alpha * w[j];
            if (flags & 1) u += bias[colB + j];
            if (flags & 4) u = 0.5f * u * (1.0f + erff(u * 0.7071067811865476f));
            w[j] = u;
        }
        float* cp = C + (long long)(row0 + i) * ldc;
        *(float4*)(cp + colA) = *(float4*)&v[0];
        *(float4*)(cp + colB) = *(float4*)&w[0];
    }
}

// ---------------------------------------------------------------------------
// gemm64: 128x64x16, 8x4 microtile (f32x2), A pre-duplicated pairs.
// flags: 1=bias 2=residual 4=gelu 8=NT. z: zb=z%nB batch, zk=z/nB K-split.
// ---------------------------------------------------------------------------
__global__ void __launch_bounds__(256) gemm64_kernel(
    long long aOff, const float* __restrict__ Bp, long long bOff,
    const float* __restrict__ bias, long long rOff, long long cOff,
    int M, int N, int K, int lda, int ldb, int ldc, int ldr,
    long long sA, long long sB, long long sC,
    float alpha, int flags, int nB, int ksplit)
{
    int z = blockIdx.z;
    int zb = z % nB, zk = z / nB;
    int Kloc = K / ksplit;
    const float* A = g_scratch + aOff + (long long)zb * sA + (long long)zk * Kloc;
    const float* Bb = (Bp ? Bp : g_scratch + bOff) + (long long)zb * sB;
    const float* B = Bb + ((flags & 8) ? (long long)zk * Kloc
                                       : (long long)zk * Kloc * ldb);
    float* C = g_scratch + cOff + (long long)z * sC;

    __shared__ __align__(16) float As2[2][16][256];
    __shared__ __align__(16) float Bs[2][16][64];

    int bm = blockIdx.y * 128, bn = blockIdx.x * 64;
    int tid = threadIdx.x;
    int a_r = tid >> 1, a_k = (tid & 1) * 8;
    int tx = tid & 15, ty = tid >> 4;

    int nt = Kloc / 16;
    float4 ar0, ar1, br0;

    {
        const float* ap = A + (long long)(bm + a_r) * lda + a_k;
        ar0 = *(const float4*)ap; ar1 = *(const float4*)(ap + 4);
        *(float2*)&As2[0][a_k + 0][2 * a_r] = make_float2(ar0.x, ar0.x);
        *(float2*)&As2[0][a_k + 1][2 * a_r] = make_float2(ar0.y, ar0.y);
        *(float2*)&As2[0][a_k + 2][2 * a_r] = make_float2(ar0.z, ar0.z);
        *(float2*)&As2[0][a_k + 3][2 * a_r] = make_float2(ar0.w, ar0.w);
        *(float2*)&As2[0][a_k + 4][2 * a_r] = make_float2(ar1.x, ar1.x);
        *(float2*)&As2[0][a_k + 5][2 * a_r] = make_float2(ar1.y, ar1.y);
        *(float2*)&As2[0][a_k + 6][2 * a_r] = make_float2(ar1.z, ar1.z);
        *(float2*)&As2[0][a_k + 7][2 * a_r] = make_float2(ar1.w, ar1.w);
        if (flags & 8) {
            int r = tid >> 2, k4 = (tid & 3) * 4;
            br0 = *(const float4*)(B + (long long)(bn + r) * ldb + k4);
            Bs[0][k4 + 0][r] = br0.x; Bs[0][k4 + 1][r] = br0.y;
            Bs[0][k4 + 2][r] = br0.z; Bs[0][k4 + 3][r] = br0.w;
        } else {
            int kk = tid >> 4, n4 = (tid & 15) * 4;
            br0 = *(const float4*)(B + (long long)kk * ldb + bn + n4);
            *(float4*)&Bs[0][kk][n4] = br0;
        }
    }
    __syncthreads();

    ull acc2[8][2];
    #pragma unroll
    for (int i = 0; i < 8; i++) { acc2[i][0] = 0ULL; acc2[i][1] = 0ULL; }

    for (int kt = 0; kt < nt; kt++) {
        int cur = kt & 1;
        bool pf = (kt + 1 < nt);
        if (pf) {
            int k0 = (kt + 1) * 16;
            const float* ap = A + (long long)(bm + a_r) * lda + k0 + a_k;
            ar0 = *(const float4*)ap; ar1 = *(const float4*)(ap + 4);
            if (flags & 8) {
                int r = tid >> 2, k4 = (tid & 3) * 4;
                br0 = *(const float4*)(B + (long long)(bn + r) * ldb + k0 + k4);
            } else {
                int kk = tid >> 4, n4 = (tid & 15) * 4;
                br0 = *(const float4*)(B + (long long)(k0 + kk) * ldb + bn + n4);
            }
        }
        #pragma unroll
        for (int kk = 0; kk < 16; kk++) {
            float a2[16];
            *(float4*)&a2[0]  = *(const float4*)&As2[cur][kk][ty * 16];
            *(float4*)&a2[4]  = *(const float4*)&As2[cur][kk][ty * 16 + 4];
            *(float4*)&a2[8]  = *(const float4*)&As2[cur][kk][ty * 16 + 8];
            *(float4*)&a2[12] = *(const float4*)&As2[cur][kk][ty * 16 + 12];
            const ull* pa = (const ull*)a2;
            float bv[4];
            *(float4*)&bv[0] = *(const float4*)&Bs[cur][kk][tx * 4];
            const ull* pb = (const ull*)bv;
            #pragma unroll
            for (int i = 0; i < 8; i++) {
                fma2(acc2[i][0], pa[i], pb[0]);
                fma2(acc2[i][1], pa[i], pb[1]);
            }
        }
        if (pf) {
            int nx = 1 - cur;
            *(float2*)&As2[nx][a_k + 0][2 * a_r] = make_float2(ar0.x, ar0.x);
            *(float2*)&As2[nx][a_k + 1][2 * a_r] = make_float2(ar0.y, ar0.y);
            *(float2*)&As2[nx][a_k + 2][2 * a_r] = make_float2(ar0.z, ar0.z);
            *(float2*)&As2[nx][a_k + 3][2 * a_r] = make_float2(ar0.w, ar0.w);
            *(float2*)&As2[nx][a_k + 4][2 * a_r] = make_float2(ar1.x, ar1.x);
            *(float2*)&As2[nx][a_k + 5][2 * a_r] = make_float2(ar1.y, ar1.y);
            *(float2*)&As2[nx][a_k + 6][2 * a_r] = make_float2(ar1.z, ar1.z);
            *(float2*)&As2[nx][a_k + 7][2 * a_r] = make_float2(ar1.w, ar1.w);
            if (flags & 8) {
                int r = tid >> 2, k4 = (tid & 3) * 4;
                Bs[nx][k4 + 0][r] = br0.x; Bs[nx][k4 + 1][r] = br0.y;
                Bs[nx][k4 + 2][r] = br0.z; Bs[nx][k4 + 3][r] = br0.w;
            } else {
                int kk = tid >> 4, n4 = (tid & 15) * 4;
                *(float4*)&Bs[nx][kk][n4] = br0;
            }
            __syncthreads();
        }
    }

    int row0 = bm + ty * 8, col0 = bn + tx * 4;
    const float* R = g_scratch + rOff;
    #pragma unroll
    for (int i = 0; i < 8; i++) {
        float v[4];
        unpack2(acc2[i][0], v[0], v[1]);
        unpack2(acc2[i][1], v[2], v[3]);
        #pragma unroll
        for (int j = 0; j < 4; j++) {
            float t = alpha * v[j];
            if (flags & 1) t += bias[col0 + j];
            if (flags & 4) t = 0.5f * t * (1.0f + erff(t * 0.7071067811865476f));
            if (flags & 2) t += R[(long long)(row0 + i) * ldr + col0 + j];
            C[(long long)(row0 + i) * ldc + col0 + j] = t;
        }
    }
}

// ---------------------------------------------------------------------------
__global__ void ta_kernel()
{
    const float* qk = g_scratch + OFF_QK;
    float* ta = g_scratch + OFF_TA;
    int b = blockIdx.x;
    int h = b >> 10, n = b & 1023;
    int s = threadIdx.x;
    const float* p = qk + ((size_t)b << 10) + s;
    float x0 = SCALE * p[0], x1 = SCALE * p[256], x2 = SCALE * p[512], x3 = SCALE * p[768];
    float m = fmaxf(fmaxf(x0, x1), fmaxf(x2, x3));
    float e0 = expf(x0 - m), e1 = expf(x1 - m), e2 = expf(x2 - m), e3 = expf(x3 - m);
    float inv = 1.0f / (e0 + e1 + e2 + e3);
    float* o = ta + ((size_t)(n * 256 + s)) * 24 + h * 4;
    o[0] = e0 * inv; o[1] = e1 * inv; o[2] = e2 * inv; o[3] = e3 * inv;
}

// ---------------------------------------------------------------------------
__global__ void xdiag_kernel()
{
    const float* ta = g_scratch + OFF_TA;
    const float* qkv = g_scratch + OFF_QKV;
    float* xd = g_scratch + OFF_XD;
    int n = blockIdx.x, c = threadIdx.x;
    int h = c >> 6;
    int s = n & 255;
    const float* tp = ta + ((size_t)(n * 256 + s)) * 24 + h * 4;
    float acc = 0.f;
    #pragma unroll
    for (int f = 0; f < 4; f++)
        acc += tp[f] * qkv[(size_t)(f * 256 + s) * 1152 + 768 + c];
    xd[(size_t)n * 384 + c] = acc;
}

// ---------------------------------------------------------------------------
__global__ void __launch_bounds__(256) middle_kernel(int g, float* __restrict__ out_attn,
                                                     int write_out)
{
    int n = blockIdx.x;
    int hg = blockIdx.y;
    int s = threadIdx.x;
    __shared__ __align__(16) float sta[256][24];
    __shared__ float red[8];
    __shared__ float mv[2];

    const float4* tap = (const float4*)(g_scratch + OFF_TA + (size_t)n * 6144);
    float4* stp = (float4*)&sta[0][0];
    for (int idx = s; idx < 1536; idx += 256)
        stp[idx] = tap[idx];
    __syncthreads();

    float* lg = g_scratch + OFF_QK + (long long)hg * LG_STRIDE + (size_t)n * 6144;
    float logit = 0.f;
    #pragma unroll
    for (int j = 0; j < 24; j++)
        logit += sta[s][j] * lg[j * 256 + s];

    float m = logit;
    #pragma unroll
    for (int o = 16; o; o >>= 1) m = fmaxf(m, __shfl_xor_sync(0xffffffffu, m, o));
    if ((s & 31) == 0) red[s >> 5] = m;
    __syncthreads();
    if (s == 0) { float t = red[0]; for (int i = 1; i < 8; i++) t = fmaxf(t, red[i]); mv[0] = t; }
    __syncthreads();
    float e = expf(logit - mv[0]);
    float sum = e;
    #pragma unroll
    for (int o = 16; o; o >>= 1) sum += __shfl_xor_sync(0xffffffffu, sum, o);
    if ((s & 31) == 0) red[s >> 5] = sum;
    __syncthreads();
    if (s == 0) { float t = 0.f; for (int i = 0; i < 8; i++) t += red[i]; mv[1] = 1.0f / t; }
    __syncthreads();
    float sa = e * mv[1];
    if (write_out) out_attn[((size_t)(g * 2 + hg) * 1024 + n) * 256 + s] = sa;
    #pragma unroll
    for (int j = 0; j < 24; j++)
        lg[j * 256 + s] = sa * sta[s][j];
}

// ---------------------------------------------------------------------------
__global__ void oreduce_kernel(int g)
{
    const float* opart = g_scratch + OFF_OPART;
    float* o = g_scratch + OFF_O;
    int i = blockIdx.x * 256 + threadIdx.x;       // < 131072
    int hg = i >> 16;
    int r = i & 65535;
    float sum = 0.f;
    #pragma unroll
    for (int zk = 0; zk < 12; zk++)
        sum += opart[(size_t)(zk * 2 + hg) * 65536 + r];
    o[(size_t)(r >> 6) * 384 + (g * 2 + hg) * 64 + (r & 63)] = sum;
}

// ---------------------------------------------------------------------------
__global__ void upsample_kernel(float* __restrict__ out, int out_size)
{
    const float* h2 = g_scratch + OFF_H2;
    int fd = blockIdx.x;
    int f = fd / 384, d = fd % 384;
    __shared__ float ch[256];
    int t = threadIdx.x;
    ch[t] = h2[(size_t)(f * 256 + t) * 384 + d];
    __syncthreads();
    #pragma unroll
    for (int p = 0; p < 4; p++) {
        int o = t + p * 256;
        int oy = o >> 5, ox = o & 31;
        float fy = 0.5f * oy - 0.25f;
        int iy0 = (int)floorf(fy);
        float wy = fy - (float)iy0;
        int iy0c = max(iy0, 0), iy1c = min(iy0 + 1, 15);
        float fx = 0.5f * ox - 0.25f;
        int ix0 = (int)floorf(fx);
        float wx = fx - (float)ix0;
        int ix0c = max(ix0, 0), ix1c = min(ix0 + 1, 15);
        float v00 = ch[iy0c * 16 + ix0c], v01 = ch[iy0c * 16 + ix1c];
        float v10 = ch[iy1c * 16 + ix0c], v11 = ch[iy1c * 16 + ix1c];
        float v = (1.f - wy) * ((1.f - wx) * v00 + wx * v01)
                + wy * ((1.f - wx) * v10 + wx * v11);
        long long oi = (long long)fd * 1024 + o;
        if (oi < (long long)out_size) out[oi] = v;
    }
}

// ---------------------------------------------------------------------------
extern "C" void kernel_launch(void* const* d_in, const int* in_sizes, int n_in,
                              void* d_out, int out_size)
{
    (void)in_sizes; (void)n_in;
    const float* x      = (const float*)d_in[0];
    const float* qkv_w  = (const float*)d_in[1];
    const float* q2_w   = (const float*)d_in[2];
    const float* kv2_w  = (const float*)d_in[3];
    const float* proj_w = (const float*)d_in[4];
    const float* proj_b = (const float*)d_in[5];
    const float* ln1_g  = (const float*)d_in[6];
    const float* ln1_b  = (const float*)d_in[7];
    const float* ln2_g  = (const float*)d_in[8];
    const float* ln2_b  = (const float*)d_in[9];
    const float* fc1_w  = (const float*)d_in[10];
    const float* fc1_b  = (const float*)d_in[11];
    const float* fc2_w  = (const float*)d_in[12];
    const float* fc2_b  = (const float*)d_in[13];
    float* out = (float*)d_out;

    pool_kernel<<<1536, 256>>>(x);
    ln_kernel<<<1024, 384>>>(OFF_TOK, ln1_g, ln1_b, OFF_XN);

    // qkv = xn @ qkv_w   (1024 x 1152 x 384, NN)
    gemm128_kernel<<<dim3(9, 8, 1), 256>>>(OFF_XN, qkv_w, 0, nullptr, OFF_QKV,
        384, 384, 1152, 1152, 0, 0, 0, 1.0f, 0);

    // VW[h'] = v_h' @ kv2_w[h' slice]   (6 batched NN, K=64)
    gemm128_kernel<<<dim3(6, 8, 6), 256>>>(OFF_QKV + 768, kv2_w, 0, nullptr, OFF_VW,
        64, 1152, 768, 768, 64, 49152, 786432, 1.0f, 0);

    // qk[h] = q_h @ k_h^T   (6 batched NT, K=64)
    gemm128_kernel<<<dim3(8, 8, 6), 256>>>(OFF_QKV, nullptr, OFF_QKV + 384, nullptr, OFF_QK,
        64, 1152, 1152, 1024, 64, 64, 1048576, 1.0f, 8);

    ta_kernel<<<6144, 256>>>();
    xdiag_kernel<<<1024, 384>>>();

    // q2 = SCALE * x_diag @ q2_w
    gemm64_kernel<<<dim3(6, 8, 1), 256>>>(OFF_XD, q2_w, 0, nullptr, 0, OFF_Q2,
        1024, 384, 384, 384, 384, 384, 0, 0, 0, 0, SCALE, 0, 1, 1);

    int wout = (out_size >= 3145728) ? 1 : 0;

    // stage 2 in 3 groups of 2 heads (Lg overlays dead QK + LG regions)
    for (int g = 0; g < 3; g++) {
        gemm128_kernel<<<dim3(48, 8, 2), 256>>>(OFF_Q2 + g * 128, nullptr, OFF_VW + g * 128,
            nullptr, OFF_QK,
            64, 384, 768, 6144, 64, 64, LG_STRIDE, 1.0f, 8);

        middle_kernel<<<dim3(1024, 2), 256>>>(g, out + 1572864, wout);

        gemm64_kernel<<<dim3(1, 8, 24), 256>>>(OFF_QK, nullptr, OFF_VW + 384 + g * 128,
            nullptr, 0, OFF_OPART,
            1024, 64, 6144, 6144, 768, 64, 0, LG_STRIDE, 64, 65536, 1.0f, 0, 2, 12);

        oreduce_kernel<<<512, 256>>>(g);
    }

    // h1 = tok + (o @ proj_w + proj_b)
    gemm64_kernel<<<dim3(6, 8, 1), 256>>>(OFF_O, proj_w, 0, proj_b, OFF_TOK, OFF_H1,
        1024, 384, 384, 384, 384, 384, 384, 0, 0, 0, 1.0f, 1 | 2, 1, 1);

    ln_kernel<<<1024, 384>>>(OFF_H1, ln2_g, ln2_b, OFF_HN);

    // mlp
    gemm128_kernel<<<dim3(12, 8, 1), 256>>>(OFF_HN, fc1_w, 0, fc1_b, OFF_MLP,
        384, 384, 1536, 1536, 0, 0, 0, 1.0f, 1 | 4);
    gemm64_kernel<<<dim3(6, 8, 1), 256>>>(OFF_MLP, fc2_w, 0, fc2_b, OFF_H1, OFF_H2,
        1024, 384, 1536, 1536, 384, 384, 384, 0, 0, 0, 1.0f, 1 | 2, 1, 1);

    upsample_kernel<<<1536, 256>>>(out, out_size);
}

// round 10
// speedup vs baseline: 1.1715x; 1.1715x over previous
#include <cuda_runtime.h>
#include <cuda_bf16.h>
#include <cstdint>
#include <math.h>

// ---------------------------------------------------------------------------
// DeformationTrajectoryAttentionBlock — fp32 + mma.sync bf16x3 for Lg GEMM.
// B=1, F=4, H=6, D=384, G=16, S=256, N=1024, HD=64, IMG=32, MLP_HID=1536
// ---------------------------------------------------------------------------

#define SCALE 0.125f
#define LN_EPS 1e-5f
typedef unsigned long long ull;

#define OFF_TOK    0LL          // 1024*384
#define OFF_XN     393216LL     // reused: q2h bf16 @ +0, q2l bf16 @ +196608
#define OFF_QKV    786432LL     // 1024*1152 ; reused: VWk-hi bf16
#define OFF_VW     1966080LL    // 6*1024*768 (6144 x 768)
#define OFF_QK     6684672LL    // 6*1024*1024 ; reused as Lg[hg=0]
#define OFF_TA     12976128LL   // 1024*256*24
#define OFF_XD     19267584LL
#define OFF_Q2     19660800LL
#define OFF_LG     20054016LL   // 1024*6144 ; Lg[hg=1]
#define LG_STRIDE  13369344LL   // OFF_LG - OFF_QK
#define OFF_OPART  26345472LL   // 24 * 1024*64
#define OFF_O      27918336LL
#define OFF_H1     28311552LL
#define OFF_HN     28704768LL
#define OFF_MLP    29097984LL   // 1024*1536 ; reused earlier: VWk-lo bf16
#define OFF_H2     30670848LL
#define SCRATCH_FLOATS 31064064LL

static __device__ float g_scratch[SCRATCH_FLOATS];

// ---- packed f32x2 helpers (R6-proven) --------------------------------------
__device__ __forceinline__ ull pack2b(float x)
{
    ull r;
    asm("mov.b64 %0, {%1, %1};" : "=l"(r) : "f"(x));
    return r;
}
__device__ __forceinline__ void fma2(ull& acc, ull a, ull b)
{
    asm("fma.rn.f32x2 %0, %1, %2, %0;" : "+l"(acc) : "l"(a), "l"(b));
}
__device__ __forceinline__ void unpack2(ull v, float& x, float& y)
{
    asm("mov.b64 {%0, %1}, %2;" : "=f"(x), "=f"(y) : "l"(v));
}
__device__ __forceinline__ uint32_t smem_to_u32(const void* smem_ptr)
{
    uint32_t addr;
    asm("{ .reg .u64 tmp; cvta.to.shared.u64 tmp, %1; cvt.u32.u64 %0, tmp; }"
        : "=r"(addr) : "l"(smem_ptr));
    return addr;
}

// ---------------------------------------------------------------------------
__global__ void pool_kernel(const float* __restrict__ x)
{
    float* tok = g_scratch + OFF_TOK;
    int fd = blockIdx.x;
    int f = fd / 384;
    const float* xp = x + (size_t)fd * 1024;
    int t = threadIdx.x;
    int gy = t >> 4, gx = t & 15;
    const float* p = xp + (gy * 2) * 32 + gx * 2;
    float m = fmaxf(fmaxf(p[0], p[1]), fmaxf(p[32], p[33]));
    tok[(size_t)(f * 256 + t) * 384 + (fd % 384)] = m;
}

// ---------------------------------------------------------------------------
__global__ void ln_kernel(long long inOff, const float* __restrict__ g,
                          const float* __restrict__ b, long long outOff)
{
    const float* in = g_scratch + inOff;
    float* out = g_scratch + outOff;
    int n = blockIdx.x, t = threadIdx.x;
    float x = in[(size_t)n * 384 + t];
    __shared__ float red[12];
    __shared__ float mv[2];
    float s = x;
    #pragma unroll
    for (int o = 16; o; o >>= 1) s += __shfl_xor_sync(0xffffffffu, s, o);
    if ((t & 31) == 0) red[t >> 5] = s;
    __syncthreads();
    if (t == 0) { float tt = 0.f; for (int i = 0; i < 12; i++) tt += red[i]; mv[0] = tt * (1.0f / 384.0f); }
    __syncthreads();
    float mean = mv[0];
    float d = x - mean;
    s = d * d;
    #pragma unroll
    for (int o = 16; o; o >>= 1) s += __shfl_xor_sync(0xffffffffu, s, o);
    if ((t & 31) == 0) red[t >> 5] = s;
    __syncthreads();
    if (t == 0) { float tt = 0.f; for (int i = 0; i < 12; i++) tt += red[i]; mv[1] = rsqrtf(tt * (1.0f / 384.0f) + LN_EPS); }
    __syncthreads();
    out[(size_t)n * 384 + t] = d * mv[1] * g[t] + b[t];
}

// ---------------------------------------------------------------------------
// gemm128 (R6-proven): 128x128x16, 8x8 microtile (f32x2), dbl-buffered.
// flags: 1=bias 4=gelu 8=NT.
// ---------------------------------------------------------------------------
__global__ void __launch_bounds__(256, 2) gemm128_kernel(
    long long aOff, const float* __restrict__ Bp, long long bOff,
    const float* __restrict__ bias, long long cOff,
    int K, int lda, int ldb, int ldc,
    long long sA, long long sB, long long sC,
    float alpha, int flags)
{
    int z = blockIdx.z;
    const float* A = g_scratch + aOff + (long long)z * sA;
    const float* B = (Bp ? Bp : g_scratch + bOff) + (long long)z * sB;
    float* C = g_scratch + cOff + (long long)z * sC;

    __shared__ __align__(16) float As[2][16][128];
    __shared__ __align__(16) float Bs[2][16][128];

    int bm = blockIdx.y * 128, bn = blockIdx.x * 128;
    int tid = threadIdx.x;
    int r2 = tid >> 1, k8 = (tid & 1) * 8;
    int bk = tid >> 4, c8 = (tid & 15) * 8;
    int ty = tid >> 4, tx = tid & 15;

    int nt = K / 16;
    float4 ar0, ar1, br0, br1;

    {
        const float* ap = A + (long long)(bm + r2) * lda + k8;
        ar0 = *(const float4*)ap; ar1 = *(const float4*)(ap + 4);
        As[0][k8 + 0][r2] = ar0.x; As[0][k8 + 1][r2] = ar0.y;
        As[0][k8 + 2][r2] = ar0.z; As[0][k8 + 3][r2] = ar0.w;
        As[0][k8 + 4][r2] = ar1.x; As[0][k8 + 5][r2] = ar1.y;
        As[0][k8 + 6][r2] = ar1.z; As[0][k8 + 7][r2] = ar1.w;
        if (flags & 8) {
            const float* bp = B + (long long)(bn + r2) * ldb + k8;
            br0 = *(const float4*)bp; br1 = *(const float4*)(bp + 4);
            Bs[0][k8 + 0][r2] = br0.x; Bs[0][k8 + 1][r2] = br0.y;
            Bs[0][k8 + 2][r2] = br0.z; Bs[0][k8 + 3][r2] = br0.w;
            Bs[0][k8 + 4][r2] = br1.x; Bs[0][k8 + 5][r2] = br1.y;
            Bs[0][k8 + 6][r2] = br1.z; Bs[0][k8 + 7][r2] = br1.w;
        } else {
            const float* bp = B + (long long)bk * ldb + bn + c8;
            br0 = *(const float4*)bp; br1 = *(const float4*)(bp + 4);
            *(float4*)&Bs[0][bk][c8] = br0;
            *(float4*)&Bs[0][bk][c8 + 4] = br1;
        }
    }
    __syncthreads();

    ull acc2[8][4];
    #pragma unroll
    for (int i = 0; i < 8; i++)
        #pragma unroll
        for (int j = 0; j < 4; j++) acc2[i][j] = 0ULL;

    for (int kt = 0; kt < nt; kt++) {
        int cur = kt & 1;
        bool pf = (kt + 1 < nt);
        if (pf) {
            int k0 = (kt + 1) * 16;
            const float* ap = A + (long long)(bm + r2) * lda + k0 + k8;
            ar0 = *(const float4*)ap; ar1 = *(const float4*)(ap + 4);
            if (flags & 8) {
                const float* bp = B + (long long)(bn + r2) * ldb + k0 + k8;
                br0 = *(const float4*)bp; br1 = *(const float4*)(bp + 4);
            } else {
                const float* bp = B + (long long)(k0 + bk) * ldb + bn + c8;
                br0 = *(const float4*)bp; br1 = *(const float4*)(bp + 4);
            }
        }
        #pragma unroll
        for (int kk = 0; kk < 16; kk++) {
            float a[8];
            *(float4*)&a[0] = *(const float4*)&As[cur][kk][ty * 8];
            *(float4*)&a[4] = *(const float4*)&As[cur][kk][ty * 8 + 4];
            const ull* bsp = (const ull*)&Bs[cur][kk][tx * 8];
            ull b0 = bsp[0], b1 = bsp[1], b2 = bsp[2], b3 = bsp[3];
            #pragma unroll
            for (int i = 0; i < 8; i++) {
                ull pa = pack2b(a[i]);
                fma2(acc2[i][0], pa, b0);
                fma2(acc2[i][1], pa, b1);
                fma2(acc2[i][2], pa, b2);
                fma2(acc2[i][3], pa, b3);
            }
        }
        if (pf) {
            int nx = 1 - cur;
            As[nx][k8 + 0][r2] = ar0.x; As[nx][k8 + 1][r2] = ar0.y;
            As[nx][k8 + 2][r2] = ar0.z; As[nx][k8 + 3][r2] = ar0.w;
            As[nx][k8 + 4][r2] = ar1.x; As[nx][k8 + 5][r2] = ar1.y;
            As[nx][k8 + 6][r2] = ar1.z; As[nx][k8 + 7][r2] = ar1.w;
            if (flags & 8) {
                Bs[nx][k8 + 0][r2] = br0.x; Bs[nx][k8 + 1][r2] = br0.y;
                Bs[nx][k8 + 2][r2] = br0.z; Bs[nx][k8 + 3][r2] = br0.w;
                Bs[nx][k8 + 4][r2] = br1.x; Bs[nx][k8 + 5][r2] = br1.y;
                Bs[nx][k8 + 6][r2] = br1.z; Bs[nx][k8 + 7][r2] = br1.w;
            } else {
                *(float4*)&Bs[nx][bk][c8] = br0;
                *(float4*)&Bs[nx][bk][c8 + 4] = br1;
            }
            __syncthreads();
        }
    }

    int row0 = bm + ty * 8, col0 = bn + tx * 8;
    #pragma unroll
    for (int i = 0; i < 8; i++) {
        float v[8];
        #pragma unroll
        for (int j = 0; j < 4; j++)
            unpack2(acc2[i][j], v[2 * j], v[2 * j + 1]);
        #pragma unroll
        for (int j = 0; j < 8; j++) {
            float t = alpha * v[j];
            if (flags & 1) t += bias[col0 + j];
            if (flags & 4) t = 0.5f * t * (1.0f + erff(t * 0.7071067811865476f));
            v[j] = t;
        }
        float* cp = C + (long long)(row0 + i) * ldc + col0;
        *(float4*)cp = *(float4*)&v[0];
        *(float4*)(cp + 4) = *(float4*)&v[4];
    }
}

// ---------------------------------------------------------------------------
// gemm64 (R6-proven): 128x64x16, 8x4 microtile (f32x2).
// flags: 1=bias 2=residual 4=gelu 8=NT. z: zb=z%nB batch, zk=z/nB K-split.
// ---------------------------------------------------------------------------
__global__ void __launch_bounds__(256) gemm64_kernel(
    long long aOff, const float* __restrict__ Bp, long long bOff,
    const float* __restrict__ bias, long long rOff, long long cOff,
    int M, int N, int K, int lda, int ldb, int ldc, int ldr,
    long long sA, long long sB, long long sC,
    float alpha, int flags, int nB, int ksplit)
{
    int z = blockIdx.z;
    int zb = z % nB, zk = z / nB;
    int Kloc = K / ksplit;
    const float* A = g_scratch + aOff + (long long)zb * sA + (long long)zk * Kloc;
    const float* Bb = (Bp ? Bp : g_scratch + bOff) + (long long)zb * sB;
    const float* B = Bb + ((flags & 8) ? (long long)zk * Kloc
                                       : (long long)zk * Kloc * ldb);
    float* C = g_scratch + cOff + (long long)z * sC;

    __shared__ __align__(16) float As[2][16][128];
    __shared__ __align__(16) float Bs[2][16][64];

    int bm = blockIdx.y * 128, bn = blockIdx.x * 64;
    int tid = threadIdx.x;
    int a_r = tid >> 1, a_k = (tid & 1) * 8;
    int tx = tid & 15, ty = tid >> 4;

    int nt = Kloc / 16;
    float4 ar0, ar1, br0;

    {
        const float* ap = A + (long long)(bm + a_r) * lda + a_k;
        ar0 = *(const float4*)ap; ar1 = *(const float4*)(ap + 4);
        As[0][a_k + 0][a_r] = ar0.x; As[0][a_k + 1][a_r] = ar0.y;
        As[0][a_k + 2][a_r] = ar0.z; As[0][a_k + 3][a_r] = ar0.w;
        As[0][a_k + 4][a_r] = ar1.x; As[0][a_k + 5][a_r] = ar1.y;
        As[0][a_k + 6][a_r] = ar1.z; As[0][a_k + 7][a_r] = ar1.w;
        if (flags & 8) {
            int r = tid >> 2, k4 = (tid & 3) * 4;
            br0 = *(const float4*)(B + (long long)(bn + r) * ldb + k4);
            Bs[0][k4 + 0][r] = br0.x; Bs[0][k4 + 1][r] = br0.y;
            Bs[0][k4 + 2][r] = br0.z; Bs[0][k4 + 3][r] = br0.w;
        } else {
            int kk = tid >> 4, n4 = (tid & 15) * 4;
            br0 = *(const float4*)(B + (long long)kk * ldb + bn + n4);
            *(float4*)&Bs[0][kk][n4] = br0;
        }
    }
    __syncthreads();

    ull acc2[8][2];
    #pragma unroll
    for (int i = 0; i < 8; i++) { acc2[i][0] = 0ULL; acc2[i][1] = 0ULL; }

    for (int kt = 0; kt < nt; kt++) {
        int cur = kt & 1;
        bool pf = (kt + 1 < nt);
        if (pf) {
            int k0 = (kt + 1) * 16;
            const float* ap = A + (long long)(bm + a_r) * lda + k0 + a_k;
            ar0 = *(const float4*)ap; ar1 = *(const float4*)(ap + 4);
            if (flags & 8) {
                int r = tid >> 2, k4 = (tid & 3) * 4;
                br0 = *(const float4*)(B + (long long)(bn + r) * ldb + k0 + k4);
            } else {
                int kk = tid >> 4, n4 = (tid & 15) * 4;
                br0 = *(const float4*)(B + (long long)(k0 + kk) * ldb + bn + n4);
            }
        }
        #pragma unroll
        for (int kk = 0; kk < 16; kk++) {
            float a[8];
            *(float4*)&a[0] = *(const float4*)&As[cur][kk][ty * 8];
            *(float4*)&a[4] = *(const float4*)&As[cur][kk][ty * 8 + 4];
            const ull* bsp = (const ull*)&Bs[cur][kk][tx * 4];
            ull b0 = bsp[0], b1 = bsp[1];
            #pragma unroll
            for (int i = 0; i < 8; i++) {
                ull pa = pack2b(a[i]);
                fma2(acc2[i][0], pa, b0);
                fma2(acc2[i][1], pa, b1);
            }
        }
        if (pf) {
            int nx = 1 - cur;
            As[nx][a_k + 0][a_r] = ar0.x; As[nx][a_k + 1][a_r] = ar0.y;
            As[nx][a_k + 2][a_r] = ar0.z; As[nx][a_k + 3][a_r] = ar0.w;
            As[nx][a_k + 4][a_r] = ar1.x; As[nx][a_k + 5][a_r] = ar1.y;
            As[nx][a_k + 6][a_r] = ar1.z; As[nx][a_k + 7][a_r] = ar1.w;
            if (flags & 8) {
                int r = tid >> 2, k4 = (tid & 3) * 4;
                Bs[nx][k4 + 0][r] = br0.x; Bs[nx][k4 + 1][r] = br0.y;
                Bs[nx][k4 + 2][r] = br0.z; Bs[nx][k4 + 3][r] = br0.w;
            } else {
                int kk = tid >> 4, n4 = (tid & 15) * 4;
                *(float4*)&Bs[nx][kk][n4] = br0;
            }
            __syncthreads();
        }
    }

    int row0 = bm + ty * 8, col0 = bn + tx * 4;
    const float* R = g_scratch + rOff;
    #pragma unroll
    for (int i = 0; i < 8; i++) {
        float v[4];
        unpack2(acc2[i][0], v[0], v[1]);
        unpack2(acc2[i][1], v[2], v[3]);
        #pragma unroll
        for (int j = 0; j < 4; j++) {
            float t = alpha * v[j];
            if (flags & 1) t += bias[col0 + j];
            if (flags & 4) t = 0.5f * t * (1.0f + erff(t * 0.7071067811865476f));
            if (flags & 2) t += R[(long long)(row0 + i) * ldr + col0 + j];
            C[(long long)(row0 + i) * ldc + col0 + j] = t;
        }
    }
}

// ---------------------------------------------------------------------------
__global__ void ta_kernel()
{
    const float* qk = g_scratch + OFF_QK;
    float* ta = g_scratch + OFF_TA;
    int b = blockIdx.x;
    int h = b >> 10, n = b & 1023;
    int s = threadIdx.x;
    const float* p = qk + ((size_t)b << 10) + s;
    float x0 = SCALE * p[0], x1 = SCALE * p[256], x2 = SCALE * p[512], x3 = SCALE * p[768];
    float m = fmaxf(fmaxf(x0, x1), fmaxf(x2, x3));
    float e0 = expf(x0 - m), e1 = expf(x1 - m), e2 = expf(x2 - m), e3 = expf(x3 - m);
    float inv = 1.0f / (e0 + e1 + e2 + e3);
    float* o = ta + ((size_t)(n * 256 + s)) * 24 + h * 4;
    o[0] = e0 * inv; o[1] = e1 * inv; o[2] = e2 * inv; o[3] = e3 * inv;
}

// ---------------------------------------------------------------------------
__global__ void xdiag_kernel()
{
    const float* ta = g_scratch + OFF_TA;
    const float* qkv = g_scratch + OFF_QKV;
    float* xd = g_scratch + OFF_XD;
    int n = blockIdx.x, c = threadIdx.x;
    int h = c >> 6;
    int s = n & 255;
    const float* tp = ta + ((size_t)(n * 256 + s)) * 24 + h * 4;
    float acc = 0.f;
    #pragma unroll
    for (int f = 0; f < 4; f++)
        acc += tp[f] * qkv[(size_t)(f * 256 + s) * 1152 + 768 + c];
    xd[(size_t)n * 384 + c] = acc;
}

// ---------------------------------------------------------------------------
__global__ void __launch_bounds__(256) middle_kernel(int g, float* __restrict__ out_attn,
                                                     int write_out)
{
    int n = blockIdx.x;
    int hg = blockIdx.y;
    int s = threadIdx.x;
    __shared__ __align__(16) float sta[256][24];
    __shared__ float red[8];
    __shared__ float mv[2];

    const float4* tap = (const float4*)(g_scratch + OFF_TA + (size_t)n * 6144);
    float4* stp = (float4*)&sta[0][0];
    for (int idx = s; idx < 1536; idx += 256)
        stp[idx] = tap[idx];
    __syncthreads();

    float* lg = g_scratch + OFF_QK + (long long)hg * LG_STRIDE + (size_t)n * 6144;
    float logit = 0.f;
    #pragma unroll
    for (int j = 0; j < 24; j++)
        logit += sta[s][j] * lg[j * 256 + s];

    float m = logit;
    #pragma unroll
    for (int o = 16; o; o >>= 1) m = fmaxf(m, __shfl_xor_sync(0xffffffffu, m, o));
    if ((s & 31) == 0) red[s >> 5] = m;
    __syncthreads();
    if (s == 0) { float t = red[0]; for (int i = 1; i < 8; i++) t = fmaxf(t, red[i]); mv[0] = t; }
    __syncthreads();
    float e = expf(logit - mv[0]);
    float sum = e;
    #pragma unroll
    for (int o = 16; o; o >>= 1) sum += __shfl_xor_sync(0xffffffffu, sum, o);
    if ((s & 31) == 0) red[s >> 5] = sum;
    __syncthreads();
    if (s == 0) { float t = 0.f; for (int i = 0; i < 8; i++) t += red[i]; mv[1] = 1.0f / t; }
    __syncthreads();
    float sa = e * mv[1];
    if (write_out) out_attn[((size_t)(g * 2 + hg) * 1024 + n) * 256 + s] = sa;
    #pragma unroll
    for (int j = 0; j < 24; j++)
        lg[j * 256 + s] = sa * sta[s][j];
}

// ---------------------------------------------------------------------------
__global__ void oreduce_kernel(int g)
{
    const float* opart = g_scratch + OFF_OPART;
    float* o = g_scratch + OFF_O;
    int i = blockIdx.x * 256 + threadIdx.x;       // < 131072
    int hg = i >> 16;
    int r = i & 65535;
    float sum = 0.f;
    #pragma unroll
    for (int zk = 0; zk < 12; zk++)
        sum += opart[(size_t)(zk * 2 + hg) * 65536 + r];
    o[(size_t)(r >> 6) * 384 + (g * 2 + hg) * 64 + (r & 63)] = sum;
}

// ---------------------------------------------------------------------------
__global__ void upsample_kernel(float* __restrict__ out, int out_size)
{
    const float* h2 = g_scratch + OFF_H2;
    int fd = blockIdx.x;
    int f = fd / 384, d = fd % 384;
    __shared__ float ch[256];
    int t = threadIdx.x;
    ch[t] = h2[(size_t)(f * 256 + t) * 384 + d];
    __syncthreads();
    #pragma unroll
    for (int p = 0; p < 4; p++) {
        int o = t + p * 256;
        int oy = o >> 5, ox = o & 31;
        float fy = 0.5f * oy - 0.25f;
        int iy0 = (int)floorf(fy);
        float wy = fy - (float)iy0;
        int iy0c = max(iy0, 0), iy1c = min(iy0 + 1, 15);
        float fx = 0.5f * ox - 0.25f;
        int ix0 = (int)floorf(fx);
        float wx = fx - (float)ix0;
        int ix0c = max(ix0, 0), ix1c = min(ix0 + 1, 15);
        float v00 = ch[iy0c * 16 + ix0c], v01 = ch[iy0c * 16 + ix1c];
        float v10 = ch[iy1c * 16 + ix0c], v11 = ch[iy1c * 16 + ix1c];
        float v = (1.f - wy) * ((1.f - wx) * v00 + wx * v01)
                + wy * ((1.f - wx) * v10 + wx * v11);
        long long oi = (long long)fd * 1024 + o;
        if (oi < (long long)out_size) out[oi] = v;
    }
}

// ---------------------------------------------------------------------------
// bf16 hi/lo split: fp32 [rows][inStride] (first `width` cols) -> two bf16
// ---------------------------------------------------------------------------
__global__ void cvt_split_kernel(long long inOff, int inStride, int width,
                                 long long hiOff, long long loOff)
{
    long long i = (long long)blockIdx.x * 256 + threadIdx.x;
    int row = (int)(i / width);
    int col = (int)(i % width);
    float v = g_scratch[inOff + (long long)row * inStride + col];
    __nv_bfloat16 h = __float2bfloat16(v);
    float rem = v - __bfloat162float(h);
    __nv_bfloat16 l = __float2bfloat16(rem);
    ((__nv_bfloat16*)(g_scratch + hiOff))[i] = h;
    ((__nv_bfloat16*)(g_scratch + loOff))[i] = l;
}

// ===========================================================================
// mma.sync bf16x3 Lg kernel (sm_80+ path; works on plain sm_100 target)
// Lg tile (128 x 128) = q2_h @ VWk_h^T, K=64, splits hh + hl + lh.
// grid (48, 8, 2); 256 threads (8 warps, 4x2); dyn smem 73728 B.
// ===========================================================================

#define MMA_SMEM_BYTES 73728
#define APAD 72   // padded bf16 row stride (144 B, 16B-multiple, conflict-free)

__device__ __forceinline__ void ldsm_x4(uint32_t* r, uint32_t addr)
{
    asm volatile("ldmatrix.sync.aligned.m8n8.x4.shared.b16 {%0,%1,%2,%3}, [%4];"
                 : "=r"(r[0]), "=r"(r[1]), "=r"(r[2]), "=r"(r[3]) : "r"(addr));
}
__device__ __forceinline__ void mma_bf16(float* d, const uint32_t* a, const uint32_t* b)
{
    asm volatile(
        "mma.sync.aligned.m16n8k16.row.col.f32.bf16.bf16.f32 "
        "{%0,%1,%2,%3}, {%4,%5,%6,%7}, {%8,%9}, {%0,%1,%2,%3};"
        : "+f"(d[0]), "+f"(d[1]), "+f"(d[2]), "+f"(d[3])
        : "r"(a[0]), "r"(a[1]), "r"(a[2]), "r"(a[3]), "r"(b[0]), "r"(b[1]));
}

__global__ void __launch_bounds__(256) mma_lg_kernel(int g)
{
    extern __shared__ __align__(16) char dsm[];
    __nv_bfloat16* Ah = (__nv_bfloat16*)dsm;       // [128][APAD]
    __nv_bfloat16* Al = Ah + 128 * APAD;
    __nv_bfloat16* Bh = Al + 128 * APAD;
    __nv_bfloat16* Bl = Bh + 128 * APAD;

    int tid = threadIdx.x;
    int wid = tid >> 5, lid = tid & 31;
    int bn = blockIdx.x * 128;
    int bm = blockIdx.y * 128;
    int hg = blockIdx.z;
    int h = g * 2 + hg;

    const __nv_bfloat16* q2h = (const __nv_bfloat16*)(g_scratch + OFF_XN);
    const __nv_bfloat16* q2l = (const __nv_bfloat16*)(g_scratch + OFF_XN + 196608);
    const __nv_bfloat16* vwh = (const __nv_bfloat16*)(g_scratch + OFF_QKV);
    const __nv_bfloat16* vwl = (const __nv_bfloat16*)(g_scratch + OFF_MLP);

    // load 128 A rows + 128 B rows (64 bf16 each), 2 threads per row
    {
        int r = tid >> 1, half = tid & 1;
        const uint4* sah = (const uint4*)(q2h + (size_t)(bm + r) * 384 + h * 64 + half * 32);
        const uint4* sal = (const uint4*)(q2l + (size_t)(bm + r) * 384 + h * 64 + half * 32);
        uint4* dah = (uint4*)(Ah + r * APAD + half * 32);
        uint4* dal = (uint4*)(Al + r * APAD + half * 32);
        #pragma unroll
        for (int i = 0; i < 4; i++) { dah[i] = sah[i]; dal[i] = sal[i]; }
        const uint4* sbh = (const uint4*)(vwh + (size_t)(bn + r) * 384 + h * 64 + half * 32);
        const uint4* sbl = (const uint4*)(vwl + (size_t)(bn + r) * 384 + h * 64 + half * 32);
        uint4* dbh = (uint4*)(Bh + r * APAD + half * 32);
        uint4* dbl = (uint4*)(Bl + r * APAD + half * 32);
        #pragma unroll
        for (int i = 0; i < 4; i++) { dbh[i] = sbh[i]; dbl[i] = sbl[i]; }
    }
    __syncthreads();

    int warp_m = wid & 3;            // 4 warps over M (32 rows each)
    int warp_n = wid >> 2;           // 2 warps over N (64 cols each)
    int m_base = warp_m * 32;
    int n_base = warp_n * 64;

    float acc[16][4];
    #pragma unroll
    for (int i = 0; i < 16; i++)
        #pragma unroll
        for (int j = 0; j < 4; j++) acc[i][j] = 0.f;

    // A-fragment lane addressing: row = m_base + am*16 + (lid&15), col = k0 + (lid>>4)*8
    int a_row = lid & 15;
    int a_colb = (lid >> 4) * 8;
    // B-fragment (x4 covers 2 n-atoms): row = n_base + p*16 + (lid>>4)*8 + (lid&7),
    // col = k0 + ((lid>>3)&1)*8
    int b_row = (lid >> 4) * 8 + (lid & 7);
    int b_colb = ((lid >> 3) & 1) * 8;

    #pragma unroll
    for (int sp = 0; sp < 3; sp++) {
        const __nv_bfloat16* As = (sp == 2) ? Al : Ah;
        const __nv_bfloat16* Bs = (sp == 1) ? Bl : Bh;
        #pragma unroll
        for (int ks = 0; ks < 4; ks++) {
            int k0 = ks * 16;
            uint32_t afr[2][4];
            #pragma unroll
            for (int am = 0; am < 2; am++) {
                uint32_t addr = smem_to_u32(As + (size_t)(m_base + am * 16 + a_row) * APAD
                                            + k0 + a_colb);
                ldsm_x4(afr[am], addr);
            }
            uint32_t bfr[8][2];
            #pragma unroll
            for (int p = 0; p < 4; p++) {
                uint32_t r4[4];
                uint32_t addr = smem_to_u32(Bs + (size_t)(n_base + p * 16 + b_row) * APAD
                                            + k0 + b_colb);
                ldsm_x4(r4, addr);
                bfr[2 * p + 0][0] = r4[0]; bfr[2 * p + 0][1] = r4[1];
                bfr[2 * p + 1][0] = r4[2]; bfr[2 * p + 1][1] = r4[3];
            }
            #pragma unroll
            for (int am = 0; am < 2; am++)
                #pragma unroll
                for (int an = 0; an < 8; an++)
                    mma_bf16(acc[am * 8 + an], afr[am], bfr[an]);
        }
    }

    // epilogue: D fragment -> Lg fp32
    float* lg = g_scratch + OFF_QK + (long long)hg * LG_STRIDE;
    int gid = lid >> 2, tig = lid & 3;
    #pragma unroll
    for (int am = 0; am < 2; am++) {
        #pragma unroll
        for (int an = 0; an < 8; an++) {
            const float* d = acc[am * 8 + an];
            long long row0 = bm + m_base + am * 16 + gid;
            long long col = bn + n_base + an * 8 + tig * 2;
            float2 v0 = make_float2(d[0], d[1]);
            float2 v1 = make_float2(d[2], d[3]);
            *(float2*)(lg + row0 * 6144 + col) = v0;
            *(float2*)(lg + (row0 + 8) * 6144 + col) = v1;
        }
    }
}

// ---------------------------------------------------------------------------
extern "C" void kernel_launch(void* const* d_in, const int* in_sizes, int n_in,
                              void* d_out, int out_size)
{
    (void)in_sizes; (void)n_in;
    const float* x      = (const float*)d_in[0];
    const float* qkv_w  = (const float*)d_in[1];
    const float* q2_w   = (const float*)d_in[2];
    const float* kv2_w  = (const float*)d_in[3];
    const float* proj_w = (const float*)d_in[4];
    const float* proj_b = (const float*)d_in[5];
    const float* ln1_g  = (const float*)d_in[6];
    const float* ln1_b  = (const float*)d_in[7];
    const float* ln2_g  = (const float*)d_in[8];
    const float* ln2_b  = (const float*)d_in[9];
    const float* fc1_w  = (const float*)d_in[10];
    const float* fc1_b  = (const float*)d_in[11];
    const float* fc2_w  = (const float*)d_in[12];
    const float* fc2_b  = (const float*)d_in[13];
    float* out = (float*)d_out;

    cudaFuncSetAttribute(mma_lg_kernel,
                         cudaFuncAttributeMaxDynamicSharedMemorySize, MMA_SMEM_BYTES);

    pool_kernel<<<1536, 256>>>(x);
    ln_kernel<<<1024, 384>>>(OFF_TOK, ln1_g, ln1_b, OFF_XN);

    // qkv = xn @ qkv_w   (1024 x 1152 x 384, NN)
    gemm128_kernel<<<dim3(9, 8, 1), 256>>>(OFF_XN, qkv_w, 0, nullptr, OFF_QKV,
        384, 384, 1152, 1152, 0, 0, 0, 1.0f, 0);

    // VW[h'] = v_h' @ kv2_w[h' slice]   (6 batched NN, K=64)
    gemm128_kernel<<<dim3(6, 8, 6), 256>>>(OFF_QKV + 768, kv2_w, 0, nullptr, OFF_VW,
        64, 1152, 768, 768, 64, 49152, 786432, 1.0f, 0);

    // qk[h] = q_h @ k_h^T   (6 batched NT, K=64)
    gemm128_kernel<<<dim3(8, 8, 6), 256>>>(OFF_QKV, nullptr, OFF_QKV + 384, nullptr, OFF_QK,
        64, 1152, 1152, 1024, 64, 64, 1048576, 1.0f, 8);

    ta_kernel<<<6144, 256>>>();
    xdiag_kernel<<<1024, 384>>>();

    // q2 = SCALE * x_diag @ q2_w
    gemm64_kernel<<<dim3(6, 8, 1), 256>>>(OFF_XD, q2_w, 0, nullptr, 0, OFF_Q2,
        1024, 384, 384, 384, 384, 384, 0, 0, 0, 0, SCALE, 0, 1, 1);

    // bf16 hi/lo splits: q2 -> XN region; VW k-half -> QKV / MLP regions
    cvt_split_kernel<<<1536, 256>>>(OFF_Q2, 384, 384, OFF_XN, OFF_XN + 196608);
    cvt_split_kernel<<<9216, 256>>>(OFF_VW, 768, 384, OFF_QKV, OFF_MLP);

    int wout = (out_size >= 3145728) ? 1 : 0;

    // stage 2 in 3 groups of 2 heads (Lg overlays dead QK + LG regions)
    for (int g = 0; g < 3; g++) {
        mma_lg_kernel<<<dim3(48, 8, 2), 256, MMA_SMEM_BYTES>>>(g);

        middle_kernel<<<dim3(1024, 2), 256>>>(g, out + 1572864, wout);

        gemm64_kernel<<<dim3(1, 8, 24), 256>>>(OFF_QK, nullptr, OFF_VW + 384 + g * 128,
            nullptr, 0, OFF_OPART,
            1024, 64, 6144, 6144, 768, 64, 0, LG_STRIDE, 64, 65536, 1.0f, 0, 2, 12);

        oreduce_kernel<<<512, 256>>>(g);
    }

    // h1 = tok + (o @ proj_w + proj_b)
    gemm64_kernel<<<dim3(6, 8, 1), 256>>>(OFF_O, proj_w, 0, proj_b, OFF_TOK, OFF_H1,
        1024, 384, 384, 384, 384, 384, 384, 0, 0, 0, 1.0f, 1 | 2, 1, 1);

    ln_kernel<<<1024, 384>>>(OFF_H1, ln2_g, ln2_b, OFF_HN);

    // mlp
    gemm128_kernel<<<dim3(12, 8, 1), 256>>>(OFF_HN, fc1_w, 0, fc1_b, OFF_MLP,
        384, 384, 1536, 1536, 0, 0, 0, 1.0f, 1 | 4);
    gemm64_kernel<<<dim3(6, 8, 1), 256>>>(OFF_MLP, fc2_w, 0, fc2_b, OFF_H1, OFF_H2,
        1024, 384, 1536, 1536, 384, 384, 384, 0, 0, 0, 1.0f, 1 | 2, 1, 1);

    upsample_kernel<<<1536, 256>>>(out, out_size);
}

// round 11
// speedup vs baseline: 1.2481x; 1.0654x over previous
#include <cuda_runtime.h>
#include <cuda_bf16.h>
#include <cstdint>
#include <math.h>

// ---------------------------------------------------------------------------
// DeformationTrajectoryAttentionBlock — fp32 + mma.sync bf16x3 (Lg + o GEMMs).
// B=1, F=4, H=6, D=384, G=16, S=256, N=1024, HD=64, IMG=32, MLP_HID=1536
// ---------------------------------------------------------------------------

#define SCALE 0.125f
#define LN_EPS 1e-5f
typedef unsigned long long ull;

#define OFF_TOK    0LL          // 1024*384
#define OFF_XN     393216LL     // reused: q2h bf16 @ +0, q2l bf16 @ +196608
#define OFF_QKV    786432LL     // 1024*1152 ; reused: VWk-hi bf16
#define OFF_VW     1966080LL    // 6*1024*768 (6144 x 768)
#define OFF_QK     6684672LL    // 6*1024*1024 ; reused as Lg[hg=0] / AB bf16
#define OFF_TA     12976128LL   // 1024*256*24
#define OFF_XD     19267584LL
#define OFF_Q2     19660800LL
#define OFF_LG     20054016LL   // 1024*6144 ; Lg[hg=1] / AB bf16
#define LG_STRIDE  13369344LL   // OFF_LG - OFF_QK
#define OFF_OPART  26345472LL   // 24 * 1024*64
#define OFF_O      27918336LL
#define OFF_H1     28311552LL
#define OFF_HN     28704768LL
#define OFF_MLP    29097984LL   // 1024*1536 ; reused earlier: VWk-lo bf16
#define OFF_H2     30670848LL
#define OFF_VWTH   31064064LL   // VWv^T hi bf16 [6][64][6144] (1179648 floats)
#define OFF_VWTL   32243712LL   // VWv^T lo bf16
#define SCRATCH_FLOATS 33423360LL

static __device__ float g_scratch[SCRATCH_FLOATS];

// ---- packed f32x2 helpers (R6-proven) --------------------------------------
__device__ __forceinline__ ull pack2b(float x)
{
    ull r;
    asm("mov.b64 %0, {%1, %1};" : "=l"(r) : "f"(x));
    return r;
}
__device__ __forceinline__ void fma2(ull& acc, ull a, ull b)
{
    asm("fma.rn.f32x2 %0, %1, %2, %0;" : "+l"(acc) : "l"(a), "l"(b));
}
__device__ __forceinline__ void unpack2(ull v, float& x, float& y)
{
    asm("mov.b64 {%0, %1}, %2;" : "=f"(x), "=f"(y) : "l"(v));
}
__device__ __forceinline__ uint32_t smem_to_u32(const void* smem_ptr)
{
    uint32_t addr;
    asm("{ .reg .u64 tmp; cvta.to.shared.u64 tmp, %1; cvt.u32.u64 %0, tmp; }"
        : "=r"(addr) : "l"(smem_ptr));
    return addr;
}

// ---------------------------------------------------------------------------
__global__ void pool_kernel(const float* __restrict__ x)
{
    float* tok = g_scratch + OFF_TOK;
    int fd = blockIdx.x;
    int f = fd / 384;
    const float* xp = x + (size_t)fd * 1024;
    int t = threadIdx.x;
    int gy = t >> 4, gx = t & 15;
    const float* p = xp + (gy * 2) * 32 + gx * 2;
    float m = fmaxf(fmaxf(p[0], p[1]), fmaxf(p[32], p[33]));
    tok[(size_t)(f * 256 + t) * 384 + (fd % 384)] = m;
}

// ---------------------------------------------------------------------------
__global__ void ln_kernel(long long inOff, const float* __restrict__ g,
                          const float* __restrict__ b, long long outOff)
{
    const float* in = g_scratch + inOff;
    float* out = g_scratch + outOff;
    int n = blockIdx.x, t = threadIdx.x;
    float x = in[(size_t)n * 384 + t];
    __shared__ float red[12];
    __shared__ float mv[2];
    float s = x;
    #pragma unroll
    for (int o = 16; o; o >>= 1) s += __shfl_xor_sync(0xffffffffu, s, o);
    if ((t & 31) == 0) red[t >> 5] = s;
    __syncthreads();
    if (t == 0) { float tt = 0.f; for (int i = 0; i < 12; i++) tt += red[i]; mv[0] = tt * (1.0f / 384.0f); }
    __syncthreads();
    float mean = mv[0];
    float d = x - mean;
    s = d * d;
    #pragma unroll
    for (int o = 16; o; o >>= 1) s += __shfl_xor_sync(0xffffffffu, s, o);
    if ((t & 31) == 0) red[t >> 5] = s;
    __syncthreads();
    if (t == 0) { float tt = 0.f; for (int i = 0; i < 12; i++) tt += red[i]; mv[1] = rsqrtf(tt * (1.0f / 384.0f) + LN_EPS); }
    __syncthreads();
    out[(size_t)n * 384 + t] = d * mv[1] * g[t] + b[t];
}

// ---------------------------------------------------------------------------
// gemm128 (R6-proven): 128x128x16, 8x8 microtile (f32x2), dbl-buffered.
// flags: 1=bias 4=gelu 8=NT.
// ---------------------------------------------------------------------------
__global__ void __launch_bounds__(256, 2) gemm128_kernel(
    long long aOff, const float* __restrict__ Bp, long long bOff,
    const float* __restrict__ bias, long long cOff,
    int K, int lda, int ldb, int ldc,
    long long sA, long long sB, long long sC,
    float alpha, int flags)
{
    int z = blockIdx.z;
    const float* A = g_scratch + aOff + (long long)z * sA;
    const float* B = (Bp ? Bp : g_scratch + bOff) + (long long)z * sB;
    float* C = g_scratch + cOff + (long long)z * sC;

    __shared__ __align__(16) float As[2][16][128];
    __shared__ __align__(16) float Bs[2][16][128];

    int bm = blockIdx.y * 128, bn = blockIdx.x * 128;
    int tid = threadIdx.x;
    int r2 = tid >> 1, k8 = (tid & 1) * 8;
    int bk = tid >> 4, c8 = (tid & 15) * 8;
    int ty = tid >> 4, tx = tid & 15;

    int nt = K / 16;
    float4 ar0, ar1, br0, br1;

    {
        const float* ap = A + (long long)(bm + r2) * lda + k8;
        ar0 = *(const float4*)ap; ar1 = *(const float4*)(ap + 4);
        As[0][k8 + 0][r2] = ar0.x; As[0][k8 + 1][r2] = ar0.y;
        As[0][k8 + 2][r2] = ar0.z; As[0][k8 + 3][r2] = ar0.w;
        As[0][k8 + 4][r2] = ar1.x; As[0][k8 + 5][r2] = ar1.y;
        As[0][k8 + 6][r2] = ar1.z; As[0][k8 + 7][r2] = ar1.w;
        if (flags & 8) {
            const float* bp = B + (long long)(bn + r2) * ldb + k8;
            br0 = *(const float4*)bp; br1 = *(const float4*)(bp + 4);
            Bs[0][k8 + 0][r2] = br0.x; Bs[0][k8 + 1][r2] = br0.y;
            Bs[0][k8 + 2][r2] = br0.z; Bs[0][k8 + 3][r2] = br0.w;
            Bs[0][k8 + 4][r2] = br1.x; Bs[0][k8 + 5][r2] = br1.y;
            Bs[0][k8 + 6][r2] = br1.z; Bs[0][k8 + 7][r2] = br1.w;
        } else {
            const float* bp = B + (long long)bk * ldb + bn + c8;
            br0 = *(const float4*)bp; br1 = *(const float4*)(bp + 4);
            *(float4*)&Bs[0][bk][c8] = br0;
            *(float4*)&Bs[0][bk][c8 + 4] = br1;
        }
    }
    __syncthreads();

    ull acc2[8][4];
    #pragma unroll
    for (int i = 0; i < 8; i++)
        #pragma unroll
        for (int j = 0; j < 4; j++) acc2[i][j] = 0ULL;

    for (int kt = 0; kt < nt; kt++) {
        int cur = kt & 1;
        bool pf = (kt + 1 < nt);
        if (pf) {
            int k0 = (kt + 1) * 16;
            const float* ap = A + (long long)(bm + r2) * lda + k0 + k8;
            ar0 = *(const float4*)ap; ar1 = *(const float4*)(ap + 4);
            if (flags & 8) {
                const float* bp = B + (long long)(bn + r2) * ldb + k0 + k8;
                br0 = *(const float4*)bp; br1 = *(const float4*)(bp + 4);
            } else {
                const float* bp = B + (long long)(k0 + bk) * ldb + bn + c8;
                br0 = *(const float4*)bp; br1 = *(const float4*)(bp + 4);
            }
        }
        #pragma unroll
        for (int kk = 0; kk < 16; kk++) {
            float a[8];
            *(float4*)&a[0] = *(const float4*)&As[cur][kk][ty * 8];
            *(float4*)&a[4] = *(const float4*)&As[cur][kk][ty * 8 + 4];
            const ull* bsp = (const ull*)&Bs[cur][kk][tx * 8];
            ull b0 = bsp[0], b1 = bsp[1], b2 = bsp[2], b3 = bsp[3];
            #pragma unroll
            for (int i = 0; i < 8; i++) {
                ull pa = pack2b(a[i]);
                fma2(acc2[i][0], pa, b0);
                fma2(acc2[i][1], pa, b1);
                fma2(acc2[i][2], pa, b2);
                fma2(acc2[i][3], pa, b3);
            }
        }
        if (pf) {
            int nx = 1 - cur;
            As[nx][k8 + 0][r2] = ar0.x; As[nx][k8 + 1][r2] = ar0.y;
            As[nx][k8 + 2][r2] = ar0.z; As[nx][k8 + 3][r2] = ar0.w;
            As[nx][k8 + 4][r2] = ar1.x; As[nx][k8 + 5][r2] = ar1.y;
            As[nx][k8 + 6][r2] = ar1.z; As[nx][k8 + 7][r2] = ar1.w;
            if (flags & 8) {
                Bs[nx][k8 + 0][r2] = br0.x; Bs[nx][k8 + 1][r2] = br0.y;
                Bs[nx][k8 + 2][r2] = br0.z; Bs[nx][k8 + 3][r2] = br0.w;
                Bs[nx][k8 + 4][r2] = br1.x; Bs[nx][k8 + 5][r2] = br1.y;
                Bs[nx][k8 + 6][r2] = br1.z; Bs[nx][k8 + 7][r2] = br1.w;
            } else {
                *(float4*)&Bs[nx][bk][c8] = br0;
                *(float4*)&Bs[nx][bk][c8 + 4] = br1;
            }
            __syncthreads();
        }
    }

    int row0 = bm + ty * 8, col0 = bn + tx * 8;
    #pragma unroll
    for (int i = 0; i < 8; i++) {
        float v[8];
        #pragma unroll
        for (int j = 0; j < 4; j++)
            unpack2(acc2[i][j], v[2 * j], v[2 * j + 1]);
        #pragma unroll
        for (int j = 0; j < 8; j++) {
            float t = alpha * v[j];
            if (flags & 1) t += bias[col0 + j];
            if (flags & 4) t = 0.5f * t * (1.0f + erff(t * 0.7071067811865476f));
            v[j] = t;
        }
        float* cp = C + (long long)(row0 + i) * ldc + col0;
        *(float4*)cp = *(float4*)&v[0];
        *(float4*)(cp + 4) = *(float4*)&v[4];
    }
}

// ---------------------------------------------------------------------------
// gemm64 (R6-proven): 128x64x16, 8x4 microtile (f32x2).
// flags: 1=bias 2=residual 4=gelu 8=NT. z: zb=z%nB batch, zk=z/nB K-split.
// ---------------------------------------------------------------------------
__global__ void __launch_bounds__(256) gemm64_kernel(
    long long aOff, const float* __restrict__ Bp, long long bOff,
    const float* __restrict__ bias, long long rOff, long long cOff,
    int M, int N, int K, int lda, int ldb, int ldc, int ldr,
    long long sA, long long sB, long long sC,
    float alpha, int flags, int nB, int ksplit)
{
    int z = blockIdx.z;
    int zb = z % nB, zk = z / nB;
    int Kloc = K / ksplit;
    const float* A = g_scratch + aOff + (long long)zb * sA + (long long)zk * Kloc;
    const float* Bb = (Bp ? Bp : g_scratch + bOff) + (long long)zb * sB;
    const float* B = Bb + ((flags & 8) ? (long long)zk * Kloc
                                       : (long long)zk * Kloc * ldb);
    float* C = g_scratch + cOff + (long long)z * sC;

    __shared__ __align__(16) float As[2][16][128];
    __shared__ __align__(16) float Bs[2][16][64];

    int bm = blockIdx.y * 128, bn = blockIdx.x * 64;
    int tid = threadIdx.x;
    int a_r = tid >> 1, a_k = (tid & 1) * 8;
    int tx = tid & 15, ty = tid >> 4;

    int nt = Kloc / 16;
    float4 ar0, ar1, br0;

    {
        const float* ap = A + (long long)(bm + a_r) * lda + a_k;
        ar0 = *(const float4*)ap; ar1 = *(const float4*)(ap + 4);
        As[0][a_k + 0][a_r] = ar0.x; As[0][a_k + 1][a_r] = ar0.y;
        As[0][a_k + 2][a_r] = ar0.z; As[0][a_k + 3][a_r] = ar0.w;
        As[0][a_k + 4][a_r] = ar1.x; As[0][a_k + 5][a_r] = ar1.y;
        As[0][a_k + 6][a_r] = ar1.z; As[0][a_k + 7][a_r] = ar1.w;
        if (flags & 8) {
            int r = tid >> 2, k4 = (tid & 3) * 4;
            br0 = *(const float4*)(B + (long long)(bn + r) * ldb + k4);
            Bs[0][k4 + 0][r] = br0.x; Bs[0][k4 + 1][r] = br0.y;
            Bs[0][k4 + 2][r] = br0.z; Bs[0][k4 + 3][r] = br0.w;
        } else {
            int kk = tid >> 4, n4 = (tid & 15) * 4;
            br0 = *(const float4*)(B + (long long)kk * ldb + bn + n4);
            *(float4*)&Bs[0][kk][n4] = br0;
        }
    }
    __syncthreads();

    ull acc2[8][2];
    #pragma unroll
    for (int i = 0; i < 8; i++) { acc2[i][0] = 0ULL; acc2[i][1] = 0ULL; }

    for (int kt = 0; kt < nt; kt++) {
        int cur = kt & 1;
        bool pf = (kt + 1 < nt);
        if (pf) {
            int k0 = (kt + 1) * 16;
            const float* ap = A + (long long)(bm + a_r) * lda + k0 + a_k;
            ar0 = *(const float4*)ap; ar1 = *(const float4*)(ap + 4);
            if (flags & 8) {
                int r = tid >> 2, k4 = (tid & 3) * 4;
                br0 = *(const float4*)(B + (long long)(bn + r) * ldb + k0 + k4);
            } else {
                int kk = tid >> 4, n4 = (tid & 15) * 4;
                br0 = *(const float4*)(B + (long long)(k0 + kk) * ldb + bn + n4);
            }
        }
        #pragma unroll
        for (int kk = 0; kk < 16; kk++) {
            float a[8];
            *(float4*)&a[0] = *(const float4*)&As[cur][kk][ty * 8];
            *(float4*)&a[4] = *(const float4*)&As[cur][kk][ty * 8 + 4];
            const ull* bsp = (const ull*)&Bs[cur][kk][tx * 4];
            ull b0 = bsp[0], b1 = bsp[1];
            #pragma unroll
            for (int i = 0; i < 8; i++) {
                ull pa = pack2b(a[i]);
                fma2(acc2[i][0], pa, b0);
                fma2(acc2[i][1], pa, b1);
            }
        }
        if (pf) {
            int nx = 1 - cur;
            As[nx][a_k + 0][a_r] = ar0.x; As[nx][a_k + 1][a_r] = ar0.y;
            As[nx][a_k + 2][a_r] = ar0.z; As[nx][a_k + 3][a_r] = ar0.w;
            As[nx][a_k + 4][a_r] = ar1.x; As[nx][a_k + 5][a_r] = ar1.y;
            As[nx][a_k + 6][a_r] = ar1.z; As[nx][a_k + 7][a_r] = ar1.w;
            if (flags & 8) {
                int r = tid >> 2, k4 = (tid & 3) * 4;
                Bs[nx][k4 + 0][r] = br0.x; Bs[nx][k4 + 1][r] = br0.y;
                Bs[nx][k4 + 2][r] = br0.z; Bs[nx][k4 + 3][r] = br0.w;
            } else {
                int kk = tid >> 4, n4 = (tid & 15) * 4;
                *(float4*)&Bs[nx][kk][n4] = br0;
            }
            __syncthreads();
        }
    }

    int row0 = bm + ty * 8, col0 = bn + tx * 4;
    const float* R = g_scratch + rOff;
    #pragma unroll
    for (int i = 0; i < 8; i++) {
        float v[4];
        unpack2(acc2[i][0], v[0], v[1]);
        unpack2(acc2[i][1], v[2], v[3]);
        #pragma unroll
        for (int j = 0; j < 4; j++) {
            float t = alpha * v[j];
            if (flags & 1) t += bias[col0 + j];
            if (flags & 4) t = 0.5f * t * (1.0f + erff(t * 0.7071067811865476f));
            if (flags & 2) t += R[(long long)(row0 + i) * ldr + col0 + j];
            C[(long long)(row0 + i) * ldc + col0 + j] = t;
        }
    }
}

// ---------------------------------------------------------------------------
__global__ void ta_kernel()
{
    const float* qk = g_scratch + OFF_QK;
    float* ta = g_scratch + OFF_TA;
    int b = blockIdx.x;
    int h = b >> 10, n = b & 1023;
    int s = threadIdx.x;
    const float* p = qk + ((size_t)b << 10) + s;
    float x0 = SCALE * p[0], x1 = SCALE * p[256], x2 = SCALE * p[512], x3 = SCALE * p[768];
    float m = fmaxf(fmaxf(x0, x1), fmaxf(x2, x3));
    float e0 = expf(x0 - m), e1 = expf(x1 - m), e2 = expf(x2 - m), e3 = expf(x3 - m);
    float inv = 1.0f / (e0 + e1 + e2 + e3);
    float* o = ta + ((size_t)(n * 256 + s)) * 24 + h * 4;
    o[0] = e0 * inv; o[1] = e1 * inv; o[2] = e2 * inv; o[3] = e3 * inv;
}

// ---------------------------------------------------------------------------
__global__ void xdiag_kernel()
{
    const float* ta = g_scratch + OFF_TA;
    const float* qkv = g_scratch + OFF_QKV;
    float* xd = g_scratch + OFF_XD;
    int n = blockIdx.x, c = threadIdx.x;
    int h = c >> 6;
    int s = n & 255;
    const float* tp = ta + ((size_t)(n * 256 + s)) * 24 + h * 4;
    float acc = 0.f;
    #pragma unroll
    for (int f = 0; f < 4; f++)
        acc += tp[f] * qkv[(size_t)(f * 256 + s) * 1152 + 768 + c];
    xd[(size_t)n * 384 + c] = acc;
}

// ---------------------------------------------------------------------------
// middle: logits + softmax + AB written IN PLACE as bf16 hi/lo over Lg row.
// Row layout after this kernel (viewed as bf16[12288]): hi[k] at [k],
// lo[k] at [6144+k], k = j*256+s.
// ---------------------------------------------------------------------------
__global__ void __launch_bounds__(256) middle_kernel(int g, float* __restrict__ out_attn,
                                                     int write_out)
{
    int n = blockIdx.x;
    int hg = blockIdx.y;
    int s = threadIdx.x;
    __shared__ __align__(16) float sta[256][24];
    __shared__ float red[8];
    __shared__ float mv[2];

    const float4* tap = (const float4*)(g_scratch + OFF_TA + (size_t)n * 6144);
    float4* stp = (float4*)&sta[0][0];
    for (int idx = s; idx < 1536; idx += 256)
        stp[idx] = tap[idx];
    __syncthreads();

    float* lg = g_scratch + OFF_QK + (long long)hg * LG_STRIDE + (size_t)n * 6144;
    float logit = 0.f;
    float lgv[24];
    #pragma unroll
    for (int j = 0; j < 24; j++) {
        lgv[j] = lg[j * 256 + s];
        logit += sta[s][j] * lgv[j];
    }

    float m = logit;
    #pragma unroll
    for (int o = 16; o; o >>= 1) m = fmaxf(m, __shfl_xor_sync(0xffffffffu, m, o));
    if ((s & 31) == 0) red[s >> 5] = m;
    __syncthreads();
    if (s == 0) { float t = red[0]; for (int i = 1; i < 8; i++) t = fmaxf(t, red[i]); mv[0] = t; }
    __syncthreads();
    float e = expf(logit - mv[0]);
    float sum = e;
    #pragma unroll
    for (int o = 16; o; o >>= 1) sum += __shfl_xor_sync(0xffffffffu, sum, o);
    if ((s & 31) == 0) red[s >> 5] = sum;
    __syncthreads();
    if (s == 0) { float t = 0.f; for (int i = 0; i < 8; i++) t += red[i]; mv[1] = 1.0f / t; }
    __syncthreads();
    float sa = e * mv[1];
    if (write_out) out_attn[((size_t)(g * 2 + hg) * 1024 + n) * 256 + s] = sa;
    __nv_bfloat16* ab = (__nv_bfloat16*)lg;
    #pragma unroll
    for (int j = 0; j < 24; j++) {
        float v = sa * sta[s][j];
        __nv_bfloat16 hi = __float2bfloat16(v);
        __nv_bfloat16 lo = __float2bfloat16(v - __bfloat162float(hi));
        ab[j * 256 + s] = hi;
        ab[6144 + j * 256 + s] = lo;
    }
}

// ---------------------------------------------------------------------------
__global__ void oreduce_kernel(int g)
{
    const float* opart = g_scratch + OFF_OPART;
    float* o = g_scratch + OFF_O;
    int i = blockIdx.x * 256 + threadIdx.x;       // < 131072
    int hg = i >> 16;
    int r = i & 65535;
    float sum = 0.f;
    #pragma unroll
    for (int zk = 0; zk < 12; zk++)
        sum += opart[(size_t)(zk * 2 + hg) * 65536 + r];
    o[(size_t)(r >> 6) * 384 + (g * 2 + hg) * 64 + (r & 63)] = sum;
}

// ---------------------------------------------------------------------------
__global__ void upsample_kernel(float* __restrict__ out, int out_size)
{
    const float* h2 = g_scratch + OFF_H2;
    int fd = blockIdx.x;
    int f = fd / 384, d = fd % 384;
    __shared__ float ch[256];
    int t = threadIdx.x;
    ch[t] = h2[(size_t)(f * 256 + t) * 384 + d];
    __syncthreads();
    #pragma unroll
    for (int p = 0; p < 4; p++) {
        int o = t + p * 256;
        int oy = o >> 5, ox = o & 31;
        float fy = 0.5f * oy - 0.25f;
        int iy0 = (int)floorf(fy);
        float wy = fy - (float)iy0;
        int iy0c = max(iy0, 0), iy1c = min(iy0 + 1, 15);
        float fx = 0.5f * ox - 0.25f;
        int ix0 = (int)floorf(fx);
        float wx = fx - (float)ix0;
        int ix0c = max(ix0, 0), ix1c = min(ix0 + 1, 15);
        float v00 = ch[iy0c * 16 + ix0c], v01 = ch[iy0c * 16 + ix1c];
        float v10 = ch[iy1c * 16 + ix0c], v11 = ch[iy1c * 16 + ix1c];
        float v = (1.f - wy) * ((1.f - wx) * v00 + wx * v01)
                + wy * ((1.f - wx) * v10 + wx * v11);
        long long oi = (long long)fd * 1024 + o;
        if (oi < (long long)out_size) out[oi] = v;
    }
}

// ---------------------------------------------------------------------------
// bf16 hi/lo split: fp32 [rows][inStride] (first `width` cols) -> two bf16
// ---------------------------------------------------------------------------
__global__ void cvt_split_kernel(long long inOff, int inStride, int width,
                                 long long hiOff, long long loOff)
{
    long long i = (long long)blockIdx.x * 256 + threadIdx.x;
    int row = (int)(i / width);
    int col = (int)(i % width);
    float v = g_scratch[inOff + (long long)row * inStride + col];
    __nv_bfloat16 h = __float2bfloat16(v);
    float rem = v - __bfloat162float(h);
    __nv_bfloat16 l = __float2bfloat16(rem);
    ((__nv_bfloat16*)(g_scratch + hiOff))[i] = h;
    ((__nv_bfloat16*)(g_scratch + loOff))[i] = l;
}

// ---------------------------------------------------------------------------
// cvt_vwt: transpose-split VWv -> VWvT[h][n=64][k=6144] bf16 hi/lo.
// grid (96, 6), 256 threads; smem 64x64 fp32 tile.
// ---------------------------------------------------------------------------
__global__ void cvt_vwt_kernel()
{
    __shared__ float tile[64][65];
    int kt = blockIdx.x * 64;
    int h = blockIdx.y;
    int tid = threadIdx.x;
    for (int i = tid; i < 4096; i += 256) {
        int k = i >> 6, n = i & 63;
        tile[k][n] = g_scratch[OFF_VW + (size_t)(kt + k) * 768 + 384 + h * 64 + n];
    }
    __syncthreads();
    __nv_bfloat16* vh = (__nv_bfloat16*)(g_scratch + OFF_VWTH);
    __nv_bfloat16* vl = (__nv_bfloat16*)(g_scratch + OFF_VWTL);
    for (int i = tid; i < 4096; i += 256) {
        int n = i >> 6, k = i & 63;
        float v = tile[k][n];
        __nv_bfloat16 hi = __float2bfloat16(v);
        __nv_bfloat16 lo = __float2bfloat16(v - __bfloat162float(hi));
        size_t idx = ((size_t)h * 64 + n) * 6144 + kt + k;
        vh[idx] = hi;
        vl[idx] = lo;
    }
}

// ===========================================================================
// mma.sync helpers (R10-proven)
// ===========================================================================
__device__ __forceinline__ void ldsm_x4(uint32_t* r, uint32_t addr)
{
    asm volatile("ldmatrix.sync.aligned.m8n8.x4.shared.b16 {%0,%1,%2,%3}, [%4];"
                 : "=r"(r[0]), "=r"(r[1]), "=r"(r[2]), "=r"(r[3]) : "r"(addr));
}
__device__ __forceinline__ void mma_bf16(float* d, const uint32_t* a, const uint32_t* b)
{
    asm volatile(
        "mma.sync.aligned.m16n8k16.row.col.f32.bf16.bf16.f32 "
        "{%0,%1,%2,%3}, {%4,%5,%6,%7}, {%8,%9}, {%0,%1,%2,%3};"
        : "+f"(d[0]), "+f"(d[1]), "+f"(d[2]), "+f"(d[3])
        : "r"(a[0]), "r"(a[1]), "r"(a[2]), "r"(a[3]), "r"(b[0]), "r"(b[1]));
}

#define MMA_SMEM_BYTES 73728
#define APAD 72   // padded bf16 row stride (144 B)

// ===========================================================================
// mma_lg (R10-proven): Lg tile (128 x 128) = q2_h @ VWk_h^T, K=64, x3 splits.
// grid (48, 8, 2); 256 threads (8 warps, 4x2); dyn smem 73728 B.
// ===========================================================================
__global__ void __launch_bounds__(256) mma_lg_kernel(int g)
{
    extern __shared__ __align__(16) char dsm[];
    __nv_bfloat16* Ah = (__nv_bfloat16*)dsm;       // [128][APAD]
    __nv_bfloat16* Al = Ah + 128 * APAD;
    __nv_bfloat16* Bh = Al + 128 * APAD;
    __nv_bfloat16* Bl = Bh + 128 * APAD;

    int tid = threadIdx.x;
    int wid = tid >> 5, lid = tid & 31;
    int bn = blockIdx.x * 128;
    int bm = blockIdx.y * 128;
    int hg = blockIdx.z;
    int h = g * 2 + hg;

    const __nv_bfloat16* q2h = (const __nv_bfloat16*)(g_scratch + OFF_XN);
    const __nv_bfloat16* q2l = (const __nv_bfloat16*)(g_scratch + OFF_XN + 196608);
    const __nv_bfloat16* vwh = (const __nv_bfloat16*)(g_scratch + OFF_QKV);
    const __nv_bfloat16* vwl = (const __nv_bfloat16*)(g_scratch + OFF_MLP);

    {
        int r = tid >> 1, half = tid & 1;
        const uint4* sah = (const uint4*)(q2h + (size_t)(bm + r) * 384 + h * 64 + half * 32);
        const uint4* sal = (const uint4*)(q2l + (size_t)(bm + r) * 384 + h * 64 + half * 32);
        uint4* dah = (uint4*)(Ah + r * APAD + half * 32);
        uint4* dal = (uint4*)(Al + r * APAD + half * 32);
        #pragma unroll
        for (int i = 0; i < 4; i++) { dah[i] = sah[i]; dal[i] = sal[i]; }
        const uint4* sbh = (const uint4*)(vwh + (size_t)(bn + r) * 384 + h * 64 + half * 32);
        const uint4* sbl = (const uint4*)(vwl + (size_t)(bn + r) * 384 + h * 64 + half * 32);
        uint4* dbh = (uint4*)(Bh + r * APAD + half * 32);
        uint4* dbl = (uint4*)(Bl + r * APAD + half * 32);
        #pragma unroll
        for (int i = 0; i < 4; i++) { dbh[i] = sbh[i]; dbl[i] = sbl[i]; }
    }
    __syncthreads();

    int warp_m = wid & 3;
    int warp_n = wid >> 2;
    int m_base = warp_m * 32;
    int n_base = warp_n * 64;

    float acc[16][4];
    #pragma unroll
    for (int i = 0; i < 16; i++)
        #pragma unroll
        for (int j = 0; j < 4; j++) acc[i][j] = 0.f;

    int a_row = lid & 15;
    int a_colb = (lid >> 4) * 8;
    int b_row = (lid >> 4) * 8 + (lid & 7);
    int b_colb = ((lid >> 3) & 1) * 8;

    #pragma unroll
    for (int sp = 0; sp < 3; sp++) {
        const __nv_bfloat16* As = (sp == 2) ? Al : Ah;
        const __nv_bfloat16* Bs = (sp == 1) ? Bl : Bh;
        #pragma unroll
        for (int ks = 0; ks < 4; ks++) {
            int k0 = ks * 16;
            uint32_t afr[2][4];
            #pragma unroll
            for (int am = 0; am < 2; am++) {
                uint32_t addr = smem_to_u32(As + (size_t)(m_base + am * 16 + a_row) * APAD
                                            + k0 + a_colb);
                ldsm_x4(afr[am], addr);
            }
            uint32_t bfr[8][2];
            #pragma unroll
            for (int p = 0; p < 4; p++) {
                uint32_t r4[4];
                uint32_t addr = smem_to_u32(Bs + (size_t)(n_base + p * 16 + b_row) * APAD
                                            + k0 + b_colb);
                ldsm_x4(r4, addr);
                bfr[2 * p + 0][0] = r4[0]; bfr[2 * p + 0][1] = r4[1];
                bfr[2 * p + 1][0] = r4[2]; bfr[2 * p + 1][1] = r4[3];
            }
            #pragma unroll
            for (int am = 0; am < 2; am++)
                #pragma unroll
                for (int an = 0; an < 8; an++)
                    mma_bf16(acc[am * 8 + an], afr[am], bfr[an]);
        }
    }

    float* lg = g_scratch + OFF_QK + (long long)hg * LG_STRIDE;
    int gid = lid >> 2, tig = lid & 3;
    #pragma unroll
    for (int am = 0; am < 2; am++) {
        #pragma unroll
        for (int an = 0; an < 8; an++) {
            const float* d = acc[am * 8 + an];
            long long row0 = bm + m_base + am * 16 + gid;
            long long col = bn + n_base + an * 8 + tig * 2;
            float2 v0 = make_float2(d[0], d[1]);
            float2 v1 = make_float2(d[2], d[3]);
            *(float2*)(lg + row0 * 6144 + col) = v0;
            *(float2*)(lg + (row0 + 8) * 6144 + col) = v1;
        }
    }
}

// ===========================================================================
// mma_o: o partials (128 x 64) = AB(bf16 hi/lo) @ VWvT(bf16 hi/lo)^T,
// K chunk = 512 per split. grid (12, 8, 2); 256 threads (8 warps, 4x2).
// dyn smem: Ah/Al 128x72, Bh/Bl 64x72 bf16 = 55296 B.
// ===========================================================================
#define MMAO_SMEM_BYTES 55296

__global__ void __launch_bounds__(256) mma_o_kernel(int g)
{
    extern __shared__ __align__(16) char dsm[];
    __nv_bfloat16* Ah = (__nv_bfloat16*)dsm;       // [128][APAD]
    __nv_bfloat16* Al = Ah + 128 * APAD;
    __nv_bfloat16* Bh = Al + 128 * APAD;           // [64][APAD]
    __nv_bfloat16* Bl = Bh + 64 * APAD;

    int tid = threadIdx.x;
    int wid = tid >> 5, lid = tid & 31;
    int zk = blockIdx.x;
    int bm = blockIdx.y * 128;
    int hg = blockIdx.z;
    int h = g * 2 + hg;

    const __nv_bfloat16* ab = (const __nv_bfloat16*)(g_scratch + OFF_QK
                                                     + (long long)hg * LG_STRIDE);
    const __nv_bfloat16* vh = (const __nv_bfloat16*)(g_scratch + OFF_VWTH)
                              + (size_t)h * 64 * 6144;
    const __nv_bfloat16* vl = (const __nv_bfloat16*)(g_scratch + OFF_VWTL)
                              + (size_t)h * 64 * 6144;

    int warp_m = wid & 3;
    int warp_n = wid >> 2;
    int m_base = warp_m * 32;
    int n_base = warp_n * 32;

    float acc[8][4];
    #pragma unroll
    for (int i = 0; i < 8; i++)
        #pragma unroll
        for (int j = 0; j < 4; j++) acc[i][j] = 0.f;

    int a_row = lid & 15;
    int a_colb = (lid >> 4) * 8;
    int b_row = (lid >> 4) * 8 + (lid & 7);
    int b_colb = ((lid >> 3) & 1) * 8;

    int r2 = tid >> 1, half = tid & 1;

    for (int ch = 0; ch < 8; ch++) {
        int koff = zk * 512 + ch * 64;
        // load A rows (AB hi/lo): row stride 12288 bf16, lo at +6144
        {
            const uint4* sah = (const uint4*)(ab + (size_t)(bm + r2) * 12288 + koff + half * 32);
            const uint4* sal = (const uint4*)(ab + (size_t)(bm + r2) * 12288 + 6144 + koff + half * 32);
            uint4* dah = (uint4*)(Ah + r2 * APAD + half * 32);
            uint4* dal = (uint4*)(Al + r2 * APAD + half * 32);
            #pragma unroll
            for (int i = 0; i < 4; i++) { dah[i] = sah[i]; dal[i] = sal[i]; }
        }
        if (tid < 128) {
            const uint4* sbh = (const uint4*)(vh + (size_t)r2 * 6144 + koff + half * 32);
            const uint4* sbl = (const uint4*)(vl + (size_t)r2 * 6144 + koff + half * 32);
            uint4* dbh = (uint4*)(Bh + r2 * APAD + half * 32);
            uint4* dbl = (uint4*)(Bl + r2 * APAD + half * 32);
            #pragma unroll
            for (int i = 0; i < 4; i++) { dbh[i] = sbh[i]; dbl[i] = sbl[i]; }
        }
        __syncthreads();

        #pragma unroll
        for (int sp = 0; sp < 3; sp++) {
            const __nv_bfloat16* As = (sp == 2) ? Al : Ah;
            const __nv_bfloat16* Bs = (sp == 1) ? Bl : Bh;
            #pragma unroll
            for (int ks = 0; ks < 4; ks++) {
                int k0 = ks * 16;
                uint32_t afr[2][4];
                #pragma unroll
                for (int am = 0; am < 2; am++) {
                    uint32_t addr = smem_to_u32(As + (size_t)(m_base + am * 16 + a_row) * APAD
                                                + k0 + a_colb);
                    ldsm_x4(afr[am], addr);
                }
                uint32_t bfr[4][2];
                #pragma unroll
                for (int p = 0; p < 2; p++) {
                    uint32_t r4[4];
                    uint32_t addr = smem_to_u32(Bs + (size_t)(n_base + p * 16 + b_row) * APAD
                                                + k0 + b_colb);
                    ldsm_x4(r4, addr);
                    bfr[2 * p + 0][0] = r4[0]; bfr[2 * p + 0][1] = r4[1];
                    bfr[2 * p + 1][0] = r4[2]; bfr[2 * p + 1][1] = r4[3];
                }
                #pragma unroll
                for (int am = 0; am < 2; am++)
                    #pragma unroll
                    for (int an = 0; an < 4; an++)
                        mma_bf16(acc[am * 4 + an], afr[am], bfr[an]);
            }
        }
        __syncthreads();
    }

    // partial store to OPART[(zk*2+hg)][m][64]
    float* opart = g_scratch + OFF_OPART + (size_t)(zk * 2 + hg) * 65536;
    int gid = lid >> 2, tig = lid & 3;
    #pragma unroll
    for (int am = 0; am < 2; am++) {
        #pragma unroll
        for (int an = 0; an < 4; an++) {
            const float* d = acc[am * 4 + an];
            int row0 = bm + m_base + am * 16 + gid;
            int col = n_base + an * 8 + tig * 2;
            *(float2*)(opart + (size_t)row0 * 64 + col) = make_float2(d[0], d[1]);
            *(float2*)(opart + (size_t)(row0 + 8) * 64 + col) = make_float2(d[2], d[3]);
        }
    }
}

// ---------------------------------------------------------------------------
extern "C" void kernel_launch(void* const* d_in, const int* in_sizes, int n_in,
                              void* d_out, int out_size)
{
    (void)in_sizes; (void)n_in;
    const float* x      = (const float*)d_in[0];
    const float* qkv_w  = (const float*)d_in[1];
    const float* q2_w   = (const float*)d_in[2];
    const float* kv2_w  = (const float*)d_in[3];
    const float* proj_w = (const float*)d_in[4];
    const float* proj_b = (const float*)d_in[5];
    const float* ln1_g  = (const float*)d_in[6];
    const float* ln1_b  = (const float*)d_in[7];
    const float* ln2_g  = (const float*)d_in[8];
    const float* ln2_b  = (const float*)d_in[9];
    const float* fc1_w  = (const float*)d_in[10];
    const float* fc1_b  = (const float*)d_in[11];
    const float* fc2_w  = (const float*)d_in[12];
    const float* fc2_b  = (const float*)d_in[13];
    float* out = (float*)d_out;

    cudaFuncSetAttribute(mma_lg_kernel,
                         cudaFuncAttributeMaxDynamicSharedMemorySize, MMA_SMEM_BYTES);
    cudaFuncSetAttribute(mma_o_kernel,
                         cudaFuncAttributeMaxDynamicSharedMemorySize, MMAO_SMEM_BYTES);

    pool_kernel<<<1536, 256>>>(x);
    ln_kernel<<<1024, 384>>>(OFF_TOK, ln1_g, ln1_b, OFF_XN);

    // qkv = xn @ qkv_w   (1024 x 1152 x 384, NN)
    gemm128_kernel<<<dim3(9, 8, 1), 256>>>(OFF_XN, qkv_w, 0, nullptr, OFF_QKV,
        384, 384, 1152, 1152, 0, 0, 0, 1.0f, 0);

    // VW[h'] = v_h' @ kv2_w[h' slice]   (6 batched NN, K=64)
    gemm128_kernel<<<dim3(6, 8, 6), 256>>>(OFF_QKV + 768, kv2_w, 0, nullptr, OFF_VW,
        64, 1152, 768, 768, 64, 49152, 786432, 1.0f, 0);

    // qk[h] = q_h @ k_h^T   (6 batched NT, K=64)
    gemm128_kernel<<<dim3(8, 8, 6), 256>>>(OFF_QKV, nullptr, OFF_QKV + 384, nullptr, OFF_QK,
        64, 1152, 1152, 1024, 64, 64, 1048576, 1.0f, 8);

    ta_kernel<<<6144, 256>>>();
    xdiag_kernel<<<1024, 384>>>();

    // q2 = SCALE * x_diag @ q2_w
    gemm64_kernel<<<dim3(6, 8, 1), 256>>>(OFF_XD, q2_w, 0, nullptr, 0, OFF_Q2,
        1024, 384, 384, 384, 384, 384, 0, 0, 0, 0, SCALE, 0, 1, 1);

    // bf16 hi/lo splits: q2 -> XN; VW k-half -> QKV / MLP; VWv -> transposed
    cvt_split_kernel<<<1536, 256>>>(OFF_Q2, 384, 384, OFF_XN, OFF_XN + 196608);
    cvt_split_kernel<<<9216, 256>>>(OFF_VW, 768, 384, OFF_QKV, OFF_MLP);
    cvt_vwt_kernel<<<dim3(96, 6), 256>>>();

    int wout = (out_size >= 3145728) ? 1 : 0;

    // stage 2 in 3 groups of 2 heads (Lg/AB overlays dead QK + LG regions)
    for (int g = 0; g < 3; g++) {
        mma_lg_kernel<<<dim3(48, 8, 2), 256, MMA_SMEM_BYTES>>>(g);

        middle_kernel<<<dim3(1024, 2), 256>>>(g, out + 1572864, wout);

        mma_o_kernel<<<dim3(12, 8, 2), 256, MMAO_SMEM_BYTES>>>(g);

        oreduce_kernel<<<512, 256>>>(g);
    }

    // h1 = tok + (o @ proj_w + proj_b)
    gemm64_kernel<<<dim3(6, 8, 1), 256>>>(OFF_O, proj_w, 0, proj_b, OFF_TOK, OFF_H1,
        1024, 384, 384, 384, 384, 384, 384, 0, 0, 0, 1.0f, 1 | 2, 1, 1);

    ln_kernel<<<1024, 384>>>(OFF_H1, ln2_g, ln2_b, OFF_HN);

    // mlp
    gemm128_kernel<<<dim3(12, 8, 1), 256>>>(OFF_HN, fc1_w, 0, fc1_b, OFF_MLP,
        384, 384, 1536, 1536, 0, 0, 0, 1.0f, 1 | 4);
    gemm64_kernel<<<dim3(6, 8, 1), 256>>>(OFF_MLP, fc2_w, 0, fc2_b, OFF_H1, OFF_H2,
        1024, 384, 1536, 1536, 384, 384, 384, 0, 0, 0, 1.0f, 1 | 2, 1, 1);

    upsample_kernel<<<1536, 256>>>(out, out_size);
}

// round 13
// speedup vs baseline: 1.2848x; 1.0294x over previous
#include <cuda_runtime.h>
#include <cuda_bf16.h>
#include <cstdint>
#include <math.h>

// ---------------------------------------------------------------------------
// DeformationTrajectoryAttentionBlock — mma.sync bf16x3 (Lg, o, qkv, fc1, fc2).
// B=1, F=4, H=6, D=384, G=16, S=256, N=1024, HD=64, IMG=32, MLP_HID=1536
// ---------------------------------------------------------------------------

#define SCALE 0.125f
#define LN_EPS 1e-5f
typedef unsigned long long ull;

#define OFF_TOK    0LL          // 1024*384
#define OFF_XN     393216LL     // reused: q2h bf16 @ +0, q2l bf16 @ +196608
#define OFF_QKV    786432LL     // 1024*1152 ; reused: VWk-hi bf16
#define OFF_VW     1966080LL    // 6*1024*768 (6144 x 768)
#define OFF_QK     6684672LL    // 6*1024*1024 ; Lg[hg=0]/AB ; later fc1T/mlp/fc2T
#define OFF_TA     12976128LL   // 1024*256*24
#define OFF_XD     19267584LL   // x_diag ; also xn/hn bf16 hi+lo staging
#define OFF_Q2     19660800LL
#define OFF_LG     20054016LL   // 1024*6144 ; Lg[hg=1]/AB ; earlier qkv_wT bf16
#define LG_STRIDE  13369344LL   // OFF_LG - OFF_QK
#define OFF_OPART  26345472LL   // 24 * 1024*64
#define OFF_O      27918336LL
#define OFF_H1     28311552LL
#define OFF_HN     28704768LL
#define OFF_MLP    29097984LL   // 1024*1536 ; earlier VWk-lo bf16
#define OFF_H2     30670848LL
#define OFF_VWTH   31064064LL   // VWv^T hi bf16 [6][64][6144]
#define OFF_VWTL   32243712LL   // VWv^T lo bf16
#define SCRATCH_FLOATS 33423360LL

static __device__ float g_scratch[SCRATCH_FLOATS];

// ---- packed f32x2 helpers --------------------------------------------------
__device__ __forceinline__ ull pack2b(float x)
{
    ull r;
    asm("mov.b64 %0, {%1, %1};" : "=l"(r) : "f"(x));
    return r;
}
__device__ __forceinline__ void fma2(ull& acc, ull a, ull b)
{
    asm("fma.rn.f32x2 %0, %1, %2, %0;" : "+l"(acc) : "l"(a), "l"(b));
}
__device__ __forceinline__ void unpack2(ull v, float& x, float& y)
{
    asm("mov.b64 {%0, %1}, %2;" : "=f"(x), "=f"(y) : "l"(v));
}
__device__ __forceinline__ uint32_t smem_to_u32(const void* smem_ptr)
{
    uint32_t addr;
    asm("{ .reg .u64 tmp; cvta.to.shared.u64 tmp, %1; cvt.u32.u64 %0, tmp; }"
        : "=r"(addr) : "l"(smem_ptr));
    return addr;
}

// ---------------------------------------------------------------------------
__global__ void pool_kernel(const float* __restrict__ x)
{
    float* tok = g_scratch + OFF_TOK;
    int fd = blockIdx.x;
    int f = fd / 384;
    const float* xp = x + (size_t)fd * 1024;
    int t = threadIdx.x;
    int gy = t >> 4, gx = t & 15;
    const float* p = xp + (gy * 2) * 32 + gx * 2;
    float m = fmaxf(fmaxf(p[0], p[1]), fmaxf(p[32], p[33]));
    tok[(size_t)(f * 256 + t) * 384 + (fd % 384)] = m;
}

// ---------------------------------------------------------------------------
__global__ void ln_kernel(long long inOff, const float* __restrict__ g,
                          const float* __restrict__ b, long long outOff)
{
    const float* in = g_scratch + inOff;
    float* out = g_scratch + outOff;
    int n = blockIdx.x, t = threadIdx.x;
    float x = in[(size_t)n * 384 + t];
    __shared__ float red[12];
    __shared__ float mv[2];
    float s = x;
    #pragma unroll
    for (int o = 16; o; o >>= 1) s += __shfl_xor_sync(0xffffffffu, s, o);
    if ((t & 31) == 0) red[t >> 5] = s;
    __syncthreads();
    if (t == 0) { float tt = 0.f; for (int i = 0; i < 12; i++) tt += red[i]; mv[0] = tt * (1.0f / 384.0f); }
    __syncthreads();
    float mean = mv[0];
    float d = x - mean;
    s = d * d;
    #pragma unroll
    for (int o = 16; o; o >>= 1) s += __shfl_xor_sync(0xffffffffu, s, o);
    if ((t & 31) == 0) red[t >> 5] = s;
    __syncthreads();
    if (t == 0) { float tt = 0.f; for (int i = 0; i < 12; i++) tt += red[i]; mv[1] = rsqrtf(tt * (1.0f / 384.0f) + LN_EPS); }
    __syncthreads();
    out[(size_t)n * 384 + t] = d * mv[1] * g[t] + b[t];
}

// ---------------------------------------------------------------------------
// gemm128 (R6-proven): 128x128x16, 8x8 microtile (f32x2), dbl-buffered.
// flags: 1=bias 4=gelu 8=NT.
// ---------------------------------------------------------------------------
__global__ void __launch_bounds__(256, 2) gemm128_kernel(
    long long aOff, const float* __restrict__ Bp, long long bOff,
    const float* __restrict__ bias, long long cOff,
    int K, int lda, int ldb, int ldc,
    long long sA, long long sB, long long sC,
    float alpha, int flags)
{
    int z = blockIdx.z;
    const float* A = g_scratch + aOff + (long long)z * sA;
    const float* B = (Bp ? Bp : g_scratch + bOff) + (long long)z * sB;
    float* C = g_scratch + cOff + (long long)z * sC;

    __shared__ __align__(16) float As[2][16][128];
    __shared__ __align__(16) float Bs[2][16][128];

    int bm = blockIdx.y * 128, bn = blockIdx.x * 128;
    int tid = threadIdx.x;
    int r2 = tid >> 1, k8 = (tid & 1) * 8;
    int bk = tid >> 4, c8 = (tid & 15) * 8;
    int ty = tid >> 4, tx = tid & 15;

    int nt = K / 16;
    float4 ar0, ar1, br0, br1;

    {
        const float* ap = A + (long long)(bm + r2) * lda + k8;
        ar0 = *(const float4*)ap; ar1 = *(const float4*)(ap + 4);
        As[0][k8 + 0][r2] = ar0.x; As[0][k8 + 1][r2] = ar0.y;
        As[0][k8 + 2][r2] = ar0.z; As[0][k8 + 3][r2] = ar0.w;
        As[0][k8 + 4][r2] = ar1.x; As[0][k8 + 5][r2] = ar1.y;
        As[0][k8 + 6][r2] = ar1.z; As[0][k8 + 7][r2] = ar1.w;
        if (flags & 8) {
            const float* bp = B + (long long)(bn + r2) * ldb + k8;
            br0 = *(const float4*)bp; br1 = *(const float4*)(bp + 4);
            Bs[0][k8 + 0][r2] = br0.x; Bs[0][k8 + 1][r2] = br0.y;
            Bs[0][k8 + 2][r2] = br0.z; Bs[0][k8 + 3][r2] = br0.w;
            Bs[0][k8 + 4][r2] = br1.x; Bs[0][k8 + 5][r2] = br1.y;
            Bs[0][k8 + 6][r2] = br1.z; Bs[0][k8 + 7][r2] = br1.w;
        } else {
            const float* bp = B + (long long)bk * ldb + bn + c8;
            br0 = *(const float4*)bp; br1 = *(const float4*)(bp + 4);
            *(float4*)&Bs[0][bk][c8] = br0;
            *(float4*)&Bs[0][bk][c8 + 4] = br1;
        }
    }
    __syncthreads();

    ull acc2[8][4];
    #pragma unroll
    for (int i = 0; i < 8; i++)
        #pragma unroll
        for (int j = 0; j < 4; j++) acc2[i][j] = 0ULL;

    for (int kt = 0; kt < nt; kt++) {
        int cur = kt & 1;
        bool pf = (kt + 1 < nt);
        if (pf) {
            int k0 = (kt + 1) * 16;
            const float* ap = A + (long long)(bm + r2) * lda + k0 + k8;
            ar0 = *(const float4*)ap; ar1 = *(const float4*)(ap + 4);
            if (flags & 8) {
                const float* bp = B + (long long)(bn + r2) * ldb + k0 + k8;
                br0 = *(const float4*)bp; br1 = *(const float4*)(bp + 4);
            } else {
                const float* bp = B + (long long)(k0 + bk) * ldb + bn + c8;
                br0 = *(const float4*)bp; br1 = *(const float4*)(bp + 4);
            }
        }
        #pragma unroll
        for (int kk = 0; kk < 16; kk++) {
            float a[8];
            *(float4*)&a[0] = *(const float4*)&As[cur][kk][ty * 8];
            *(float4*)&a[4] = *(const float4*)&As[cur][kk][ty * 8 + 4];
            const ull* bsp = (const ull*)&Bs[cur][kk][tx * 8];
            ull b0 = bsp[0], b1 = bsp[1], b2 = bsp[2], b3 = bsp[3];
            #pragma unroll
            for (int i = 0; i < 8; i++) {
                ull pa = pack2b(a[i]);
                fma2(acc2[i][0], pa, b0);
                fma2(acc2[i][1], pa, b1);
                fma2(acc2[i][2], pa, b2);
                fma2(acc2[i][3], pa, b3);
            }
        }
        if (pf) {
            int nx = 1 - cur;
            As[nx][k8 + 0][r2] = ar0.x; As[nx][k8 + 1][r2] = ar0.y;
            As[nx][k8 + 2][r2] = ar0.z; As[nx][k8 + 3][r2] = ar0.w;
            As[nx][k8 + 4][r2] = ar1.x; As[nx][k8 + 5][r2] = ar1.y;
            As[nx][k8 + 6][r2] = ar1.z; As[nx][k8 + 7][r2] = ar1.w;
            if (flags & 8) {
                Bs[nx][k8 + 0][r2] = br0.x; Bs[nx][k8 + 1][r2] = br0.y;
                Bs[nx][k8 + 2][r2] = br0.z; Bs[nx][k8 + 3][r2] = br0.w;
                Bs[nx][k8 + 4][r2] = br1.x; Bs[nx][k8 + 5][r2] = br1.y;
                Bs[nx][k8 + 6][r2] = br1.z; Bs[nx][k8 + 7][r2] = br1.w;
            } else {
                *(float4*)&Bs[nx][bk][c8] = br0;
                *(float4*)&Bs[nx][bk][c8 + 4] = br1;
            }
            __syncthreads();
        }
    }

    int row0 = bm + ty * 8, col0 = bn + tx * 8;
    #pragma unroll
    for (int i = 0; i < 8; i++) {
        float v[8];
        #pragma unroll
        for (int j = 0; j < 4; j++)
            unpack2(acc2[i][j], v[2 * j], v[2 * j + 1]);
        #pragma unroll
        for (int j = 0; j < 8; j++) {
            float t = alpha * v[j];
            if (flags & 1) t += bias[col0 + j];
            if (flags & 4) t = 0.5f * t * (1.0f + erff(t * 0.7071067811865476f));
            v[j] = t;
        }
        float* cp = C + (long long)(row0 + i) * ldc + col0;
        *(float4*)cp = *(float4*)&v[0];
        *(float4*)(cp + 4) = *(float4*)&v[4];
    }
}

// ---------------------------------------------------------------------------
// gemm64 (R6-proven): 128x64x16, 8x4 microtile (f32x2).
// flags: 1=bias 2=residual 4=gelu 8=NT. z: zb=z%nB batch, zk=z/nB K-split.
// ---------------------------------------------------------------------------
__global__ void __launch_bounds__(256) gemm64_kernel(
    long long aOff, const float* __restrict__ Bp, long long bOff,
    const float* __restrict__ bias, long long rOff, long long cOff,
    int M, int N, int K, int lda, int ldb, int ldc, int ldr,
    long long sA, long long sB, long long sC,
    float alpha, int flags, int nB, int ksplit)
{
    int z = blockIdx.z;
    int zb = z % nB, zk = z / nB;
    int Kloc = K / ksplit;
    const float* A = g_scratch + aOff + (long long)zb * sA + (long long)zk * Kloc;
    const float* Bb = (Bp ? Bp : g_scratch + bOff) + (long long)zb * sB;
    const float* B = Bb + ((flags & 8) ? (long long)zk * Kloc
                                       : (long long)zk * Kloc * ldb);
    float* C = g_scratch + cOff + (long long)z * sC;

    __shared__ __align__(16) float As[2][16][128];
    __shared__ __align__(16) float Bs[2][16][64];

    int bm = blockIdx.y * 128, bn = blockIdx.x * 64;
    int tid = threadIdx.x;
    int a_r = tid >> 1, a_k = (tid & 1) * 8;
    int tx = tid & 15, ty = tid >> 4;

    int nt = Kloc / 16;
    float4 ar0, ar1, br0;

    {
        const float* ap = A + (long long)(bm + a_r) * lda + a_k;
        ar0 = *(const float4*)ap; ar1 = *(const float4*)(ap + 4);
        As[0][a_k + 0][a_r] = ar0.x; As[0][a_k + 1][a_r] = ar0.y;
        As[0][a_k + 2][a_r] = ar0.z; As[0][a_k + 3][a_r] = ar0.w;
        As[0][a_k + 4][a_r] = ar1.x; As[0][a_k + 5][a_r] = ar1.y;
        As[0][a_k + 6][a_r] = ar1.z; As[0][a_k + 7][a_r] = ar1.w;
        if (flags & 8) {
            int r = tid >> 2, k4 = (tid & 3) * 4;
            br0 = *(const float4*)(B + (long long)(bn + r) * ldb + k4);
            Bs[0][k4 + 0][r] = br0.x; Bs[0][k4 + 1][r] = br0.y;
            Bs[0][k4 + 2][r] = br0.z; Bs[0][k4 + 3][r] = br0.w;
        } else {
            int kk = tid >> 4, n4 = (tid & 15) * 4;
            br0 = *(const float4*)(B + (long long)kk * ldb + bn + n4);
            *(float4*)&Bs[0][kk][n4] = br0;
        }
    }
    __syncthreads();

    ull acc2[8][2];
    #pragma unroll
    for (int i = 0; i < 8; i++) { acc2[i][0] = 0ULL; acc2[i][1] = 0ULL; }

    for (int kt = 0; kt < nt; kt++) {
        int cur = kt & 1;
        bool pf = (kt + 1 < nt);
        if (pf) {
            int k0 = (kt + 1) * 16;
            const float* ap = A + (long long)(bm + a_r) * lda + k0 + a_k;
            ar0 = *(const float4*)ap; ar1 = *(const float4*)(ap + 4);
            if (flags & 8) {
                int r = tid >> 2, k4 = (tid & 3) * 4;
                br0 = *(const float4*)(B + (long long)(bn + r) * ldb + k0 + k4);
            } else {
                int kk = tid >> 4, n4 = (tid & 15) * 4;
                br0 = *(const float4*)(B + (long long)(k0 + kk) * ldb + bn + n4);
            }
        }
        #pragma unroll
        for (int kk = 0; kk < 16; kk++) {
            float a[8];
            *(float4*)&a[0] = *(const float4*)&As[cur][kk][ty * 8];
            *(float4*)&a[4] = *(const float4*)&As[cur][kk][ty * 8 + 4];
            const ull* bsp = (const ull*)&Bs[cur][kk][tx * 4];
            ull b0 = bsp[0], b1 = bsp[1];
            #pragma unroll
            for (int i = 0; i < 8; i++) {
                ull pa = pack2b(a[i]);
                fma2(acc2[i][0], pa, b0);
                fma2(acc2[i][1], pa, b1);
            }
        }
        if (pf) {
            int nx = 1 - cur;
            As[nx][a_k + 0][a_r] = ar0.x; As[nx][a_k + 1][a_r] = ar0.y;
            As[nx][a_k + 2][a_r] = ar0.z; As[nx][a_k + 3][a_r] = ar0.w;
            As[nx][a_k + 4][a_r] = ar1.x; As[nx][a_k + 5][a_r] = ar1.y;
            As[nx][a_k + 6][a_r] = ar1.z; As[nx][a_k + 7][a_r] = ar1.w;
            if (flags & 8) {
                int r = tid >> 2, k4 = (tid & 3) * 4;
                Bs[nx][k4 + 0][r] = br0.x; Bs[nx][k4 + 1][r] = br0.y;
                Bs[nx][k4 + 2][r] = br0.z; Bs[nx][k4 + 3][r] = br0.w;
            } else {
                int kk = tid >> 4, n4 = (tid & 15) * 4;
                *(float4*)&Bs[nx][kk][n4] = br0;
            }
            __syncthreads();
        }
    }

    int row0 = bm + ty * 8, col0 = bn + tx * 4;
    const float* R = g_scratch + rOff;
    #pragma unroll
    for (int i = 0; i < 8; i++) {
        float v[4];
        unpack2(acc2[i][0], v[0], v[1]);
        unpack2(acc2[i][1], v[2], v[3]);
        #pragma unroll
        for (int j = 0; j < 4; j++) {
            float t = alpha * v[j];
            if (flags & 1) t += bias[col0 + j];
            if (flags & 4) t = 0.5f * t * (1.0f + erff(t * 0.7071067811865476f));
            if (flags & 2) t += R[(long long)(row0 + i) * ldr + col0 + j];
            C[(long long)(row0 + i) * ldc + col0 + j] = t;
        }
    }
}

// ---------------------------------------------------------------------------
__global__ void ta_kernel()
{
    const float* qk = g_scratch + OFF_QK;
    float* ta = g_scratch + OFF_TA;
    int b = blockIdx.x;
    int h = b >> 10, n = b & 1023;
    int s = threadIdx.x;
    const float* p = qk + ((size_t)b << 10) + s;
    float x0 = SCALE * p[0], x1 = SCALE * p[256], x2 = SCALE * p[512], x3 = SCALE * p[768];
    float m = fmaxf(fmaxf(x0, x1), fmaxf(x2, x3));
    float e0 = expf(x0 - m), e1 = expf(x1 - m), e2 = expf(x2 - m), e3 = expf(x3 - m);
    float inv = 1.0f / (e0 + e1 + e2 + e3);
    float* o = ta + ((size_t)(n * 256 + s)) * 24 + h * 4;
    o[0] = e0 * inv; o[1] = e1 * inv; o[2] = e2 * inv; o[3] = e3 * inv;
}

// ---------------------------------------------------------------------------
__global__ void xdiag_kernel()
{
    const float* ta = g_scratch + OFF_TA;
    const float* qkv = g_scratch + OFF_QKV;
    float* xd = g_scratch + OFF_XD;
    int n = blockIdx.x, c = threadIdx.x;
    int h = c >> 6;
    int s = n & 255;
    const float* tp = ta + ((size_t)(n * 256 + s)) * 24 + h * 4;
    float acc = 0.f;
    #pragma unroll
    for (int f = 0; f < 4; f++)
        acc += tp[f] * qkv[(size_t)(f * 256 + s) * 1152 + 768 + c];
    xd[(size_t)n * 384 + c] = acc;
}

// ---------------------------------------------------------------------------
// middle: logits + softmax + AB in place as bf16 hi/lo over Lg row.
// ---------------------------------------------------------------------------
__global__ void __launch_bounds__(256) middle_kernel(int g, float* __restrict__ out_attn,
                                                     int write_out)
{
    int n = blockIdx.x;
    int hg = blockIdx.y;
    int s = threadIdx.x;
    __shared__ __align__(16) float sta[256][24];
    __shared__ float red[8];
    __shared__ float mv[2];

    const float4* tap = (const float4*)(g_scratch + OFF_TA + (size_t)n * 6144);
    float4* stp = (float4*)&sta[0][0];
    for (int idx = s; idx < 1536; idx += 256)
        stp[idx] = tap[idx];
    __syncthreads();

    float* lg = g_scratch + OFF_QK + (long long)hg * LG_STRIDE + (size_t)n * 6144;
    float logit = 0.f;
    #pragma unroll
    for (int j = 0; j < 24; j++)
        logit += sta[s][j] * lg[j * 256 + s];

    float m = logit;
    #pragma unroll
    for (int o = 16; o; o >>= 1) m = fmaxf(m, __shfl_xor_sync(0xffffffffu, m, o));
    if ((s & 31) == 0) red[s >> 5] = m;
    __syncthreads();
    if (s == 0) { float t = red[0]; for (int i = 1; i < 8; i++) t = fmaxf(t, red[i]); mv[0] = t; }
    __syncthreads();
    float e = expf(logit - mv[0]);
    float sum = e;
    #pragma unroll
    for (int o = 16; o; o >>= 1) sum += __shfl_xor_sync(0xffffffffu, sum, o);
    if ((s & 31) == 0) red[s >> 5] = sum;
    __syncthreads();
    if (s == 0) { float t = 0.f; for (int i = 0; i < 8; i++) t += red[i]; mv[1] = 1.0f / t; }
    __syncthreads();
    float sa = e * mv[1];
    if (write_out) out_attn[((size_t)(g * 2 + hg) * 1024 + n) * 256 + s] = sa;
    __nv_bfloat16* ab = (__nv_bfloat16*)lg;
    #pragma unroll
    for (int j = 0; j < 24; j++) {
        float v = sa * sta[s][j];
        __nv_bfloat16 hi = __float2bfloat16(v);
        __nv_bfloat16 lo = __float2bfloat16(v - __bfloat162float(hi));
        ab[j * 256 + s] = hi;
        ab[6144 + j * 256 + s] = lo;
    }
}

// ---------------------------------------------------------------------------
__global__ void oreduce_kernel(int g)
{
    const float* opart = g_scratch + OFF_OPART;
    float* o = g_scratch + OFF_O;
    int i = blockIdx.x * 256 + threadIdx.x;       // < 131072
    int hg = i >> 16;
    int r = i & 65535;
    float sum = 0.f;
    #pragma unroll
    for (int zk = 0; zk < 12; zk++)
        sum += opart[(size_t)(zk * 2 + hg) * 65536 + r];
    o[(size_t)(r >> 6) * 384 + (g * 2 + hg) * 64 + (r & 63)] = sum;
}

// ---------------------------------------------------------------------------
__global__ void upsample_kernel(float* __restrict__ out, int out_size)
{
    const float* h2 = g_scratch + OFF_H2;
    int fd = blockIdx.x;
    int f = fd / 384, d = fd % 384;
    __shared__ float ch[256];
    int t = threadIdx.x;
    ch[t] = h2[(size_t)(f * 256 + t) * 384 + d];
    __syncthreads();
    #pragma unroll
    for (int p = 0; p < 4; p++) {
        int o = t + p * 256;
        int oy = o >> 5, ox = o & 31;
        float fy = 0.5f * oy - 0.25f;
        int iy0 = (int)floorf(fy);
        float wy = fy - (float)iy0;
        int iy0c = max(iy0, 0), iy1c = min(iy0 + 1, 15);
        float fx = 0.5f * ox - 0.25f;
        int ix0 = (int)floorf(fx);
        float wx = fx - (float)ix0;
        int ix0c = max(ix0, 0), ix1c = min(ix0 + 1, 15);
        float v00 = ch[iy0c * 16 + ix0c], v01 = ch[iy0c * 16 + ix1c];
        float v10 = ch[iy1c * 16 + ix0c], v11 = ch[iy1c * 16 + ix1c];
        float v = (1.f - wy) * ((1.f - wx) * v00 + wx * v01)
                + wy * ((1.f - wx) * v10 + wx * v11);
        long long oi = (long long)fd * 1024 + o;
        if (oi < (long long)out_size) out[oi] = v;
    }
}

// ---------------------------------------------------------------------------
// bf16 hi/lo split: fp32 [rows][inStride] (first `width` cols) -> two bf16
// ---------------------------------------------------------------------------
__global__ void cvt_split_kernel(long long inOff, int inStride, int width,
                                 long long hiOff, long long loOff)
{
    long long i = (long long)blockIdx.x * 256 + threadIdx.x;
    int row = (int)(i / width);
    int col = (int)(i % width);
    float v = g_scratch[inOff + (long long)row * inStride + col];
    __nv_bfloat16 h = __float2bfloat16(v);
    float rem = v - __bfloat162float(h);
    __nv_bfloat16 l = __float2bfloat16(rem);
    ((__nv_bfloat16*)(g_scratch + hiOff))[i] = h;
    ((__nv_bfloat16*)(g_scratch + loOff))[i] = l;
}

// ---------------------------------------------------------------------------
// cvt_wt: transpose-split global fp32 W[Kd][Nd] -> WT hi/lo bf16 [Nd][Kd].
// grid (Kd/64, Nd/64), 256 threads.
// ---------------------------------------------------------------------------
__global__ void cvt_wt_kernel(const float* __restrict__ W, int Kd, int Nd,
                              long long hiOff, long long loOff)
{
    __shared__ float tile[64][65];
    int kt = blockIdx.x * 64;
    int nt = blockIdx.y * 64;
    int tid = threadIdx.x;
    for (int i = tid; i < 4096; i += 256) {
        int k = i >> 6, n = i & 63;
        tile[k][n] = W[(size_t)(kt + k) * Nd + nt + n];
    }
    __syncthreads();
    __nv_bfloat16* vh = (__nv_bfloat16*)(g_scratch + hiOff);
    __nv_bfloat16* vl = (__nv_bfloat16*)(g_scratch + loOff);
    for (int i = tid; i < 4096; i += 256) {
        int n = i >> 6, k = i & 63;
        float v = tile[k][n];
        __nv_bfloat16 hi = __float2bfloat16(v);
        __nv_bfloat16 lo = __float2bfloat16(v - __bfloat162float(hi));
        size_t idx = (size_t)(nt + n) * Kd + kt + k;
        vh[idx] = hi;
        vl[idx] = lo;
    }
}

// ---------------------------------------------------------------------------
// cvt_vwt: transpose-split VWv -> VWvT[h][n=64][k=6144] bf16 hi/lo.
// ---------------------------------------------------------------------------
__global__ void cvt_vwt_kernel()
{
    __shared__ float tile[64][65];
    int kt = blockIdx.x * 64;
    int h = blockIdx.y;
    int tid = threadIdx.x;
    for (int i = tid; i < 4096; i += 256) {
        int k = i >> 6, n = i & 63;
        tile[k][n] = g_scratch[OFF_VW + (size_t)(kt + k) * 768 + 384 + h * 64 + n];
    }
    __syncthreads();
    __nv_bfloat16* vh = (__nv_bfloat16*)(g_scratch + OFF_VWTH);
    __nv_bfloat16* vl = (__nv_bfloat16*)(g_scratch + OFF_VWTL);
    for (int i = tid; i < 4096; i += 256) {
        int n = i >> 6, k = i & 63;
        float v = tile[k][n];
        __nv_bfloat16 hi = __float2bfloat16(v);
        __nv_bfloat16 lo = __float2bfloat16(v - __bfloat162float(hi));
        size_t idx = ((size_t)h * 64 + n) * 6144 + kt + k;
        vh[idx] = hi;
        vl[idx] = lo;
    }
}

// ===========================================================================
// mma.sync helpers (R10/R11-proven)
// ===========================================================================
__device__ __forceinline__ void ldsm_x4(uint32_t* r, uint32_t addr)
{
    asm volatile("ldmatrix.sync.aligned.m8n8.x4.shared.b16 {%0,%1,%2,%3}, [%4];"
                 : "=r"(r[0]), "=r"(r[1]), "=r"(r[2]), "=r"(r[3]) : "r"(addr));
}
__device__ __forceinline__ void mma_bf16(float* d, const uint32_t* a, const uint32_t* b)
{
    asm volatile(
        "mma.sync.aligned.m16n8k16.row.col.f32.bf16.bf16.f32 "
        "{%0,%1,%2,%3}, {%4,%5,%6,%7}, {%8,%9}, {%0,%1,%2,%3};"
        : "+f"(d[0]), "+f"(d[1]), "+f"(d[2]), "+f"(d[3])
        : "r"(a[0]), "r"(a[1]), "r"(a[2]), "r"(a[3]), "r"(b[0]), "r"(b[1]));
}

#define MMA_SMEM_BYTES 73728
#define APAD 72

// ===========================================================================
// mma_lg (R10-proven): Lg tile (128 x 128) = q2_h @ VWk_h^T, K=64, x3 splits.
// ===========================================================================
__global__ void __launch_bounds__(256) mma_lg_kernel(int g)
{
    extern __shared__ __align__(16) char dsm[];
    __nv_bfloat16* Ah = (__nv_bfloat16*)dsm;
    __nv_bfloat16* Al = Ah + 128 * APAD;
    __nv_bfloat16* Bh = Al + 128 * APAD;
    __nv_bfloat16* Bl = Bh + 128 * APAD;

    int tid = threadIdx.x;
    int wid = tid >> 5, lid = tid & 31;
    int bn = blockIdx.x * 128;
    int bm = blockIdx.y * 128;
    int hg = blockIdx.z;
    int h = g * 2 + hg;

    const __nv_bfloat16* q2h = (const __nv_bfloat16*)(g_scratch + OFF_XN);
    const __nv_bfloat16* q2l = (const __nv_bfloat16*)(g_scratch + OFF_XN + 196608);
    const __nv_bfloat16* vwh = (const __nv_bfloat16*)(g_scratch + OFF_QKV);
    const __nv_bfloat16* vwl = (const __nv_bfloat16*)(g_scratch + OFF_MLP);

    {
        int r = tid >> 1, half = tid & 1;
        const uint4* sah = (const uint4*)(q2h + (size_t)(bm + r) * 384 + h * 64 + half * 32);
        const uint4* sal = (const uint4*)(q2l + (size_t)(bm + r) * 384 + h * 64 + half * 32);
        uint4* dah = (uint4*)(Ah + r * APAD + half * 32);
        uint4* dal = (uint4*)(Al + r * APAD + half * 32);
        #pragma unroll
        for (int i = 0; i < 4; i++) { dah[i] = sah[i]; dal[i] = sal[i]; }
        const uint4* sbh = (const uint4*)(vwh + (size_t)(bn + r) * 384 + h * 64 + half * 32);
        const uint4* sbl = (const uint4*)(vwl + (size_t)(bn + r) * 384 + h * 64 + half * 32);
        uint4* dbh = (uint4*)(Bh + r * APAD + half * 32);
        uint4* dbl = (uint4*)(Bl + r * APAD + half * 32);
        #pragma unroll
        for (int i = 0; i < 4; i++) { dbh[i] = sbh[i]; dbl[i] = sbl[i]; }
    }
    __syncthreads();

    int warp_m = wid & 3;
    int warp_n = wid >> 2;
    int m_base = warp_m * 32;
    int n_base = warp_n * 64;

    float acc[16][4];
    #pragma unroll
    for (int i = 0; i < 16; i++)
        #pragma unroll
        for (int j = 0; j < 4; j++) acc[i][j] = 0.f;

    int a_row = lid & 15;
    int a_colb = (lid >> 4) * 8;
    int b_row = (lid >> 4) * 8 + (lid & 7);
    int b_colb = ((lid >> 3) & 1) * 8;

    #pragma unroll
    for (int sp = 0; sp < 3; sp++) {
        const __nv_bfloat16* As = (sp == 2) ? Al : Ah;
        const __nv_bfloat16* Bs = (sp == 1) ? Bl : Bh;
        #pragma unroll
        for (int ks = 0; ks < 4; ks++) {
            int k0 = ks * 16;
            uint32_t afr[2][4];
            #pragma unroll
            for (int am = 0; am < 2; am++) {
                uint32_t addr = smem_to_u32(As + (size_t)(m_base + am * 16 + a_row) * APAD
                                            + k0 + a_colb);
                ldsm_x4(afr[am], addr);
            }
            uint32_t bfr[8][2];
            #pragma unroll
            for (int p = 0; p < 4; p++) {
                uint32_t r4[4];
                uint32_t addr = smem_to_u32(Bs + (size_t)(n_base + p * 16 + b_row) * APAD
                                            + k0 + b_colb);
                ldsm_x4(r4, addr);
                bfr[2 * p + 0][0] = r4[0]; bfr[2 * p + 0][1] = r4[1];
                bfr[2 * p + 1][0] = r4[2]; bfr[2 * p + 1][1] = r4[3];
            }
            #pragma unroll
            for (int am = 0; am < 2; am++)
                #pragma unroll
                for (int an = 0; an < 8; an++)
                    mma_bf16(acc[am * 8 + an], afr[am], bfr[an]);
        }
    }

    float* lg = g_scratch + OFF_QK + (long long)hg * LG_STRIDE;
    int gid = lid >> 2, tig = lid & 3;
    #pragma unroll
    for (int am = 0; am < 2; am++) {
        #pragma unroll
        for (int an = 0; an < 8; an++) {
            const float* d = acc[am * 8 + an];
            long long row0 = bm + m_base + am * 16 + gid;
            long long col = bn + n_base + an * 8 + tig * 2;
            *(float2*)(lg + row0 * 6144 + col) = make_float2(d[0], d[1]);
            *(float2*)(lg + (row0 + 8) * 6144 + col) = make_float2(d[2], d[3]);
        }
    }
}

// ===========================================================================
// mma_o (R11-proven): o partials = AB(bf16 hi/lo) @ VWvT^T.
// ===========================================================================
#define MMAO_SMEM_BYTES 55296

__global__ void __launch_bounds__(256) mma_o_kernel(int g)
{
    extern __shared__ __align__(16) char dsm[];
    __nv_bfloat16* Ah = (__nv_bfloat16*)dsm;
    __nv_bfloat16* Al = Ah + 128 * APAD;
    __nv_bfloat16* Bh = Al + 128 * APAD;
    __nv_bfloat16* Bl = Bh + 64 * APAD;

    int tid = threadIdx.x;
    int wid = tid >> 5, lid = tid & 31;
    int zk = blockIdx.x;
    int bm = blockIdx.y * 128;
    int hg = blockIdx.z;
    int h = g * 2 + hg;

    const __nv_bfloat16* ab = (const __nv_bfloat16*)(g_scratch + OFF_QK
                                                     + (long long)hg * LG_STRIDE);
    const __nv_bfloat16* vh = (const __nv_bfloat16*)(g_scratch + OFF_VWTH)
                              + (size_t)h * 64 * 6144;
    const __nv_bfloat16* vl = (const __nv_bfloat16*)(g_scratch + OFF_VWTL)
                              + (size_t)h * 64 * 6144;

    int warp_m = wid & 3;
    int warp_n = wid >> 2;
    int m_base = warp_m * 32;
    int n_base = warp_n * 32;

    float acc[8][4];
    #pragma unroll
    for (int i = 0; i < 8; i++)
        #pragma unroll
        for (int j = 0; j < 4; j++) acc[i][j] = 0.f;

    int a_row = lid & 15;
    int a_colb = (lid >> 4) * 8;
    int b_row = (lid >> 4) * 8 + (lid & 7);
    int b_colb = ((lid >> 3) & 1) * 8;

    int r2 = tid >> 1, half = tid & 1;

    for (int ch = 0; ch < 8; ch++) {
        int koff = zk * 512 + ch * 64;
        {
            const uint4* sah = (const uint4*)(ab + (size_t)(bm + r2) * 12288 + koff + half * 32);
            const uint4* sal = (const uint4*)(ab + (size_t)(bm + r2) * 12288 + 6144 + koff + half * 32);
            uint4* dah = (uint4*)(Ah + r2 * APAD + half * 32);
            uint4* dal = (uint4*)(Al + r2 * APAD + half * 32);
            #pragma unroll
            for (int i = 0; i < 4; i++) { dah[i] = sah[i]; dal[i] = sal[i]; }
        }
        if (tid < 128) {
            const uint4* sbh = (const uint4*)(vh + (size_t)r2 * 6144 + koff + half * 32);
            const uint4* sbl = (const uint4*)(vl + (size_t)r2 * 6144 + koff + half * 32);
            uint4* dbh = (uint4*)(Bh + r2 * APAD + half * 32);
            uint4* dbl = (uint4*)(Bl + r2 * APAD + half * 32);
            #pragma unroll
            for (int i = 0; i < 4; i++) { dbh[i] = sbh[i]; dbl[i] = sbl[i]; }
        }
        __syncthreads();

        #pragma unroll
        for (int sp = 0; sp < 3; sp++) {
            const __nv_bfloat16* As = (sp == 2) ? Al : Ah;
            const __nv_bfloat16* Bs = (sp == 1) ? Bl : Bh;
            #pragma unroll
            for (int ks = 0; ks < 4; ks++) {
                int k0 = ks * 16;
                uint32_t afr[2][4];
                #pragma unroll
                for (int am = 0; am < 2; am++) {
                    uint32_t addr = smem_to_u32(As + (size_t)(m_base + am * 16 + a_row) * APAD
                                                + k0 + a_colb);
                    ldsm_x4(afr[am], addr);
                }
                uint32_t bfr[4][2];
                #pragma unroll
                for (int p = 0; p < 2; p++) {
                    uint32_t r4[4];
                    uint32_t addr = smem_to_u32(Bs + (size_t)(n_base + p * 16 + b_row) * APAD
                                                + k0 + b_colb);
                    ldsm_x4(r4, addr);
                    bfr[2 * p + 0][0] = r4[0]; bfr[2 * p + 0][1] = r4[1];
                    bfr[2 * p + 1][0] = r4[2]; bfr[2 * p + 1][1] = r4[3];
                }
                #pragma unroll
                for (int am = 0; am < 2; am++)
                    #pragma unroll
                    for (int an = 0; an < 4; an++)
                        mma_bf16(acc[am * 4 + an], afr[am], bfr[an]);
            }
        }
        __syncthreads();
    }

    float* opart = g_scratch + OFF_OPART + (size_t)(zk * 2 + hg) * 65536;
    int gid = lid >> 2, tig = lid & 3;
    #pragma unroll
    for (int am = 0; am < 2; am++) {
        #pragma unroll
        for (int an = 0; an < 4; an++) {
            const float* d = acc[am * 4 + an];
            int row0 = bm + m_base + am * 16 + gid;
            int col = n_base + an * 8 + tig * 2;
            *(float2*)(opart + (size_t)row0 * 64 + col) = make_float2(d[0], d[1]);
            *(float2*)(opart + (size_t)(row0 + 8) * 64 + col) = make_float2(d[2], d[3]);
        }
    }
}

// ===========================================================================
// mma_nt: generic C[M x N] = A(bf16 hi/lo [M][K]) @ WT(bf16 hi/lo [N][K])^T,
// x3 splits, K chunked by 64. grid (N/128, M/128); 256 threads.
// flags: 1=bias 2=residual 4=gelu. C fp32 [M][ldc]; residual [M][ldc].
// ===========================================================================
__global__ void __launch_bounds__(256) mma_nt_kernel(
    long long aHiOff, long long aLoOff,
    long long bHiOff, long long bLoOff,
    const float* __restrict__ bias, long long rOff, long long cOff,
    int K, int ldc, int flags)
{
    extern __shared__ __align__(16) char dsm[];
    __nv_bfloat16* Ah = (__nv_bfloat16*)dsm;
    __nv_bfloat16* Al = Ah + 128 * APAD;
    __nv_bfloat16* Bh = Al + 128 * APAD;
    __nv_bfloat16* Bl = Bh + 128 * APAD;

    int tid = threadIdx.x;
    int wid = tid >> 5, lid = tid & 31;
    int bn = blockIdx.x * 128;
    int bm = blockIdx.y * 128;

    const __nv_bfloat16* ah = (const __nv_bfloat16*)(g_scratch + aHiOff);
    const __nv_bfloat16* al = (const __nv_bfloat16*)(g_scratch + aLoOff);
    const __nv_bfloat16* bh = (const __nv_bfloat16*)(g_scratch + bHiOff);
    const __nv_bfloat16* bl = (const __nv_bfloat16*)(g_scratch + bLoOff);

    int warp_m = wid & 3;
    int warp_n = wid >> 2;
    int m_base = warp_m * 32;
    int n_base = warp_n * 64;

    float acc[16][4];
    #pragma unroll
    for (int i = 0; i < 16; i++)
        #pragma unroll
        for (int j = 0; j < 4; j++) acc[i][j] = 0.f;

    int a_row = lid & 15;
    int a_colb = (lid >> 4) * 8;
    int b_row = (lid >> 4) * 8 + (lid & 7);
    int b_colb = ((lid >> 3) & 1) * 8;

    int r2 = tid >> 1, half = tid & 1;
    int nch = K / 64;

    for (int ch = 0; ch < nch; ch++) {
        int koff = ch * 64;
        {
            const uint4* sah = (const uint4*)(ah + (size_t)(bm + r2) * K + koff + half * 32);
            const uint4* sal = (const uint4*)(al + (size_t)(bm + r2) * K + koff + half * 32);
            uint4* dah = (uint4*)(Ah + r2 * APAD + half * 32);
            uint4* dal = (uint4*)(Al + r2 * APAD + half * 32);
            #pragma unroll
            for (int i = 0; i < 4; i++) { dah[i] = sah[i]; dal[i] = sal[i]; }
            const uint4* sbh = (const uint4*)(bh + (size_t)(bn + r2) * K + koff + half * 32);
            const uint4* sbl = (const uint4*)(bl + (size_t)(bn + r2) * K + koff + half * 32);
            uint4* dbh = (uint4*)(Bh + r2 * APAD + half * 32);
            uint4* dbl = (uint4*)(Bl + r2 * APAD + half * 32);
            #pragma unroll
            for (int i = 0; i < 4; i++) { dbh[i] = sbh[i]; dbl[i] = sbl[i]; }
        }
        __syncthreads();

        #pragma unroll
        for (int sp = 0; sp < 3; sp++) {
            const __nv_bfloat16* As = (sp == 2) ? Al : Ah;
            const __nv_bfloat16* Bs = (sp == 1) ? Bl : Bh;
            #pragma unroll
            for (int ks = 0; ks < 4; ks++) {
                int k0 = ks * 16;
                uint32_t afr[2][4];
                #pragma unroll
                for (int am = 0; am < 2; am++) {
                    uint32_t addr = smem_to_u32(As + (size_t)(m_base + am * 16 + a_row) * APAD
                                                + k0 + a_colb);
                    ldsm_x4(afr[am], addr);
                }
                uint32_t bfr[8][2];
                #pragma unroll
                for (int p = 0; p < 4; p++) {
                    uint32_t r4[4];
                    uint32_t addr = smem_to_u32(Bs + (size_t)(n_base + p * 16 + b_row) * APAD
                                                + k0 + b_colb);
                    ldsm_x4(r4, addr);
                    bfr[2 * p + 0][0] = r4[0]; bfr[2 * p + 0][1] = r4[1];
                    bfr[2 * p + 1][0] = r4[2]; bfr[2 * p + 1][1] = r4[3];
                }
                #pragma unroll
                for (int am = 0; am < 2; am++)
                    #pragma unroll
                    for (int an = 0; an < 8; an++)
                        mma_bf16(acc[am * 8 + an], afr[am], bfr[an]);
            }
        }
        __syncthreads();
    }

    float* C = g_scratch + cOff;
    const float* R = g_scratch + rOff;
    int gid = lid >> 2, tig = lid & 3;
    #pragma unroll
    for (int am = 0; am < 2; am++) {
        #pragma unroll
        for (int an = 0; an < 8; an++) {
            float d0 = acc[am * 8 + an][0], d1 = acc[am * 8 + an][1];
            float d2 = acc[am * 8 + an][2], d3 = acc[am * 8 + an][3];
            long long rowA = bm + m_base + am * 16 + gid;
            long long rowB = rowA + 8;
            long long col = bn + n_base + an * 8 + tig * 2;
            if (flags & 1) { float b0 = bias[col], b1 = bias[col + 1];
                             d0 += b0; d1 += b1; d2 += b0; d3 += b1; }
            if (flags & 4) {
                d0 = 0.5f * d0 * (1.0f + erff(d0 * 0.7071067811865476f));
                d1 = 0.5f * d1 * (1.0f + erff(d1 * 0.7071067811865476f));
                d2 = 0.5f * d2 * (1.0f + erff(d2 * 0.7071067811865476f));
                d3 = 0.5f * d3 * (1.0f + erff(d3 * 0.7071067811865476f));
            }
            if (flags & 2) {
                d0 += R[rowA * ldc + col]; d1 += R[rowA * ldc + col + 1];
                d2 += R[rowB * ldc + col]; d3 += R[rowB * ldc + col + 1];
            }
            *(float2*)(C + rowA * ldc + col) = make_float2(d0, d1);
            *(float2*)(C + rowB * ldc + col) = make_float2(d2, d3);
        }
    }
}

// ---------------------------------------------------------------------------
extern "C" void kernel_launch(void* const* d_in, const int* in_sizes, int n_in,
                              void* d_out, int out_size)
{
    (void)in_sizes; (void)n_in;
    const float* x      = (const float*)d_in[0];
    const float* qkv_w  = (const float*)d_in[1];
    const float* q2_w   = (const float*)d_in[2];
    const float* kv2_w  = (const float*)d_in[3];
    const float* proj_w = (const float*)d_in[4];
    const float* proj_b = (const float*)d_in[5];
    const float* ln1_g  = (const float*)d_in[6];
    const float* ln1_b  = (const float*)d_in[7];
    const float* ln2_g  = (const float*)d_in[8];
    const float* ln2_b  = (const float*)d_in[9];
    const float* fc1_w  = (const float*)d_in[10];
    const float* fc1_b  = (const float*)d_in[11];
    const float* fc2_w  = (const float*)d_in[12];
    const float* fc2_b  = (const float*)d_in[13];
    float* out = (float*)d_out;

    cudaFuncSetAttribute(mma_lg_kernel,
                         cudaFuncAttributeMaxDynamicSharedMemorySize, MMA_SMEM_BYTES);
    cudaFuncSetAttribute(mma_o_kernel,
                         cudaFuncAttributeMaxDynamicSharedMemorySize, MMAO_SMEM_BYTES);
    cudaFuncSetAttribute(mma_nt_kernel,
                         cudaFuncAttributeMaxDynamicSharedMemorySize, MMA_SMEM_BYTES);

    pool_kernel<<<1536, 256>>>(x);
    ln_kernel<<<1024, 384>>>(OFF_TOK, ln1_g, ln1_b, OFF_XN);

    // qkv via mma: split xn -> XD region; qkv_w^T -> LG region
    cvt_split_kernel<<<1536, 256>>>(OFF_XN, 384, 384, OFF_XD, OFF_XD + 196608);
    cvt_wt_kernel<<<dim3(6, 18), 256>>>(qkv_w, 384, 1152, OFF_LG, OFF_LG + 221184);
    mma_nt_kernel<<<dim3(9, 8), 256, MMA_SMEM_BYTES>>>(
        OFF_XD, OFF_XD + 196608, OFF_LG, OFF_LG + 221184,
        nullptr, 0, OFF_QKV, 384, 1152, 0);

    // VW[h'] = v_h' @ kv2_w[h' slice]   (6 batched NN, K=64, SIMT)
    gemm128_kernel<<<dim3(6, 8, 6), 256>>>(OFF_QKV + 768, kv2_w, 0, nullptr, OFF_VW,
        64, 1152, 768, 768, 64, 49152, 786432, 1.0f, 0);

    // qk[h] = q_h @ k_h^T   (6 batched NT, K=64, SIMT)
    gemm128_kernel<<<dim3(8, 8, 6), 256>>>(OFF_QKV, nullptr, OFF_QKV + 384, nullptr, OFF_QK,
        64, 1152, 1152, 1024, 64, 64, 1048576, 1.0f, 8);

    ta_kernel<<<6144, 256>>>();
    xdiag_kernel<<<1024, 384>>>();

    // q2 = SCALE * x_diag @ q2_w (SIMT)
    gemm64_kernel<<<dim3(6, 8, 1), 256>>>(OFF_XD, q2_w, 0, nullptr, 0, OFF_Q2,
        1024, 384, 384, 384, 384, 384, 0, 0, 0, 0, SCALE, 0, 1, 1);

    // bf16 hi/lo splits: q2 -> XN; VW k-half -> QKV / MLP; VWv -> transposed
    cvt_split_kernel<<<1536, 256>>>(OFF_Q2, 384, 384, OFF_XN, OFF_XN + 196608);
    cvt_split_kernel<<<9216, 256>>>(OFF_VW, 768, 384, OFF_QKV, OFF_MLP);
    cvt_vwt_kernel<<<dim3(96, 6), 256>>>();

    int wout = (out_size >= 3145728) ? 1 : 0;

    // stage 2 in 3 groups of 2 heads (Lg/AB overlays dead QK + LG regions)
    for (int g = 0; g < 3; g++) {
        mma_lg_kernel<<<dim3(48, 8, 2), 256, MMA_SMEM_BYTES>>>(g);
        middle_kernel<<<dim3(1024, 2), 256>>>(g, out + 1572864, wout);
        mma_o_kernel<<<dim3(12, 8, 2), 256, MMAO_SMEM_BYTES>>>(g);
        oreduce_kernel<<<512, 256>>>(g);
    }

    // h1 = tok + (o @ proj_w + proj_b) (SIMT)
    gemm64_kernel<<<dim3(6, 8, 1), 256>>>(OFF_O, proj_w, 0, proj_b, OFF_TOK, OFF_H1,
        1024, 384, 384, 384, 384, 384, 384, 0, 0, 0, 1.0f, 1 | 2, 1, 1);

    ln_kernel<<<1024, 384>>>(OFF_H1, ln2_g, ln2_b, OFF_HN);

    // fc1 via mma: split hn -> XD region; fc1_w^T -> QK region
    cvt_split_kernel<<<1536, 256>>>(OFF_HN, 384, 384, OFF_XD, OFF_XD + 196608);
    cvt_wt_kernel<<<dim3(6, 24), 256>>>(fc1_w, 384, 1536, OFF_QK, OFF_QK + 294912);
    mma_nt_kernel<<<dim3(12, 8), 256, MMA_SMEM_BYTES>>>(
        OFF_XD, OFF_XD + 196608, OFF_QK, OFF_QK + 294912,
        fc1_b, 0, OFF_MLP, 384, 1536, 1 | 4);

    // fc2 via mma: split mlp + fc2_w^T into QK region
    cvt_split_kernel<<<6144, 256>>>(OFF_MLP, 1536, 1536,
                                    OFF_QK + 589824, OFF_QK + 1376256);
    cvt_wt_kernel<<<dim3(24, 6), 256>>>(fc2_w, 1536, 384,
                                        OFF_QK + 2162688, OFF_QK + 2457600);
    mma_nt_kernel<<<dim3(3, 8), 256, MMA_SMEM_BYTES>>>(
        OFF_QK + 589824, OFF_QK + 1376256, OFF_QK + 2162688, OFF_QK + 2457600,
        fc2_b, OFF_H1, OFF_H2, 1536, 384, 1 | 2);

    upsample_kernel<<<1536, 256>>>(out, out_size);
}

// round 14
// speedup vs baseline: 1.3001x; 1.0119x over previous
#include <cuda_runtime.h>
#include <cuda_bf16.h>
#include <cstdint>
#include <math.h>

// ---------------------------------------------------------------------------
// DeformationTrajectoryAttentionBlock — mma.sync bf16x3 everywhere big.
// B=1, F=4, H=6, D=384, G=16, S=256, N=1024, HD=64, IMG=32, MLP_HID=1536
// ---------------------------------------------------------------------------

#define SCALE 0.125f
#define LN_EPS 1e-5f
typedef unsigned long long ull;

#define OFF_TOK    0LL          // 1024*384
#define OFF_XN     393216LL     // reused: q2h bf16 @ +0, q2l bf16 @ +196608
#define OFF_QKV    786432LL     // 1024*1152 fp32 ; later VWk-hi bf16
#define OFF_VW     1966080LL    // 6*1024*768 (6144 x 768)
#define OFF_QK     6684672LL    // qk fp32 / Lg[hg=0]/AB ; later fc1T/mlp/fc2T
#define OFF_TA     12976128LL   // 1024*256*24
#define OFF_XD     19267584LL   // xn splits -> kv2_wT splits -> x_diag ; hn splits
#define OFF_Q2     19660800LL
#define OFF_LG     20054016LL   // qkv_wT -> qkvSplit bf16 -> Lg[hg=1]/AB
#define LG_STRIDE  13369344LL   // OFF_LG - OFF_QK
#define OFF_OPART  26345472LL   // 24 * 1024*64
#define OFF_O      27918336LL
#define OFF_H1     28311552LL
#define OFF_HN     28704768LL
#define OFF_MLP    29097984LL   // mlp fp32 ; earlier VWk-lo bf16
#define OFF_H2     30670848LL
#define OFF_VWTH   31064064LL   // VWv^T hi bf16 [6][64][6144]
#define OFF_VWTL   32243712LL   // VWv^T lo bf16
#define SCRATCH_FLOATS 33423360LL

static __device__ float g_scratch[SCRATCH_FLOATS];

// ---- packed f32x2 helpers --------------------------------------------------
__device__ __forceinline__ ull pack2b(float x)
{
    ull r;
    asm("mov.b64 %0, {%1, %1};" : "=l"(r) : "f"(x));
    return r;
}
__device__ __forceinline__ void fma2(ull& acc, ull a, ull b)
{
    asm("fma.rn.f32x2 %0, %1, %2, %0;" : "+l"(acc) : "l"(a), "l"(b));
}
__device__ __forceinline__ void unpack2(ull v, float& x, float& y)
{
    asm("mov.b64 {%0, %1}, %2;" : "=f"(x), "=f"(y) : "l"(v));
}
__device__ __forceinline__ uint32_t smem_to_u32(const void* smem_ptr)
{
    uint32_t addr;
    asm("{ .reg .u64 tmp; cvta.to.shared.u64 tmp, %1; cvt.u32.u64 %0, tmp; }"
        : "=r"(addr) : "l"(smem_ptr));
    return addr;
}

// ---------------------------------------------------------------------------
__global__ void pool_kernel(const float* __restrict__ x)
{
    float* tok = g_scratch + OFF_TOK;
    int fd = blockIdx.x;
    int f = fd / 384;
    const float* xp = x + (size_t)fd * 1024;
    int t = threadIdx.x;
    int gy = t >> 4, gx = t & 15;
    const float* p = xp + (gy * 2) * 32 + gx * 2;
    float m = fmaxf(fmaxf(p[0], p[1]), fmaxf(p[32], p[33]));
    tok[(size_t)(f * 256 + t) * 384 + (fd % 384)] = m;
}

// ---------------------------------------------------------------------------
__global__ void ln_kernel(long long inOff, const float* __restrict__ g,
                          const float* __restrict__ b, long long outOff)
{
    const float* in = g_scratch + inOff;
    float* out = g_scratch + outOff;
    int n = blockIdx.x, t = threadIdx.x;
    float x = in[(size_t)n * 384 + t];
    __shared__ float red[12];
    __shared__ float mv[2];
    float s = x;
    #pragma unroll
    for (int o = 16; o; o >>= 1) s += __shfl_xor_sync(0xffffffffu, s, o);
    if ((t & 31) == 0) red[t >> 5] = s;
    __syncthreads();
    if (t == 0) { float tt = 0.f; for (int i = 0; i < 12; i++) tt += red[i]; mv[0] = tt * (1.0f / 384.0f); }
    __syncthreads();
    float mean = mv[0];
    float d = x - mean;
    s = d * d;
    #pragma unroll
    for (int o = 16; o; o >>= 1) s += __shfl_xor_sync(0xffffffffu, s, o);
    if ((t & 31) == 0) red[t >> 5] = s;
    __syncthreads();
    if (t == 0) { float tt = 0.f; for (int i = 0; i < 12; i++) tt += red[i]; mv[1] = rsqrtf(tt * (1.0f / 384.0f) + LN_EPS); }
    __syncthreads();
    out[(size_t)n * 384 + t] = d * mv[1] * g[t] + b[t];
}

// ---------------------------------------------------------------------------
// gemm64 (R6-proven): 128x64x16, 8x4 microtile (f32x2).
// flags: 1=bias 2=residual 4=gelu 8=NT. z: zb=z%nB batch, zk=z/nB K-split.
// ---------------------------------------------------------------------------
__global__ void __launch_bounds__(256) gemm64_kernel(
    long long aOff, const float* __restrict__ Bp, long long bOff,
    const float* __restrict__ bias, long long rOff, long long cOff,
    int M, int N, int K, int lda, int ldb, int ldc, int ldr,
    long long sA, long long sB, long long sC,
    float alpha, int flags, int nB, int ksplit)
{
    int z = blockIdx.z;
    int zb = z % nB, zk = z / nB;
    int Kloc = K / ksplit;
    const float* A = g_scratch + aOff + (long long)zb * sA + (long long)zk * Kloc;
    const float* Bb = (Bp ? Bp : g_scratch + bOff) + (long long)zb * sB;
    const float* B = Bb + ((flags & 8) ? (long long)zk * Kloc
                                       : (long long)zk * Kloc * ldb);
    float* C = g_scratch + cOff + (long long)z * sC;

    __shared__ __align__(16) float As[2][16][128];
    __shared__ __align__(16) float Bs[2][16][64];

    int bm = blockIdx.y * 128, bn = blockIdx.x * 64;
    int tid = threadIdx.x;
    int a_r = tid >> 1, a_k = (tid & 1) * 8;
    int tx = tid & 15, ty = tid >> 4;

    int nt = Kloc / 16;
    float4 ar0, ar1, br0;

    {
        const float* ap = A + (long long)(bm + a_r) * lda + a_k;
        ar0 = *(const float4*)ap; ar1 = *(const float4*)(ap + 4);
        As[0][a_k + 0][a_r] = ar0.x; As[0][a_k + 1][a_r] = ar0.y;
        As[0][a_k + 2][a_r] = ar0.z; As[0][a_k + 3][a_r] = ar0.w;
        As[0][a_k + 4][a_r] = ar1.x; As[0][a_k + 5][a_r] = ar1.y;
        As[0][a_k + 6][a_r] = ar1.z; As[0][a_k + 7][a_r] = ar1.w;
        if (flags & 8) {
            int r = tid >> 2, k4 = (tid & 3) * 4;
            br0 = *(const float4*)(B + (long long)(bn + r) * ldb + k4);
            Bs[0][k4 + 0][r] = br0.x; Bs[0][k4 + 1][r] = br0.y;
            Bs[0][k4 + 2][r] = br0.z; Bs[0][k4 + 3][r] = br0.w;
        } else {
            int kk = tid >> 4, n4 = (tid & 15) * 4;
            br0 = *(const float4*)(B + (long long)kk * ldb + bn + n4);
            *(float4*)&Bs[0][kk][n4] = br0;
        }
    }
    __syncthreads();

    ull acc2[8][2];
    #pragma unroll
    for (int i = 0; i < 8; i++) { acc2[i][0] = 0ULL; acc2[i][1] = 0ULL; }

    for (int kt = 0; kt < nt; kt++) {
        int cur = kt & 1;
        bool pf = (kt + 1 < nt);
        if (pf) {
            int k0 = (kt + 1) * 16;
            const float* ap = A + (long long)(bm + a_r) * lda + k0 + a_k;
            ar0 = *(const float4*)ap; ar1 = *(const float4*)(ap + 4);
            if (flags & 8) {
                int r = tid >> 2, k4 = (tid & 3) * 4;
                br0 = *(const float4*)(B + (long long)(bn + r) * ldb + k0 + k4);
            } else {
                int kk = tid >> 4, n4 = (tid & 15) * 4;
                br0 = *(const float4*)(B + (long long)(k0 + kk) * ldb + bn + n4);
            }
        }
        #pragma unroll
        for (int kk = 0; kk < 16; kk++) {
            float a[8];
            *(float4*)&a[0] = *(const float4*)&As[cur][kk][ty * 8];
            *(float4*)&a[4] = *(const float4*)&As[cur][kk][ty * 8 + 4];
            const ull* bsp = (const ull*)&Bs[cur][kk][tx * 4];
            ull b0 = bsp[0], b1 = bsp[1];
            #pragma unroll
            for (int i = 0; i < 8; i++) {
                ull pa = pack2b(a[i]);
                fma2(acc2[i][0], pa, b0);
                fma2(acc2[i][1], pa, b1);
            }
        }
        if (pf) {
            int nx = 1 - cur;
            As[nx][a_k + 0][a_r] = ar0.x; As[nx][a_k + 1][a_r] = ar0.y;
            As[nx][a_k + 2][a_r] = ar0.z; As[nx][a_k + 3][a_r] = ar0.w;
            As[nx][a_k + 4][a_r] = ar1.x; As[nx][a_k + 5][a_r] = ar1.y;
            As[nx][a_k + 6][a_r] = ar1.z; As[nx][a_k + 7][a_r] = ar1.w;
            if (flags & 8) {
                int r = tid >> 2, k4 = (tid & 3) * 4;
                Bs[nx][k4 + 0][r] = br0.x; Bs[nx][k4 + 1][r] = br0.y;
                Bs[nx][k4 + 2][r] = br0.z; Bs[nx][k4 + 3][r] = br0.w;
            } else {
                int kk = tid >> 4, n4 = (tid & 15) * 4;
                *(float4*)&Bs[nx][kk][n4] = br0;
            }
            __syncthreads();
        }
    }

    int row0 = bm + ty * 8, col0 = bn + tx * 4;
    const float* R = g_scratch + rOff;
    #pragma unroll
    for (int i = 0; i < 8; i++) {
        float v[4];
        unpack2(acc2[i][0], v[0], v[1]);
        unpack2(acc2[i][1], v[2], v[3]);
        #pragma unroll
        for (int j = 0; j < 4; j++) {
            float t = alpha * v[j];
            if (flags & 1) t += bias[col0 + j];
            if (flags & 4) t = 0.5f * t * (1.0f + erff(t * 0.7071067811865476f));
            if (flags & 2) t += R[(long long)(row0 + i) * ldr + col0 + j];
            C[(long long)(row0 + i) * ldc + col0 + j] = t;
        }
    }
}

// ---------------------------------------------------------------------------
__global__ void ta_kernel()
{
    const float* qk = g_scratch + OFF_QK;
    float* ta = g_scratch + OFF_TA;
    int b = blockIdx.x;
    int h = b >> 10, n = b & 1023;
    int s = threadIdx.x;
    const float* p = qk + ((size_t)b << 10) + s;
    float x0 = SCALE * p[0], x1 = SCALE * p[256], x2 = SCALE * p[512], x3 = SCALE * p[768];
    float m = fmaxf(fmaxf(x0, x1), fmaxf(x2, x3));
    float e0 = expf(x0 - m), e1 = expf(x1 - m), e2 = expf(x2 - m), e3 = expf(x3 - m);
    float inv = 1.0f / (e0 + e1 + e2 + e3);
    float* o = ta + ((size_t)(n * 256 + s)) * 24 + h * 4;
    o[0] = e0 * inv; o[1] = e1 * inv; o[2] = e2 * inv; o[3] = e3 * inv;
}

// ---------------------------------------------------------------------------
__global__ void xdiag_kernel()
{
    const float* ta = g_scratch + OFF_TA;
    const float* qkv = g_scratch + OFF_QKV;
    float* xd = g_scratch + OFF_XD;
    int n = blockIdx.x, c = threadIdx.x;
    int h = c >> 6;
    int s = n & 255;
    const float* tp = ta + ((size_t)(n * 256 + s)) * 24 + h * 4;
    float acc = 0.f;
    #pragma unroll
    for (int f = 0; f < 4; f++)
        acc += tp[f] * qkv[(size_t)(f * 256 + s) * 1152 + 768 + c];
    xd[(size_t)n * 384 + c] = acc;
}

// ---------------------------------------------------------------------------
// middle: logits + softmax + AB in place as bf16 hi/lo over Lg row.
// ---------------------------------------------------------------------------
__global__ void __launch_bounds__(256) middle_kernel(int g, float* __restrict__ out_attn,
                                                     int write_out)
{
    int n = blockIdx.x;
    int hg = blockIdx.y;
    int s = threadIdx.x;
    __shared__ __align__(16) float sta[256][24];
    __shared__ float red[8];
    __shared__ float mv[2];

    const float4* tap = (const float4*)(g_scratch + OFF_TA + (size_t)n * 6144);
    float4* stp = (float4*)&sta[0][0];
    for (int idx = s; idx < 1536; idx += 256)
        stp[idx] = tap[idx];
    __syncthreads();

    float* lg = g_scratch + OFF_QK + (long long)hg * LG_STRIDE + (size_t)n * 6144;
    float logit = 0.f;
    #pragma unroll
    for (int j = 0; j < 24; j++)
        logit += sta[s][j] * lg[j * 256 + s];

    float m = logit;
    #pragma unroll
    for (int o = 16; o; o >>= 1) m = fmaxf(m, __shfl_xor_sync(0xffffffffu, m, o));
    if ((s & 31) == 0) red[s >> 5] = m;
    __syncthreads();
    if (s == 0) { float t = red[0]; for (int i = 1; i < 8; i++) t = fmaxf(t, red[i]); mv[0] = t; }
    __syncthreads();
    float e = expf(logit - mv[0]);
    float sum = e;
    #pragma unroll
    for (int o = 16; o; o >>= 1) sum += __shfl_xor_sync(0xffffffffu, sum, o);
    if ((s & 31) == 0) red[s >> 5] = sum;
    __syncthreads();
    if (s == 0) { float t = 0.f; for (int i = 0; i < 8; i++) t += red[i]; mv[1] = 1.0f / t; }
    __syncthreads();
    float sa = e * mv[1];
    if (write_out) out_attn[((size_t)(g * 2 + hg) * 1024 + n) * 256 + s] = sa;
    __nv_bfloat16* ab = (__nv_bfloat16*)lg;
    #pragma unroll
    for (int j = 0; j < 24; j++) {
        float v = sa * sta[s][j];
        __nv_bfloat16 hi = __float2bfloat16(v);
        __nv_bfloat16 lo = __float2bfloat16(v - __bfloat162float(hi));
        ab[j * 256 + s] = hi;
        ab[6144 + j * 256 + s] = lo;
    }
}

// ---------------------------------------------------------------------------
__global__ void oreduce_kernel(int g)
{
    const float* opart = g_scratch + OFF_OPART;
    float* o = g_scratch + OFF_O;
    int i = blockIdx.x * 256 + threadIdx.x;       // < 131072
    int hg = i >> 16;
    int r = i & 65535;
    float sum = 0.f;
    #pragma unroll
    for (int zk = 0; zk < 12; zk++)
        sum += opart[(size_t)(zk * 2 + hg) * 65536 + r];
    o[(size_t)(r >> 6) * 384 + (g * 2 + hg) * 64 + (r & 63)] = sum;
}

// ---------------------------------------------------------------------------
__global__ void upsample_kernel(float* __restrict__ out, int out_size)
{
    const float* h2 = g_scratch + OFF_H2;
    int fd = blockIdx.x;
    int f = fd / 384, d = fd % 384;
    __shared__ float ch[256];
    int t = threadIdx.x;
    ch[t] = h2[(size_t)(f * 256 + t) * 384 + d];
    __syncthreads();
    #pragma unroll
    for (int p = 0; p < 4; p++) {
        int o = t + p * 256;
        int oy = o >> 5, ox = o & 31;
        float fy = 0.5f * oy - 0.25f;
        int iy0 = (int)floorf(fy);
        float wy = fy - (float)iy0;
        int iy0c = max(iy0, 0), iy1c = min(iy0 + 1, 15);
        float fx = 0.5f * ox - 0.25f;
        int ix0 = (int)floorf(fx);
        float wx = fx - (float)ix0;
        int ix0c = max(ix0, 0), ix1c = min(ix0 + 1, 15);
        float v00 = ch[iy0c * 16 + ix0c], v01 = ch[iy0c * 16 + ix1c];
        float v10 = ch[iy1c * 16 + ix0c], v11 = ch[iy1c * 16 + ix1c];
        float v = (1.f - wy) * ((1.f - wx) * v00 + wx * v01)
                + wy * ((1.f - wx) * v10 + wx * v11);
        long long oi = (long long)fd * 1024 + o;
        if (oi < (long long)out_size) out[oi] = v;
    }
}

// ---------------------------------------------------------------------------
// bf16 hi/lo split: fp32 [rows][inStride] (first `width` cols) -> two bf16
// ---------------------------------------------------------------------------
__global__ void cvt_split_kernel(long long inOff, int inStride, int width,
                                 long long hiOff, long long loOff)
{
    long long i = (long long)blockIdx.x * 256 + threadIdx.x;
    int row = (int)(i / width);
    int col = (int)(i % width);
    float v = g_scratch[inOff + (long long)row * inStride + col];
    __nv_bfloat16 h = __float2bfloat16(v);
    float rem = v - __bfloat162float(h);
    __nv_bfloat16 l = __float2bfloat16(rem);
    ((__nv_bfloat16*)(g_scratch + hiOff))[i] = h;
    ((__nv_bfloat16*)(g_scratch + loOff))[i] = l;
}

// ---------------------------------------------------------------------------
// cvt_wt: transpose-split global fp32 W[Kd][Nd] -> WT hi/lo bf16 [Nd][Kd].
// ---------------------------------------------------------------------------
__global__ void cvt_wt_kernel(const float* __restrict__ W, int Kd, int Nd,
                              long long hiOff, long long loOff)
{
    __shared__ float tile[64][65];
    int kt = blockIdx.x * 64;
    int nt = blockIdx.y * 64;
    int tid = threadIdx.x;
    for (int i = tid; i < 4096; i += 256) {
        int k = i >> 6, n = i & 63;
        tile[k][n] = W[(size_t)(kt + k) * Nd + nt + n];
    }
    __syncthreads();
    __nv_bfloat16* vh = (__nv_bfloat16*)(g_scratch + hiOff);
    __nv_bfloat16* vl = (__nv_bfloat16*)(g_scratch + loOff);
    for (int i = tid; i < 4096; i += 256) {
        int n = i >> 6, k = i & 63;
        float v = tile[k][n];
        __nv_bfloat16 hi = __float2bfloat16(v);
        __nv_bfloat16 lo = __float2bfloat16(v - __bfloat162float(hi));
        size_t idx = (size_t)(nt + n) * Kd + kt + k;
        vh[idx] = hi;
        vl[idx] = lo;
    }
}

// ---------------------------------------------------------------------------
// cvt_vwt: transpose-split VWv -> VWvT[h][n=64][k=6144] bf16 hi/lo.
// ---------------------------------------------------------------------------
__global__ void cvt_vwt_kernel()
{
    __shared__ float tile[64][65];
    int kt = blockIdx.x * 64;
    int h = blockIdx.y;
    int tid = threadIdx.x;
    for (int i = tid; i < 4096; i += 256) {
        int k = i >> 6, n = i & 63;
        tile[k][n] = g_scratch[OFF_VW + (size_t)(kt + k) * 768 + 384 + h * 64 + n];
    }
    __syncthreads();
    __nv_bfloat16* vh = (__nv_bfloat16*)(g_scratch + OFF_VWTH);
    __nv_bfloat16* vl = (__nv_bfloat16*)(g_scratch + OFF_VWTL);
    for (int i = tid; i < 4096; i += 256) {
        int n = i >> 6, k = i & 63;
        float v = tile[k][n];
        __nv_bfloat16 hi = __float2bfloat16(v);
        __nv_bfloat16 lo = __float2bfloat16(v - __bfloat162float(hi));
        size_t idx = ((size_t)h * 64 + n) * 6144 + kt + k;
        vh[idx] = hi;
        vl[idx] = lo;
    }
}

// ===========================================================================
// mma.sync helpers (R10/R11-proven)
// ===========================================================================
__device__ __forceinline__ void ldsm_x4(uint32_t* r, uint32_t addr)
{
    asm volatile("ldmatrix.sync.aligned.m8n8.x4.shared.b16 {%0,%1,%2,%3}, [%4];"
                 : "=r"(r[0]), "=r"(r[1]), "=r"(r[2]), "=r"(r[3]) : "r"(addr));
}
__device__ __forceinline__ void mma_bf16(float* d, const uint32_t* a, const uint32_t* b)
{
    asm volatile(
        "mma.sync.aligned.m16n8k16.row.col.f32.bf16.bf16.f32 "
        "{%0,%1,%2,%3}, {%4,%5,%6,%7}, {%8,%9}, {%0,%1,%2,%3};"
        : "+f"(d[0]), "+f"(d[1]), "+f"(d[2]), "+f"(d[3])
        : "r"(a[0]), "r"(a[1]), "r"(a[2]), "r"(a[3]), "r"(b[0]), "r"(b[1]));
}

#define MMA_SMEM_BYTES 73728
#define APAD 72

// ===========================================================================
// mma_lg (R10-proven): Lg tile (128 x 128) = q2_h @ VWk_h^T, K=64, x3 splits.
// ===========================================================================
__global__ void __launch_bounds__(256) mma_lg_kernel(int g)
{
    extern __shared__ __align__(16) char dsm[];
    __nv_bfloat16* Ah = (__nv_bfloat16*)dsm;
    __nv_bfloat16* Al = Ah + 128 * APAD;
    __nv_bfloat16* Bh = Al + 128 * APAD;
    __nv_bfloat16* Bl = Bh + 128 * APAD;

    int tid = threadIdx.x;
    int wid = tid >> 5, lid = tid & 31;
    int bn = blockIdx.x * 128;
    int bm = blockIdx.y * 128;
    int hg = blockIdx.z;
    int h = g * 2 + hg;

    const __nv_bfloat16* q2h = (const __nv_bfloat16*)(g_scratch + OFF_XN);
    const __nv_bfloat16* q2l = (const __nv_bfloat16*)(g_scratch + OFF_XN + 196608);
    const __nv_bfloat16* vwh = (const __nv_bfloat16*)(g_scratch + OFF_QKV);
    const __nv_bfloat16* vwl = (const __nv_bfloat16*)(g_scratch + OFF_MLP);

    {
        int r = tid >> 1, half = tid & 1;
        const uint4* sah = (const uint4*)(q2h + (size_t)(bm + r) * 384 + h * 64 + half * 32);
        const uint4* sal = (const uint4*)(q2l + (size_t)(bm + r) * 384 + h * 64 + half * 32);
        uint4* dah = (uint4*)(Ah + r * APAD + half * 32);
        uint4* dal = (uint4*)(Al + r * APAD + half * 32);
        #pragma unroll
        for (int i = 0; i < 4; i++) { dah[i] = sah[i]; dal[i] = sal[i]; }
        const uint4* sbh = (const uint4*)(vwh + (size_t)(bn + r) * 384 + h * 64 + half * 32);
        const uint4* sbl = (const uint4*)(vwl + (size_t)(bn + r) * 384 + h * 64 + half * 32);
        uint4* dbh = (uint4*)(Bh + r * APAD + half * 32);
        uint4* dbl = (uint4*)(Bl + r * APAD + half * 32);
        #pragma unroll
        for (int i = 0; i < 4; i++) { dbh[i] = sbh[i]; dbl[i] = sbl[i]; }
    }
    __syncthreads();

    int warp_m = wid & 3;
    int warp_n = wid >> 2;
    int m_base = warp_m * 32;
    int n_base = warp_n * 64;

    float acc[16][4];
    #pragma unroll
    for (int i = 0; i < 16; i++)
        #pragma unroll
        for (int j = 0; j < 4; j++) acc[i][j] = 0.f;

    int a_row = lid & 15;
    int a_colb = (lid >> 4) * 8;
    int b_row = (lid >> 4) * 8 + (lid & 7);
    int b_colb = ((lid >> 3) & 1) * 8;

    #pragma unroll
    for (int sp = 0; sp < 3; sp++) {
        const __nv_bfloat16* As = (sp == 2) ? Al : Ah;
        const __nv_bfloat16* Bs = (sp == 1) ? Bl : Bh;
        #pragma unroll
        for (int ks = 0; ks < 4; ks++) {
            int k0 = ks * 16;
            uint32_t afr[2][4];
            #pragma unroll
            for (int am = 0; am < 2; am++) {
                uint32_t addr = smem_to_u32(As + (size_t)(m_base + am * 16 + a_row) * APAD
                                            + k0 + a_colb);
                ldsm_x4(afr[am], addr);
            }
            uint32_t bfr[8][2];
            #pragma unroll
            for (int p = 0; p < 4; p++) {
                uint32_t r4[4];
                uint32_t addr = smem_to_u32(Bs + (size_t)(n_base + p * 16 + b_row) * APAD
                                            + k0 + b_colb);
                ldsm_x4(r4, addr);
                bfr[2 * p + 0][0] = r4[0]; bfr[2 * p + 0][1] = r4[1];
                bfr[2 * p + 1][0] = r4[2]; bfr[2 * p + 1][1] = r4[3];
            }
            #pragma unroll
            for (int am = 0; am < 2; am++)
                #pragma unroll
                for (int an = 0; an < 8; an++)
                    mma_bf16(acc[am * 8 + an], afr[am], bfr[an]);
        }
    }

    float* lg = g_scratch + OFF_QK + (long long)hg * LG_STRIDE;
    int gid = lid >> 2, tig = lid & 3;
    #pragma unroll
    for (int am = 0; am < 2; am++) {
        #pragma unroll
        for (int an = 0; an < 8; an++) {
            const float* d = acc[am * 8 + an];
            long long row0 = bm + m_base + am * 16 + gid;
            long long col = bn + n_base + an * 8 + tig * 2;
            *(float2*)(lg + row0 * 6144 + col) = make_float2(d[0], d[1]);
            *(float2*)(lg + (row0 + 8) * 6144 + col) = make_float2(d[2], d[3]);
        }
    }
}

// ===========================================================================
// mma_nt64: generic K=64 NT mma with strided 64-col slices, x3 splits.
// A rows: aBase(H/L) bf16 + (bm+r)*lda + aCol0 + z*aColStep
// B rows: bBase(H/L) bf16 + (bn+r)*ldb + bCol0 + z*bColStep
// C fp32: cOff + z*cZStride, [row][ldc]. grid (N/128, M/128, Z).
// ===========================================================================
__global__ void __launch_bounds__(256) mma_nt64_kernel(
    long long aHiOff, long long aLoOff, int lda, int aCol0, int aColStep,
    long long bHiOff, long long bLoOff, int ldb, int bCol0, int bColStep,
    long long cOff, int ldc, long long cZStride)
{
    extern __shared__ __align__(16) char dsm[];
    __nv_bfloat16* Ah = (__nv_bfloat16*)dsm;
    __nv_bfloat16* Al = Ah + 128 * APAD;
    __nv_bfloat16* Bh = Al + 128 * APAD;
    __nv_bfloat16* Bl = Bh + 128 * APAD;

    int tid = threadIdx.x;
    int wid = tid >> 5, lid = tid & 31;
    int bn = blockIdx.x * 128;
    int bm = blockIdx.y * 128;
    int z = blockIdx.z;

    const __nv_bfloat16* ah = (const __nv_bfloat16*)(g_scratch + aHiOff)
                              + aCol0 + z * aColStep;
    const __nv_bfloat16* al = (const __nv_bfloat16*)(g_scratch + aLoOff)
                              + aCol0 + z * aColStep;
    const __nv_bfloat16* bh = (const __nv_bfloat16*)(g_scratch + bHiOff)
                              + bCol0 + z * bColStep;
    const __nv_bfloat16* bl = (const __nv_bfloat16*)(g_scratch + bLoOff)
                              + bCol0 + z * bColStep;

    {
        int r = tid >> 1, half = tid & 1;
        const uint4* sah = (const uint4*)(ah + (size_t)(bm + r) * lda + half * 32);
        const uint4* sal = (const uint4*)(al + (size_t)(bm + r) * lda + half * 32);
        uint4* dah = (uint4*)(Ah + r * APAD + half * 32);
        uint4* dal = (uint4*)(Al + r * APAD + half * 32);
        #pragma unroll
        for (int i = 0; i < 4; i++) { dah[i] = sah[i]; dal[i] = sal[i]; }
        const uint4* sbh = (const uint4*)(bh + (size_t)(bn + r) * ldb + half * 32);
        const uint4* sbl = (const uint4*)(bl + (size_t)(bn + r) * ldb + half * 32);
        uint4* dbh = (uint4*)(Bh + r * APAD + half * 32);
        uint4* dbl = (uint4*)(Bl + r * APAD + half * 32);
        #pragma unroll
        for (int i = 0; i < 4; i++) { dbh[i] = sbh[i]; dbl[i] = sbl[i]; }
    }
    __syncthreads();

    int warp_m = wid & 3;
    int warp_n = wid >> 2;
    int m_base = warp_m * 32;
    int n_base = warp_n * 64;

    float acc[16][4];
    #pragma unroll
    for (int i = 0; i < 16; i++)
        #pragma unroll
        for (int j = 0; j < 4; j++) acc[i][j] = 0.f;

    int a_row = lid & 15;
    int a_colb = (lid >> 4) * 8;
    int b_row = (lid >> 4) * 8 + (lid & 7);
    int b_colb = ((lid >> 3) & 1) * 8;

    #pragma unroll
    for (int sp = 0; sp < 3; sp++) {
        const __nv_bfloat16* As = (sp == 2) ? Al : Ah;
        const __nv_bfloat16* Bs = (sp == 1) ? Bl : Bh;
        #pragma unroll
        for (int ks = 0; ks < 4; ks++) {
            int k0 = ks * 16;
            uint32_t afr[2][4];
            #pragma unroll
            for (int am = 0; am < 2; am++) {
                uint32_t addr = smem_to_u32(As + (size_t)(m_base + am * 16 + a_row) * APAD
                                            + k0 + a_colb);
                ldsm_x4(afr[am], addr);
            }
            uint32_t bfr[8][2];
            #pragma unroll
            for (int p = 0; p < 4; p++) {
                uint32_t r4[4];
                uint32_t addr = smem_to_u32(Bs + (size_t)(n_base + p * 16 + b_row) * APAD
                                            + k0 + b_colb);
                ldsm_x4(r4, addr);
                bfr[2 * p + 0][0] = r4[0]; bfr[2 * p + 0][1] = r4[1];
                bfr[2 * p + 1][0] = r4[2]; bfr[2 * p + 1][1] = r4[3];
            }
            #pragma unroll
            for (int am = 0; am < 2; am++)
                #pragma unroll
                for (int an = 0; an < 8; an++)
                    mma_bf16(acc[am * 8 + an], afr[am], bfr[an]);
        }
    }

    float* C = g_scratch + cOff + (long long)z * cZStride;
    int gid = lid >> 2, tig = lid & 3;
    #pragma unroll
    for (int am = 0; am < 2; am++) {
        #pragma unroll
        for (int an = 0; an < 8; an++) {
            const float* d = acc[am * 8 + an];
            long long row0 = bm + m_base + am * 16 + gid;
            long long col = bn + n_base + an * 8 + tig * 2;
            *(float2*)(C + row0 * ldc + col) = make_float2(d[0], d[1]);
            *(float2*)(C + (row0 + 8) * ldc + col) = make_float2(d[2], d[3]);
        }
    }
}

// ===========================================================================
// mma_o (R11-proven): o partials = AB(bf16 hi/lo) @ VWvT^T.
// ===========================================================================
#define MMAO_SMEM_BYTES 55296

__global__ void __launch_bounds__(256) mma_o_kernel(int g)
{
    extern __shared__ __align__(16) char dsm[];
    __nv_bfloat16* Ah = (__nv_bfloat16*)dsm;
    __nv_bfloat16* Al = Ah + 128 * APAD;
    __nv_bfloat16* Bh = Al + 128 * APAD;
    __nv_bfloat16* Bl = Bh + 64 * APAD;

    int tid = threadIdx.x;
    int wid = tid >> 5, lid = tid & 31;
    int zk = blockIdx.x;
    int bm = blockIdx.y * 128;
    int hg = blockIdx.z;
    int h = g * 2 + hg;

    const __nv_bfloat16* ab = (const __nv_bfloat16*)(g_scratch + OFF_QK
                                                     + (long long)hg * LG_STRIDE);
    const __nv_bfloat16* vh = (const __nv_bfloat16*)(g_scratch + OFF_VWTH)
                              + (size_t)h * 64 * 6144;
    const __nv_bfloat16* vl = (const __nv_bfloat16*)(g_scratch + OFF_VWTL)
                              + (size_t)h * 64 * 6144;

    int warp_m = wid & 3;
    int warp_n = wid >> 2;
    int m_base = warp_m * 32;
    int n_base = warp_n * 32;

    float acc[8][4];
    #pragma unroll
    for (int i = 0; i < 8; i++)
        #pragma unroll
        for (int j = 0; j < 4; j++) acc[i][j] = 0.f;

    int a_row = lid & 15;
    int a_colb = (lid >> 4) * 8;
    int b_row = (lid >> 4) * 8 + (lid & 7);
    int b_colb = ((lid >> 3) & 1) * 8;

    int r2 = tid >> 1, half = tid & 1;

    for (int ch = 0; ch < 8; ch++) {
        int koff = zk * 512 + ch * 64;
        {
            const uint4* sah = (const uint4*)(ab + (size_t)(bm + r2) * 12288 + koff + half * 32);
            const uint4* sal = (const uint4*)(ab + (size_t)(bm + r2) * 12288 + 6144 + koff + half * 32);
            uint4* dah = (uint4*)(Ah + r2 * APAD + half * 32);
            uint4* dal = (uint4*)(Al + r2 * APAD + half * 32);
            #pragma unroll
            for (int i = 0; i < 4; i++) { dah[i] = sah[i]; dal[i] = sal[i]; }
        }
        if (tid < 128) {
            const uint4* sbh = (const uint4*)(vh + (size_t)r2 * 6144 + koff + half * 32);
            const uint4* sbl = (const uint4*)(vl + (size_t)r2 * 6144 + koff + half * 32);
            uint4* dbh = (uint4*)(Bh + r2 * APAD + half * 32);
            uint4* dbl = (uint4*)(Bl + r2 * APAD + half * 32);
            #pragma unroll
            for (int i = 0; i < 4; i++) { dbh[i] = sbh[i]; dbl[i] = sbl[i]; }
        }
        __syncthreads();

        #pragma unroll
        for (int sp = 0; sp < 3; sp++) {
            const __nv_bfloat16* As = (sp == 2) ? Al : Ah;
            const __nv_bfloat16* Bs = (sp == 1) ? Bl : Bh;
            #pragma unroll
            for (int ks = 0; ks < 4; ks++) {
                int k0 = ks * 16;
                uint32_t afr[2][4];
                #pragma unroll
                for (int am = 0; am < 2; am++) {
                    uint32_t addr = smem_to_u32(As + (size_t)(m_base + am * 16 + a_row) * APAD
                                                + k0 + a_colb);
                    ldsm_x4(afr[am], addr);
                }
                uint32_t bfr[4][2];
                #pragma unroll
                for (int p = 0; p < 2; p++) {
                    uint32_t r4[4];
                    uint32_t addr = smem_to_u32(Bs + (size_t)(n_base + p * 16 + b_row) * APAD
                                                + k0 + b_colb);
                    ldsm_x4(r4, addr);
                    bfr[2 * p + 0][0] = r4[0]; bfr[2 * p + 0][1] = r4[1];
                    bfr[2 * p + 1][0] = r4[2]; bfr[2 * p + 1][1] = r4[3];
                }
                #pragma unroll
                for (int am = 0; am < 2; am++)
                    #pragma unroll
                    for (int an = 0; an < 4; an++)
                        mma_bf16(acc[am * 4 + an], afr[am], bfr[an]);
            }
        }
        __syncthreads();
    }

    float* opart = g_scratch + OFF_OPART + (size_t)(zk * 2 + hg) * 65536;
    int gid = lid >> 2, tig = lid & 3;
    #pragma unroll
    for (int am = 0; am < 2; am++) {
        #pragma unroll
        for (int an = 0; an < 4; an++) {
            const float* d = acc[am * 4 + an];
            int row0 = bm + m_base + am * 16 + gid;
            int col = n_base + an * 8 + tig * 2;
            *(float2*)(opart + (size_t)row0 * 64 + col) = make_float2(d[0], d[1]);
            *(float2*)(opart + (size_t)(row0 + 8) * 64 + col) = make_float2(d[2], d[3]);
        }
    }
}

// ===========================================================================
// mma_nt (R13-proven): C[M x N] = A(hi/lo [M][K]) @ WT(hi/lo [N][K])^T.
// flags: 1=bias 2=residual 4=gelu.
// ===========================================================================
__global__ void __launch_bounds__(256) mma_nt_kernel(
    long long aHiOff, long long aLoOff,
    long long bHiOff, long long bLoOff,
    const float* __restrict__ bias, long long rOff, long long cOff,
    int K, int ldc, int flags)
{
    extern __shared__ __align__(16) char dsm[];
    __nv_bfloat16* Ah = (__nv_bfloat16*)dsm;
    __nv_bfloat16* Al = Ah + 128 * APAD;
    __nv_bfloat16* Bh = Al + 128 * APAD;
    __nv_bfloat16* Bl = Bh + 128 * APAD;

    int tid = threadIdx.x;
    int wid = tid >> 5, lid = tid & 31;
    int bn = blockIdx.x * 128;
    int bm = blockIdx.y * 128;

    const __nv_bfloat16* ah = (const __nv_bfloat16*)(g_scratch + aHiOff);
    const __nv_bfloat16* al = (const __nv_bfloat16*)(g_scratch + aLoOff);
    const __nv_bfloat16* bh = (const __nv_bfloat16*)(g_scratch + bHiOff);
    const __nv_bfloat16* bl = (const __nv_bfloat16*)(g_scratch + bLoOff);

    int warp_m = wid & 3;
    int warp_n = wid >> 2;
    int m_base = warp_m * 32;
    int n_base = warp_n * 64;

    float acc[16][4];
    #pragma unroll
    for (int i = 0; i < 16; i++)
        #pragma unroll
        for (int j = 0; j < 4; j++) acc[i][j] = 0.f;

    int a_row = lid & 15;
    int a_colb = (lid >> 4) * 8;
    int b_row = (lid >> 4) * 8 + (lid & 7);
    int b_colb = ((lid >> 3) & 1) * 8;

    int r2 = tid >> 1, half = tid & 1;
    int nch = K / 64;

    for (int ch = 0; ch < nch; ch++) {
        int koff = ch * 64;
        {
            const uint4* sah = (const uint4*)(ah + (size_t)(bm + r2) * K + koff + half * 32);
            const uint4* sal = (const uint4*)(al + (size_t)(bm + r2) * K + koff + half * 32);
            uint4* dah = (uint4*)(Ah + r2 * APAD + half * 32);
            uint4* dal = (uint4*)(Al + r2 * APAD + half * 32);
            #pragma unroll
            for (int i = 0; i < 4; i++) { dah[i] = sah[i]; dal[i] = sal[i]; }
            const uint4* sbh = (const uint4*)(bh + (size_t)(bn + r2) * K + koff + half * 32);
            const uint4* sbl = (const uint4*)(bl + (size_t)(bn + r2) * K + koff + half * 32);
            uint4* dbh = (uint4*)(Bh + r2 * APAD + half * 32);
            uint4* dbl = (uint4*)(Bl + r2 * APAD + half * 32);
            #pragma unroll
            for (int i = 0; i < 4; i++) { dbh[i] = sbh[i]; dbl[i] = sbl[i]; }
        }
        __syncthreads();

        #pragma unroll
        for (int sp = 0; sp < 3; sp++) {
            const __nv_bfloat16* As = (sp == 2) ? Al : Ah;
            const __nv_bfloat16* Bs = (sp == 1) ? Bl : Bh;
            #pragma unroll
            for (int ks = 0; ks < 4; ks++) {
                int k0 = ks * 16;
                uint32_t afr[2][4];
                #pragma unroll
                for (int am = 0; am < 2; am++) {
                    uint32_t addr = smem_to_u32(As + (size_t)(m_base + am * 16 + a_row) * APAD
                                                + k0 + a_colb);
                    ldsm_x4(afr[am], addr);
                }
                uint32_t bfr[8][2];
                #pragma unroll
                for (int p = 0; p < 4; p++) {
                    uint32_t r4[4];
                    uint32_t addr = smem_to_u32(Bs + (size_t)(n_base + p * 16 + b_row) * APAD
                                                + k0 + b_colb);
                    ldsm_x4(r4, addr);
                    bfr[2 * p + 0][0] = r4[0]; bfr[2 * p + 0][1] = r4[1];
                    bfr[2 * p + 1][0] = r4[2]; bfr[2 * p + 1][1] = r4[3];
                }
                #pragma unroll
                for (int am = 0; am < 2; am++)
                    #pragma unroll
                    for (int an = 0; an < 8; an++)
                        mma_bf16(acc[am * 8 + an], afr[am], bfr[an]);
            }
        }
        __syncthreads();
    }

    float* C = g_scratch + cOff;
    const float* R = g_scratch + rOff;
    int gid = lid >> 2, tig = lid & 3;
    #pragma unroll
    for (int am = 0; am < 2; am++) {
        #pragma unroll
        for (int an = 0; an < 8; an++) {
            float d0 = acc[am * 8 + an][0], d1 = acc[am * 8 + an][1];
            float d2 = acc[am * 8 + an][2], d3 = acc[am * 8 + an][3];
            long long rowA = bm + m_base + am * 16 + gid;
            long long rowB = rowA + 8;
            long long col = bn + n_base + an * 8 + tig * 2;
            if (flags & 1) { float b0 = bias[col], b1 = bias[col + 1];
                             d0 += b0; d1 += b1; d2 += b0; d3 += b1; }
            if (flags & 4) {
                d0 = 0.5f * d0 * (1.0f + erff(d0 * 0.7071067811865476f));
                d1 = 0.5f * d1 * (1.0f + erff(d1 * 0.7071067811865476f));
                d2 = 0.5f * d2 * (1.0f + erff(d2 * 0.7071067811865476f));
                d3 = 0.5f * d3 * (1.0f + erff(d3 * 0.7071067811865476f));
            }
            if (flags & 2) {
                d0 += R[rowA * ldc + col]; d1 += R[rowA * ldc + col + 1];
                d2 += R[rowB * ldc + col]; d3 += R[rowB * ldc + col + 1];
            }
            *(float2*)(C + rowA * ldc + col) = make_float2(d0, d1);
            *(float2*)(C + rowB * ldc + col) = make_float2(d2, d3);
        }
    }
}

// ---------------------------------------------------------------------------
extern "C" void kernel_launch(void* const* d_in, const int* in_sizes, int n_in,
                              void* d_out, int out_size)
{
    (void)in_sizes; (void)n_in;
    const float* x      = (const float*)d_in[0];
    const float* qkv_w  = (const float*)d_in[1];
    const float* q2_w   = (const float*)d_in[2];
    const float* kv2_w  = (const float*)d_in[3];
    const float* proj_w = (const float*)d_in[4];
    const float* proj_b = (const float*)d_in[5];
    const float* ln1_g  = (const float*)d_in[6];
    const float* ln1_b  = (const float*)d_in[7];
    const float* ln2_g  = (const float*)d_in[8];
    const float* ln2_b  = (const float*)d_in[9];
    const float* fc1_w  = (const float*)d_in[10];
    const float* fc1_b  = (const float*)d_in[11];
    const float* fc2_w  = (const float*)d_in[12];
    const float* fc2_b  = (const float*)d_in[13];
    float* out = (float*)d_out;

    cudaFuncSetAttribute(mma_lg_kernel,
                         cudaFuncAttributeMaxDynamicSharedMemorySize, MMA_SMEM_BYTES);
    cudaFuncSetAttribute(mma_o_kernel,
                         cudaFuncAttributeMaxDynamicSharedMemorySize, MMAO_SMEM_BYTES);
    cudaFuncSetAttribute(mma_nt_kernel,
                         cudaFuncAttributeMaxDynamicSharedMemorySize, MMA_SMEM_BYTES);
    cudaFuncSetAttribute(mma_nt64_kernel,
                         cudaFuncAttributeMaxDynamicSharedMemorySize, MMA_SMEM_BYTES);

    pool_kernel<<<1536, 256>>>(x);
    ln_kernel<<<1024, 384>>>(OFF_TOK, ln1_g, ln1_b, OFF_XN);

    // qkv via mma: split xn -> XD region; qkv_w^T -> LG region
    cvt_split_kernel<<<1536, 256>>>(OFF_XN, 384, 384, OFF_XD, OFF_XD + 196608);
    cvt_wt_kernel<<<dim3(6, 18), 256>>>(qkv_w, 384, 1152, OFF_LG, OFF_LG + 221184);
    mma_nt_kernel<<<dim3(9, 8), 256, MMA_SMEM_BYTES>>>(
        OFF_XD, OFF_XD + 196608, OFF_LG, OFF_LG + 221184,
        nullptr, 0, OFF_QKV, 384, 1152, 0);

    // full qkv splits -> LG region (overwrites consumed qkv_wT)
    cvt_split_kernel<<<4608, 256>>>(OFF_QKV, 1152, 1152, OFF_LG, OFF_LG + 589824);
    // kv2_w^T splits -> XD region (overwrites consumed xn splits)
    cvt_wt_kernel<<<dim3(6, 12), 256>>>(kv2_w, 384, 768, OFF_XD, OFF_XD + 147456);

    // qk[h] = q_h @ k_h^T via mma (6 heads in z)
    mma_nt64_kernel<<<dim3(8, 8, 6), 256, MMA_SMEM_BYTES>>>(
        OFF_LG, OFF_LG + 589824, 1152, 0, 64,
        OFF_LG, OFF_LG + 589824, 1152, 384, 64,
        OFF_QK, 1024, 1048576);

    // VW[h'] = v_h' @ kv2_w[h' slice] via mma (6 heads in z)
    mma_nt64_kernel<<<dim3(6, 8, 6), 256, MMA_SMEM_BYTES>>>(
        OFF_LG, OFF_LG + 589824, 1152, 768, 64,
        OFF_XD, OFF_XD + 147456, 384, 0, 64,
        OFF_VW, 768, 786432);

    ta_kernel<<<6144, 256>>>();
    xdiag_kernel<<<1024, 384>>>();

    // q2 = SCALE * x_diag @ q2_w (SIMT)
    gemm64_kernel<<<dim3(6, 8, 1), 256>>>(OFF_XD, q2_w, 0, nullptr, 0, OFF_Q2,
        1024, 384, 384, 384, 384, 384, 0, 0, 0, 0, SCALE, 0, 1, 1);

    // bf16 hi/lo splits: q2 -> XN; VW k-half -> QKV / MLP; VWv -> transposed
    cvt_split_kernel<<<1536, 256>>>(OFF_Q2, 384, 384, OFF_XN, OFF_XN + 196608);
    cvt_split_kernel<<<9216, 256>>>(OFF_VW, 768, 384, OFF_QKV, OFF_MLP);
    cvt_vwt_kernel<<<dim3(96, 6), 256>>>();

    int wout = (out_size >= 3145728) ? 1 : 0;

    // stage 2 in 3 groups of 2 heads (Lg/AB overlays dead QK + LG regions)
    for (int g = 0; g < 3; g++) {
        mma_lg_kernel<<<dim3(48, 8, 2), 256, MMA_SMEM_BYTES>>>(g);
        middle_kernel<<<dim3(1024, 2), 256>>>(g, out + 1572864, wout);
        mma_o_kernel<<<dim3(12, 8, 2), 256, MMAO_SMEM_BYTES>>>(g);
        oreduce_kernel<<<512, 256>>>(g);
    }

    // h1 = tok + (o @ proj_w + proj_b) (SIMT)
    gemm64_kernel<<<dim3(6, 8, 1), 256>>>(OFF_O, proj_w, 0, proj_b, OFF_TOK, OFF_H1,
        1024, 384, 384, 384, 384, 384, 384, 0, 0, 0, 1.0f, 1 | 2, 1, 1);

    ln_kernel<<<1024, 384>>>(OFF_H1, ln2_g, ln2_b, OFF_HN);

    // fc1 via mma: split hn -> XD region; fc1_w^T -> QK region
    cvt_split_kernel<<<1536, 256>>>(OFF_HN, 384, 384, OFF_XD, OFF_XD + 196608);
    cvt_wt_kernel<<<dim3(6, 24), 256>>>(fc1_w, 384, 1536, OFF_QK, OFF_QK + 294912);
    mma_nt_kernel<<<dim3(12, 8), 256, MMA_SMEM_BYTES>>>(
        OFF_XD, OFF_XD + 196608, OFF_QK, OFF_QK + 294912,
        fc1_b, 0, OFF_MLP, 384, 1536, 1 | 4);

    // fc2 via mma: split mlp + fc2_w^T into QK region
    cvt_split_kernel<<<6144, 256>>>(OFF_MLP, 1536, 1536,
                                    OFF_QK + 589824, OFF_QK + 1376256);
    cvt_wt_kernel<<<dim3(24, 6), 256>>>(fc2_w, 1536, 384,
                                        OFF_QK + 2162688, OFF_QK + 2457600);
    mma_nt_kernel<<<dim3(3, 8), 256, MMA_SMEM_BYTES>>>(
        OFF_QK + 589824, OFF_QK + 1376256, OFF_QK + 2162688, OFF_QK + 2457600,
        fc2_b, OFF_H1, OFF_H2, 1536, 384, 1 | 2);

    upsample_kernel<<<1536, 256>>>(out, out_size);
}

// round 15
// speedup vs baseline: 1.3864x; 1.0664x over previous
#include <cuda_runtime.h>
#include <cuda_bf16.h>
#include <cstdint>
#include <math.h>

// ---------------------------------------------------------------------------
// DeformationTrajectoryAttentionBlock — all big GEMMs on mma.sync bf16x3;
// fused split epilogues; single batched weight-conversion kernel.
// B=1, F=4, H=6, D=384, G=16, S=256, N=1024, HD=64, IMG=32, MLP_HID=1536
// ---------------------------------------------------------------------------

#define SCALE 0.125f
#define LN_EPS 1e-5f
typedef unsigned long long ull;

#define OFF_TOK    0LL          // 1024*384 fp32
#define OFF_XN     393216LL     // q2 splits: hi bf16 @ +0, lo @ +196608
#define OFF_QKV    786432LL     // 1024*1152 fp32 ; later VWk-hi bf16
#define OFF_VW     1966080LL    // 6*1024*768 (6144 x 768) fp32
#define OFF_QK     6684672LL    // qk fp32 / Lg[hg=0]/AB ; later mlp splits
#define OFF_TA     12976128LL   // 1024*256*24
#define OFF_XD     19267584LL   // xn splits -> xd splits -> hn splits (bf16 hi/lo)
#define OFF_Q2     19660800LL   // (unused fp32 slot)
#define OFF_LG     20054016LL   // qkv splits bf16 -> Lg[hg=1]/AB
#define LG_STRIDE  13369344LL   // OFF_LG - OFF_QK
#define OFF_OPART  26345472LL   // 24 * 1024*64
#define OFF_O      27918336LL   // o splits: hi bf16 @ +0, lo @ +196608
#define OFF_H1     28311552LL
#define OFF_HN     28704768LL   // (unused fp32 slot)
#define OFF_MLP    29097984LL   // VWk-lo bf16
#define OFF_H2     30670848LL
#define OFF_VWTH   31064064LL   // VWv^T hi bf16 [6][64][6144]
#define OFF_VWTL   32243712LL   // VWv^T lo bf16
#define OFF_QKVWT  33423360LL   // qkv_w^T hi/lo (hi +0, lo +221184)
#define OFF_KV2WT  33865728LL   // kv2_w^T hi/lo (hi +0, lo +147456)
#define OFF_Q2WT   34160640LL   // SCALE*q2_w^T hi/lo (hi +0, lo +73728)
#define OFF_PROJWT 34308096LL   // proj_w^T hi/lo (hi +0, lo +73728)
#define OFF_FC1WT  34455552LL   // fc1_w^T hi/lo (hi +0, lo +294912)
#define OFF_FC2WT  35045376LL   // fc2_w^T hi/lo (hi +0, lo +294912)
#define SCRATCH_FLOATS 35635200LL

static __device__ float g_scratch[SCRATCH_FLOATS];

__device__ __forceinline__ uint32_t smem_to_u32(const void* smem_ptr)
{
    uint32_t addr;
    asm("{ .reg .u64 tmp; cvta.to.shared.u64 tmp, %1; cvt.u32.u64 %0, tmp; }"
        : "=r"(addr) : "l"(smem_ptr));
    return addr;
}
__device__ __forceinline__ void split_bf16(float v, __nv_bfloat16& hi, __nv_bfloat16& lo)
{
    hi = __float2bfloat16(v);
    lo = __float2bfloat16(v - __bfloat162float(hi));
}

// ---------------------------------------------------------------------------
__global__ void pool_kernel(const float* __restrict__ x)
{
    float* tok = g_scratch + OFF_TOK;
    int fd = blockIdx.x;
    int f = fd / 384;
    const float* xp = x + (size_t)fd * 1024;
    int t = threadIdx.x;
    int gy = t >> 4, gx = t & 15;
    const float* p = xp + (gy * 2) * 32 + gx * 2;
    float m = fmaxf(fmaxf(p[0], p[1]), fmaxf(p[32], p[33]));
    tok[(size_t)(f * 256 + t) * 384 + (fd % 384)] = m;
}

// ---------------------------------------------------------------------------
// LayerNorm over D=384; writes bf16 hi/lo splits directly.
// ---------------------------------------------------------------------------
__global__ void ln_kernel(long long inOff, const float* __restrict__ g,
                          const float* __restrict__ b,
                          long long hiOff, long long loOff)
{
    const float* in = g_scratch + inOff;
    int n = blockIdx.x, t = threadIdx.x;
    float x = in[(size_t)n * 384 + t];
    __shared__ float red[12];
    __shared__ float mv[2];
    float s = x;
    #pragma unroll
    for (int o = 16; o; o >>= 1) s += __shfl_xor_sync(0xffffffffu, s, o);
    if ((t & 31) == 0) red[t >> 5] = s;
    __syncthreads();
    if (t == 0) { float tt = 0.f; for (int i = 0; i < 12; i++) tt += red[i]; mv[0] = tt * (1.0f / 384.0f); }
    __syncthreads();
    float mean = mv[0];
    float d = x - mean;
    s = d * d;
    #pragma unroll
    for (int o = 16; o; o >>= 1) s += __shfl_xor_sync(0xffffffffu, s, o);
    if ((t & 31) == 0) red[t >> 5] = s;
    __syncthreads();
    if (t == 0) { float tt = 0.f; for (int i = 0; i < 12; i++) tt += red[i]; mv[1] = rsqrtf(tt * (1.0f / 384.0f) + LN_EPS); }
    __syncthreads();
    float v = d * mv[1] * g[t] + b[t];
    __nv_bfloat16 hi, lo;
    split_bf16(v, hi, lo);
    ((__nv_bfloat16*)(g_scratch + hiOff))[(size_t)n * 384 + t] = hi;
    ((__nv_bfloat16*)(g_scratch + loOff))[(size_t)n * 384 + t] = lo;
}

// ---------------------------------------------------------------------------
__global__ void ta_kernel()
{
    const float* qk = g_scratch + OFF_QK;
    float* ta = g_scratch + OFF_TA;
    int b = blockIdx.x;
    int h = b >> 10, n = b & 1023;
    int s = threadIdx.x;
    const float* p = qk + ((size_t)b << 10) + s;
    float x0 = SCALE * p[0], x1 = SCALE * p[256], x2 = SCALE * p[512], x3 = SCALE * p[768];
    float m = fmaxf(fmaxf(x0, x1), fmaxf(x2, x3));
    float e0 = expf(x0 - m), e1 = expf(x1 - m), e2 = expf(x2 - m), e3 = expf(x3 - m);
    float inv = 1.0f / (e0 + e1 + e2 + e3);
    float* o = ta + ((size_t)(n * 256 + s)) * 24 + h * 4;
    o[0] = e0 * inv; o[1] = e1 * inv; o[2] = e2 * inv; o[3] = e3 * inv;
}

// ---------------------------------------------------------------------------
// x_diag -> bf16 hi/lo splits directly (consumed by q2 mma).
// ---------------------------------------------------------------------------
__global__ void xdiag_kernel()
{
    const float* ta = g_scratch + OFF_TA;
    const float* qkv = g_scratch + OFF_QKV;
    int n = blockIdx.x, c = threadIdx.x;
    int h = c >> 6;
    int s = n & 255;
    const float* tp = ta + ((size_t)(n * 256 + s)) * 24 + h * 4;
    float acc = 0.f;
    #pragma unroll
    for (int f = 0; f < 4; f++)
        acc += tp[f] * qkv[(size_t)(f * 256 + s) * 1152 + 768 + c];
    __nv_bfloat16 hi, lo;
    split_bf16(acc, hi, lo);
    ((__nv_bfloat16*)(g_scratch + OFF_XD))[(size_t)n * 384 + c] = hi;
    ((__nv_bfloat16*)(g_scratch + OFF_XD + 196608))[(size_t)n * 384 + c] = lo;
}

// ---------------------------------------------------------------------------
// middle: logits + softmax + AB in place as bf16 hi/lo over Lg row.
// ---------------------------------------------------------------------------
__global__ void __launch_bounds__(256) middle_kernel(int g, float* __restrict__ out_attn,
                                                     int write_out)
{
    int n = blockIdx.x;
    int hg = blockIdx.y;
    int s = threadIdx.x;
    __shared__ __align__(16) float sta[256][24];
    __shared__ float red[8];
    __shared__ float mv[2];

    const float4* tap = (const float4*)(g_scratch + OFF_TA + (size_t)n * 6144);
    float4* stp = (float4*)&sta[0][0];
    for (int idx = s; idx < 1536; idx += 256)
        stp[idx] = tap[idx];
    __syncthreads();

    float* lg = g_scratch + OFF_QK + (long long)hg * LG_STRIDE + (size_t)n * 6144;
    float logit = 0.f;
    #pragma unroll
    for (int j = 0; j < 24; j++)
        logit += sta[s][j] * lg[j * 256 + s];

    float m = logit;
    #pragma unroll
    for (int o = 16; o; o >>= 1) m = fmaxf(m, __shfl_xor_sync(0xffffffffu, m, o));
    if ((s & 31) == 0) red[s >> 5] = m;
    __syncthreads();
    if (s == 0) { float t = red[0]; for (int i = 1; i < 8; i++) t = fmaxf(t, red[i]); mv[0] = t; }
    __syncthreads();
    float e = expf(logit - mv[0]);
    float sum = e;
    #pragma unroll
    for (int o = 16; o; o >>= 1) sum += __shfl_xor_sync(0xffffffffu, sum, o);
    if ((s & 31) == 0) red[s >> 5] = sum;
    __syncthreads();
    if (s == 0) { float t = 0.f; for (int i = 0; i < 8; i++) t += red[i]; mv[1] = 1.0f / t; }
    __syncthreads();
    float sa = e * mv[1];
    if (write_out) out_attn[((size_t)(g * 2 + hg) * 1024 + n) * 256 + s] = sa;
    __nv_bfloat16* ab = (__nv_bfloat16*)lg;
    #pragma unroll
    for (int j = 0; j < 24; j++) {
        float v = sa * sta[s][j];
        __nv_bfloat16 hi, lo;
        split_bf16(v, hi, lo);
        ab[j * 256 + s] = hi;
        ab[6144 + j * 256 + s] = lo;
    }
}

// ---------------------------------------------------------------------------
// split-K(12) reduce for head group g -> o bf16 hi/lo splits.
// ---------------------------------------------------------------------------
__global__ void oreduce_kernel(int g)
{
    const float* opart = g_scratch + OFF_OPART;
    int i = blockIdx.x * 256 + threadIdx.x;       // < 131072
    int hg = i >> 16;
    int r = i & 65535;
    float sum = 0.f;
    #pragma unroll
    for (int zk = 0; zk < 12; zk++)
        sum += opart[(size_t)(zk * 2 + hg) * 65536 + r];
    __nv_bfloat16 hi, lo;
    split_bf16(sum, hi, lo);
    size_t idx = (size_t)(r >> 6) * 384 + (g * 2 + hg) * 64 + (r & 63);
    ((__nv_bfloat16*)(g_scratch + OFF_O))[idx] = hi;
    ((__nv_bfloat16*)(g_scratch + OFF_O + 196608))[idx] = lo;
}

// ---------------------------------------------------------------------------
__global__ void upsample_kernel(float* __restrict__ out, int out_size)
{
    const float* h2 = g_scratch + OFF_H2;
    int fd = blockIdx.x;
    int f = fd / 384, d = fd % 384;
    __shared__ float ch[256];
    int t = threadIdx.x;
    ch[t] = h2[(size_t)(f * 256 + t) * 384 + d];
    __syncthreads();
    #pragma unroll
    for (int p = 0; p < 4; p++) {
        int o = t + p * 256;
        int oy = o >> 5, ox = o & 31;
        float fy = 0.5f * oy - 0.25f;
        int iy0 = (int)floorf(fy);
        float wy = fy - (float)iy0;
        int iy0c = max(iy0, 0), iy1c = min(iy0 + 1, 15);
        float fx = 0.5f * ox - 0.25f;
        int ix0 = (int)floorf(fx);
        float wx = fx - (float)ix0;
        int ix0c = max(ix0, 0), ix1c = min(ix0 + 1, 15);
        float v00 = ch[iy0c * 16 + ix0c], v01 = ch[iy0c * 16 + ix1c];
        float v10 = ch[iy1c * 16 + ix0c], v11 = ch[iy1c * 16 + ix1c];
        float v = (1.f - wy) * ((1.f - wx) * v00 + wx * v01)
                + wy * ((1.f - wx) * v10 + wx * v11);
        long long oi = (long long)fd * 1024 + o;
        if (oi < (long long)out_size) out[oi] = v;
    }
}

// ---------------------------------------------------------------------------
// bf16 hi/lo split (generic): fp32 [rows][inStride] -> two bf16 arrays
// ---------------------------------------------------------------------------
__global__ void cvt_split_kernel(long long inOff, int inStride, int width,
                                 long long hiOff, long long loOff)
{
    long long i = (long long)blockIdx.x * 256 + threadIdx.x;
    int row = (int)(i / width);
    int col = (int)(i % width);
    float v = g_scratch[inOff + (long long)row * inStride + col];
    __nv_bfloat16 h, l;
    split_bf16(v, h, l);
    ((__nv_bfloat16*)(g_scratch + hiOff))[i] = h;
    ((__nv_bfloat16*)(g_scratch + loOff))[i] = l;
}

// ---------------------------------------------------------------------------
// cvt_weights: batched transpose-split of ALL six weights (fp32 -> WT hi/lo).
// grid 540, 256 threads.
// ---------------------------------------------------------------------------
__global__ void cvt_weights_kernel(const float* __restrict__ qkv_w,
                                   const float* __restrict__ kv2_w,
                                   const float* __restrict__ q2_w,
                                   const float* __restrict__ proj_w,
                                   const float* __restrict__ fc1_w,
                                   const float* __restrict__ fc2_w)
{
    __shared__ float tile[64][65];
    int t = blockIdx.x;
    const float* W; int Kd, Nd; long long hiOff, loOff; float scale = 1.0f;
    if (t < 108)      {           W = qkv_w;  Kd = 384;  Nd = 1152;
                        hiOff = OFF_QKVWT;  loOff = OFF_QKVWT + 221184; }
    else if (t < 180) { t -= 108; W = kv2_w;  Kd = 384;  Nd = 768;
                        hiOff = OFF_KV2WT;  loOff = OFF_KV2WT + 147456; }
    else if (t < 216) { t -= 180; W = q2_w;   Kd = 384;  Nd = 384;
                        hiOff = OFF_Q2WT;   loOff = OFF_Q2WT + 73728;  scale = SCALE; }
    else if (t < 252) { t -= 216; W = proj_w; Kd = 384;  Nd = 384;
                        hiOff = OFF_PROJWT; loOff = OFF_PROJWT + 73728; }
    else if (t < 396) { t -= 252; W = fc1_w;  Kd = 384;  Nd = 1536;
                        hiOff = OFF_FC1WT;  loOff = OFF_FC1WT + 294912; }
    else              { t -= 396; W = fc2_w;  Kd = 1536; Nd = 384;
                        hiOff = OFF_FC2WT;  loOff = OFF_FC2WT + 294912; }
    int ktiles = Kd >> 6;
    int kt = (t % ktiles) * 64;
    int nt = (t / ktiles) * 64;
    int tid = threadIdx.x;
    for (int i = tid; i < 4096; i += 256) {
        int k = i >> 6, n = i & 63;
        tile[k][n] = W[(size_t)(kt + k) * Nd + nt + n] * scale;
    }
    __syncthreads();
    __nv_bfloat16* vh = (__nv_bfloat16*)(g_scratch + hiOff);
    __nv_bfloat16* vl = (__nv_bfloat16*)(g_scratch + loOff);
    for (int i = tid; i < 4096; i += 256) {
        int n = i >> 6, k = i & 63;
        float v = tile[k][n];
        __nv_bfloat16 hi, lo;
        split_bf16(v, hi, lo);
        size_t idx = (size_t)(nt + n) * Kd + kt + k;
        vh[idx] = hi;
        vl[idx] = lo;
    }
}

// ---------------------------------------------------------------------------
// cvt_vwt: transpose-split VWv -> VWvT[h][n=64][k=6144] bf16 hi/lo.
// ---------------------------------------------------------------------------
__global__ void cvt_vwt_kernel()
{
    __shared__ float tile[64][65];
    int kt = blockIdx.x * 64;
    int h = blockIdx.y;
    int tid = threadIdx.x;
    for (int i = tid; i < 4096; i += 256) {
        int k = i >> 6, n = i & 63;
        tile[k][n] = g_scratch[OFF_VW + (size_t)(kt + k) * 768 + 384 + h * 64 + n];
    }
    __syncthreads();
    __nv_bfloat16* vh = (__nv_bfloat16*)(g_scratch + OFF_VWTH);
    __nv_bfloat16* vl = (__nv_bfloat16*)(g_scratch + OFF_VWTL);
    for (int i = tid; i < 4096; i += 256) {
        int n = i >> 6, k = i & 63;
        float v = tile[k][n];
        __nv_bfloat16 hi, lo;
        split_bf16(v, hi, lo);
        size_t idx = ((size_t)h * 64 + n) * 6144 + kt + k;
        vh[idx] = hi;
        vl[idx] = lo;
    }
}

// ===========================================================================
// mma.sync helpers (R10/R11-proven)
// ===========================================================================
__device__ __forceinline__ void ldsm_x4(uint32_t* r, uint32_t addr)
{
    asm volatile("ldmatrix.sync.aligned.m8n8.x4.shared.b16 {%0,%1,%2,%3}, [%4];"
                 : "=r"(r[0]), "=r"(r[1]), "=r"(r[2]), "=r"(r[3]) : "r"(addr));
}
__device__ __forceinline__ void mma_bf16(float* d, const uint32_t* a, const uint32_t* b)
{
    asm volatile(
        "mma.sync.aligned.m16n8k16.row.col.f32.bf16.bf16.f32 "
        "{%0,%1,%2,%3}, {%4,%5,%6,%7}, {%8,%9}, {%0,%1,%2,%3};"
        : "+f"(d[0]), "+f"(d[1]), "+f"(d[2]), "+f"(d[3])
        : "r"(a[0]), "r"(a[1]), "r"(a[2]), "r"(a[3]), "r"(b[0]), "r"(b[1]));
}

#define MMA_SMEM_BYTES 73728
#define APAD 72

// ===========================================================================
// mma_lg (R10-proven): Lg tile (128 x 128) = q2_h @ VWk_h^T, K=64, x3 splits.
// ===========================================================================
__global__ void __launch_bounds__(256) mma_lg_kernel(int g)
{
    extern __shared__ __align__(16) char dsm[];
    __nv_bfloat16* Ah = (__nv_bfloat16*)dsm;
    __nv_bfloat16* Al = Ah + 128 * APAD;
    __nv_bfloat16* Bh = Al + 128 * APAD;
    __nv_bfloat16* Bl = Bh + 128 * APAD;

    int tid = threadIdx.x;
    int wid = tid >> 5, lid = tid & 31;
    int bn = blockIdx.x * 128;
    int bm = blockIdx.y * 128;
    int hg = blockIdx.z;
    int h = g * 2 + hg;

    const __nv_bfloat16* q2h = (const __nv_bfloat16*)(g_scratch + OFF_XN);
    const __nv_bfloat16* q2l = (const __nv_bfloat16*)(g_scratch + OFF_XN + 196608);
    const __nv_bfloat16* vwh = (const __nv_bfloat16*)(g_scratch + OFF_QKV);
    const __nv_bfloat16* vwl = (const __nv_bfloat16*)(g_scratch + OFF_MLP);

    {
        int r = tid >> 1, half = tid & 1;
        const uint4* sah = (const uint4*)(q2h + (size_t)(bm + r) * 384 + h * 64 + half * 32);
        const uint4* sal = (const uint4*)(q2l + (size_t)(bm + r) * 384 + h * 64 + half * 32);
        uint4* dah = (uint4*)(Ah + r * APAD + half * 32);
        uint4* dal = (uint4*)(Al + r * APAD + half * 32);
        #pragma unroll
        for (int i = 0; i < 4; i++) { dah[i] = sah[i]; dal[i] = sal[i]; }
        const uint4* sbh = (const uint4*)(vwh + (size_t)(bn + r) * 384 + h * 64 + half * 32);
        const uint4* sbl = (const uint4*)(vwl + (size_t)(bn + r) * 384 + h * 64 + half * 32);
        uint4* dbh = (uint4*)(Bh + r * APAD + half * 32);
        uint4* dbl = (uint4*)(Bl + r * APAD + half * 32);
        #pragma unroll
        for (int i = 0; i < 4; i++) { dbh[i] = sbh[i]; dbl[i] = sbl[i]; }
    }
    __syncthreads();

    int warp_m = wid & 3;
    int warp_n = wid >> 2;
    int m_base = warp_m * 32;
    int n_base = warp_n * 64;

    float acc[16][4];
    #pragma unroll
    for (int i = 0; i < 16; i++)
        #pragma unroll
        for (int j = 0; j < 4; j++) acc[i][j] = 0.f;

    int a_row = lid & 15;
    int a_colb = (lid >> 4) * 8;
    int b_row = (lid >> 4) * 8 + (lid & 7);
    int b_colb = ((lid >> 3) & 1) * 8;

    #pragma unroll
    for (int sp = 0; sp < 3; sp++) {
        const __nv_bfloat16* As = (sp == 2) ? Al : Ah;
        const __nv_bfloat16* Bs = (sp == 1) ? Bl : Bh;
        #pragma unroll
        for (int ks = 0; ks < 4; ks++) {
            int k0 = ks * 16;
            uint32_t afr[2][4];
            #pragma unroll
            for (int am = 0; am < 2; am++) {
                uint32_t addr = smem_to_u32(As + (size_t)(m_base + am * 16 + a_row) * APAD
                                            + k0 + a_colb);
                ldsm_x4(afr[am], addr);
            }
            uint32_t bfr[8][2];
            #pragma unroll
            for (int p = 0; p < 4; p++) {
                uint32_t r4[4];
                uint32_t addr = smem_to_u32(Bs + (size_t)(n_base + p * 16 + b_row) * APAD
                                            + k0 + b_colb);
                ldsm_x4(r4, addr);
                bfr[2 * p + 0][0] = r4[0]; bfr[2 * p + 0][1] = r4[1];
                bfr[2 * p + 1][0] = r4[2]; bfr[2 * p + 1][1] = r4[3];
            }
            #pragma unroll
            for (int am = 0; am < 2; am++)
                #pragma unroll
                for (int an = 0; an < 8; an++)
                    mma_bf16(acc[am * 8 + an], afr[am], bfr[an]);
        }
    }

    float* lg = g_scratch + OFF_QK + (long long)hg * LG_STRIDE;
    int gid = lid >> 2, tig = lid & 3;
    #pragma unroll
    for (int am = 0; am < 2; am++) {
        #pragma unroll
        for (int an = 0; an < 8; an++) {
            const float* d = acc[am * 8 + an];
            long long row0 = bm + m_base + am * 16 + gid;
            long long col = bn + n_base + an * 8 + tig * 2;
            *(float2*)(lg + row0 * 6144 + col) = make_float2(d[0], d[1]);
            *(float2*)(lg + (row0 + 8) * 6144 + col) = make_float2(d[2], d[3]);
        }
    }
}

// ===========================================================================
// mma_nt64 (R14-proven): K=64 NT mma with strided 64-col slices, x3 splits.
// ===========================================================================
__global__ void __launch_bounds__(256) mma_nt64_kernel(
    long long aHiOff, long long aLoOff, int lda, int aCol0, int aColStep,
    long long bHiOff, long long bLoOff, int ldb, int bCol0, int bColStep,
    long long cOff, int ldc, long long cZStride)
{
    extern __shared__ __align__(16) char dsm[];
    __nv_bfloat16* Ah = (__nv_bfloat16*)dsm;
    __nv_bfloat16* Al = Ah + 128 * APAD;
    __nv_bfloat16* Bh = Al + 128 * APAD;
    __nv_bfloat16* Bl = Bh + 128 * APAD;

    int tid = threadIdx.x;
    int wid = tid >> 5, lid = tid & 31;
    int bn = blockIdx.x * 128;
    int bm = blockIdx.y * 128;
    int z = blockIdx.z;

    const __nv_bfloat16* ah = (const __nv_bfloat16*)(g_scratch + aHiOff)
                              + aCol0 + z * aColStep;
    const __nv_bfloat16* al = (const __nv_bfloat16*)(g_scratch + aLoOff)
                              + aCol0 + z * aColStep;
    const __nv_bfloat16* bh = (const __nv_bfloat16*)(g_scratch + bHiOff)
                              + bCol0 + z * bColStep;
    const __nv_bfloat16* bl = (const __nv_bfloat16*)(g_scratch + bLoOff)
                              + bCol0 + z * bColStep;

    {
        int r = tid >> 1, half = tid & 1;
        const uint4* sah = (const uint4*)(ah + (size_t)(bm + r) * lda + half * 32);
        const uint4* sal = (const uint4*)(al + (size_t)(bm + r) * lda + half * 32);
        uint4* dah = (uint4*)(Ah + r * APAD + half * 32);
        uint4* dal = (uint4*)(Al + r * APAD + half * 32);
        #pragma unroll
        for (int i = 0; i < 4; i++) { dah[i] = sah[i]; dal[i] = sal[i]; }
        const uint4* sbh = (const uint4*)(bh + (size_t)(bn + r) * ldb + half * 32);
        const uint4* sbl = (const uint4*)(bl + (size_t)(bn + r) * ldb + half * 32);
        uint4* dbh = (uint4*)(Bh + r * APAD + half * 32);
        uint4* dbl = (uint4*)(Bl + r * APAD + half * 32);
        #pragma unroll
        for (int i = 0; i < 4; i++) { dbh[i] = sbh[i]; dbl[i] = sbl[i]; }
    }
    __syncthreads();

    int warp_m = wid & 3;
    int warp_n = wid >> 2;
    int m_base = warp_m * 32;
    int n_base = warp_n * 64;

    float acc[16][4];
    #pragma unroll
    for (int i = 0; i < 16; i++)
        #pragma unroll
        for (int j = 0; j < 4; j++) acc[i][j] = 0.f;

    int a_row = lid & 15;
    int a_colb = (lid >> 4) * 8;
    int b_row = (lid >> 4) * 8 + (lid & 7);
    int b_colb = ((lid >> 3) & 1) * 8;

    #pragma unroll
    for (int sp = 0; sp < 3; sp++) {
        const __nv_bfloat16* As = (sp == 2) ? Al : Ah;
        const __nv_bfloat16* Bs = (sp == 1) ? Bl : Bh;
        #pragma unroll
        for (int ks = 0; ks < 4; ks++) {
            int k0 = ks * 16;
            uint32_t afr[2][4];
            #pragma unroll
            for (int am = 0; am < 2; am++) {
                uint32_t addr = smem_to_u32(As + (size_t)(m_base + am * 16 + a_row) * APAD
                                            + k0 + a_colb);
                ldsm_x4(afr[am], addr);
            }
            uint32_t bfr[8][2];
            #pragma unroll
            for (int p = 0; p < 4; p++) {
                uint32_t r4[4];
                uint32_t addr = smem_to_u32(Bs + (size_t)(n_base + p * 16 + b_row) * APAD
                                            + k0 + b_colb);
                ldsm_x4(r4, addr);
                bfr[2 * p + 0][0] = r4[0]; bfr[2 * p + 0][1] = r4[1];
                bfr[2 * p + 1][0] = r4[2]; bfr[2 * p + 1][1] = r4[3];
            }
            #pragma unroll
            for (int am = 0; am < 2; am++)
                #pragma unroll
                for (int an = 0; an < 8; an++)
                    mma_bf16(acc[am * 8 + an], afr[am], bfr[an]);
        }
    }

    float* C = g_scratch + cOff + (long long)z * cZStride;
    int gid = lid >> 2, tig = lid & 3;
    #pragma unroll
    for (int am = 0; am < 2; am++) {
        #pragma unroll
        for (int an = 0; an < 8; an++) {
            const float* d = acc[am * 8 + an];
            long long row0 = bm + m_base + am * 16 + gid;
            long long col = bn + n_base + an * 8 + tig * 2;
            *(float2*)(C + row0 * ldc + col) = make_float2(d[0], d[1]);
            *(float2*)(C + (row0 + 8) * ldc + col) = make_float2(d[2], d[3]);
        }
    }
}

// ===========================================================================
// mma_o (R11-proven): o partials = AB(bf16 hi/lo) @ VWvT^T.
// ===========================================================================
#define MMAO_SMEM_BYTES 55296

__global__ void __launch_bounds__(256) mma_o_kernel(int g)
{
    extern __shared__ __align__(16) char dsm[];
    __nv_bfloat16* Ah = (__nv_bfloat16*)dsm;
    __nv_bfloat16* Al = Ah + 128 * APAD;
    __nv_bfloat16* Bh = Al + 128 * APAD;
    __nv_bfloat16* Bl = Bh + 64 * APAD;

    int tid = threadIdx.x;
    int wid = tid >> 5, lid = tid & 31;
    int zk = blockIdx.x;
    int bm = blockIdx.y * 128;
    int hg = blockIdx.z;
    int h = g * 2 + hg;

    const __nv_bfloat16* ab = (const __nv_bfloat16*)(g_scratch + OFF_QK
                                                     + (long long)hg * LG_STRIDE);
    const __nv_bfloat16* vh = (const __nv_bfloat16*)(g_scratch + OFF_VWTH)
                              + (size_t)h * 64 * 6144;
    const __nv_bfloat16* vl = (const __nv_bfloat16*)(g_scratch + OFF_VWTL)
                              + (size_t)h * 64 * 6144;

    int warp_m = wid & 3;
    int warp_n = wid >> 2;
    int m_base = warp_m * 32;
    int n_base = warp_n * 32;

    float acc[8][4];
    #pragma unroll
    for (int i = 0; i < 8; i++)
        #pragma unroll
        for (int j = 0; j < 4; j++) acc[i][j] = 0.f;

    int a_row = lid & 15;
    int a_colb = (lid >> 4) * 8;
    int b_row = (lid >> 4) * 8 + (lid & 7);
    int b_colb = ((lid >> 3) & 1) * 8;

    int r2 = tid >> 1, half = tid & 1;

    for (int ch = 0; ch < 8; ch++) {
        int koff = zk * 512 + ch * 64;
        {
            const uint4* sah = (const uint4*)(ab + (size_t)(bm + r2) * 12288 + koff + half * 32);
            const uint4* sal = (const uint4*)(ab + (size_t)(bm + r2) * 12288 + 6144 + koff + half * 32);
            uint4* dah = (uint4*)(Ah + r2 * APAD + half * 32);
            uint4* dal = (uint4*)(Al + r2 * APAD + half * 32);
            #pragma unroll
            for (int i = 0; i < 4; i++) { dah[i] = sah[i]; dal[i] = sal[i]; }
        }
        if (tid < 128) {
            const uint4* sbh = (const uint4*)(vh + (size_t)r2 * 6144 + koff + half * 32);
            const uint4* sbl = (const uint4*)(vl + (size_t)r2 * 6144 + koff + half * 32);
            uint4* dbh = (uint4*)(Bh + r2 * APAD + half * 32);
            uint4* dbl = (uint4*)(Bl + r2 * APAD + half * 32);
            #pragma unroll
            for (int i = 0; i < 4; i++) { dbh[i] = sbh[i]; dbl[i] = sbl[i]; }
        }
        __syncthreads();

        #pragma unroll
        for (int sp = 0; sp < 3; sp++) {
            const __nv_bfloat16* As = (sp == 2) ? Al : Ah;
            const __nv_bfloat16* Bs = (sp == 1) ? Bl : Bh;
            #pragma unroll
            for (int ks = 0; ks < 4; ks++) {
                int k0 = ks * 16;
                uint32_t afr[2][4];
                #pragma unroll
                for (int am = 0; am < 2; am++) {
                    uint32_t addr = smem_to_u32(As + (size_t)(m_base + am * 16 + a_row) * APAD
                                                + k0 + a_colb);
                    ldsm_x4(afr[am], addr);
                }
                uint32_t bfr[4][2];
                #pragma unroll
                for (int p = 0; p < 2; p++) {
                    uint32_t r4[4];
                    uint32_t addr = smem_to_u32(Bs + (size_t)(n_base + p * 16 + b_row) * APAD
                                                + k0 + b_colb);
                    ldsm_x4(r4, addr);
                    bfr[2 * p + 0][0] = r4[0]; bfr[2 * p + 0][1] = r4[1];
                    bfr[2 * p + 1][0] = r4[2]; bfr[2 * p + 1][1] = r4[3];
                }
                #pragma unroll
                for (int am = 0; am < 2; am++)
                    #pragma unroll
                    for (int an = 0; an < 4; an++)
                        mma_bf16(acc[am * 4 + an], afr[am], bfr[an]);
            }
        }
        __syncthreads();
    }

    float* opart = g_scratch + OFF_OPART + (size_t)(zk * 2 + hg) * 65536;
    int gid = lid >> 2, tig = lid & 3;
    #pragma unroll
    for (int am = 0; am < 2; am++) {
        #pragma unroll
        for (int an = 0; an < 4; an++) {
            const float* d = acc[am * 4 + an];
            int row0 = bm + m_base + am * 16 + gid;
            int col = n_base + an * 8 + tig * 2;
            *(float2*)(opart + (size_t)row0 * 64 + col) = make_float2(d[0], d[1]);
            *(float2*)(opart + (size_t)(row0 + 8) * 64 + col) = make_float2(d[2], d[3]);
        }
    }
}

// ===========================================================================
// mma_nt (R13-proven core, extended epilogue):
// C[M x N] = A(hi/lo [M][K]) @ WT(hi/lo [N][K])^T, x3 splits, K chunked 64.
// flags: 1=bias 2=residual 4=gelu 8=write bf16 splits 16=skip fp32.
// ===========================================================================
__global__ void __launch_bounds__(256) mma_nt_kernel(
    long long aHiOff, long long aLoOff,
    long long bHiOff, long long bLoOff,
    const float* __restrict__ bias, long long rOff, long long cOff,
    long long sHiOff, long long sLoOff,
    int K, int ldc, int flags)
{
    extern __shared__ __align__(16) char dsm[];
    __nv_bfloat16* Ah = (__nv_bfloat16*)dsm;
    __nv_bfloat16* Al = Ah + 128 * APAD;
    __nv_bfloat16* Bh = Al + 128 * APAD;
    __nv_bfloat16* Bl = Bh + 128 * APAD;

    int tid = threadIdx.x;
    int wid = tid >> 5, lid = tid & 31;
    int bn = blockIdx.x * 128;
    int bm = blockIdx.y * 128;

    const __nv_bfloat16* ah = (const __nv_bfloat16*)(g_scratch + aHiOff);
    const __nv_bfloat16* al = (const __nv_bfloat16*)(g_scratch + aLoOff);
    const __nv_bfloat16* bh = (const __nv_bfloat16*)(g_scratch + bHiOff);
    const __nv_bfloat16* bl = (const __nv_bfloat16*)(g_scratch + bLoOff);

    int warp_m = wid & 3;
    int warp_n = wid >> 2;
    int m_base = warp_m * 32;
    int n_base = warp_n * 64;

    float acc[16][4];
    #pragma unroll
    for (int i = 0; i < 16; i++)
        #pragma unroll
        for (int j = 0; j < 4; j++) acc[i][j] = 0.f;

    int a_row = lid & 15;
    int a_colb = (lid >> 4) * 8;
    int b_row = (lid >> 4) * 8 + (lid & 7);
    int b_colb = ((lid >> 3) & 1) * 8;

    int r2 = tid >> 1, half = tid & 1;
    int nch = K / 64;

    for (int ch = 0; ch < nch; ch++) {
        int koff = ch * 64;
        {
            const uint4* sah = (const uint4*)(ah + (size_t)(bm + r2) * K + koff + half * 32);
            const uint4* sal = (const uint4*)(al + (size_t)(bm + r2) * K + koff + half * 32);
            uint4* dah = (uint4*)(Ah + r2 * APAD + half * 32);
            uint4* dal = (uint4*)(Al + r2 * APAD + half * 32);
            #pragma unroll
            for (int i = 0; i < 4; i++) { dah[i] = sah[i]; dal[i] = sal[i]; }
            const uint4* sbh = (const uint4*)(bh + (size_t)(bn + r2) * K + koff + half * 32);
            const uint4* sbl = (const uint4*)(bl + (size_t)(bn + r2) * K + koff + half * 32);
            uint4* dbh = (uint4*)(Bh + r2 * APAD + half * 32);
            uint4* dbl = (uint4*)(Bl + r2 * APAD + half * 32);
            #pragma unroll
            for (int i = 0; i < 4; i++) { dbh[i] = sbh[i]; dbl[i] = sbl[i]; }
        }
        __syncthreads();

        #pragma unroll
        for (int sp = 0; sp < 3; sp++) {
            const __nv_bfloat16* As = (sp == 2) ? Al : Ah;
            const __nv_bfloat16* Bs = (sp == 1) ? Bl : Bh;
            #pragma unroll
            for (int ks = 0; ks < 4; ks++) {
                int k0 = ks * 16;
                uint32_t afr[2][4];
                #pragma unroll
                for (int am = 0; am < 2; am++) {
                    uint32_t addr = smem_to_u32(As + (size_t)(m_base + am * 16 + a_row) * APAD
                                                + k0 + a_colb);
                    ldsm_x4(afr[am], addr);
                }
                uint32_t bfr[8][2];
                #pragma unroll
                for (int p = 0; p < 4; p++) {
                    uint32_t r4[4];
                    uint32_t addr = smem_to_u32(Bs + (size_t)(n_base + p * 16 + b_row) * APAD
                                                + k0 + b_colb);
                    ldsm_x4(r4, addr);
                    bfr[2 * p + 0][0] = r4[0]; bfr[2 * p + 0][1] = r4[1];
                    bfr[2 * p + 1][0] = r4[2]; bfr[2 * p + 1][1] = r4[3];
                }
                #pragma unroll
                for (int am = 0; am < 2; am++)
                    #pragma unroll
                    for (int an = 0; an < 8; an++)
                        mma_bf16(acc[am * 8 + an], afr[am], bfr[an]);
            }
        }
        __syncthreads();
    }

    float* C = g_scratch + cOff;
    const float* R = g_scratch + rOff;
    __nv_bfloat16* SH = (__nv_bfloat16*)(g_scratch + sHiOff);
    __nv_bfloat16* SL = (__nv_bfloat16*)(g_scratch + sLoOff);
    int gid = lid >> 2, tig = lid & 3;
    #pragma unroll
    for (int am = 0; am < 2; am++) {
        #pragma unroll
        for (int an = 0; an < 8; an++) {
            float d0 = acc[am * 8 + an][0], d1 = acc[am * 8 + an][1];
            float d2 = acc[am * 8 + an][2], d3 = acc[am * 8 + an][3];
            long long rowA = bm + m_base + am * 16 + gid;
            long long rowB = rowA + 8;
            long long col = bn + n_base + an * 8 + tig * 2;
            if (flags & 1) { float b0 = bias[col], b1 = bias[col + 1];
                             d0 += b0; d1 += b1; d2 += b0; d3 += b1; }
            if (flags & 4) {
                d0 = 0.5f * d0 * (1.0f + erff(d0 * 0.7071067811865476f));
                d1 = 0.5f * d1 * (1.0f + erff(d1 * 0.7071067811865476f));
                d2 = 0.5f * d2 * (1.0f + erff(d2 * 0.7071067811865476f));
                d3 = 0.5f * d3 * (1.0f + erff(d3 * 0.7071067811865476f));
            }
            if (flags & 2) {
                d0 += R[rowA * ldc + col]; d1 += R[rowA * ldc + col + 1];
                d2 += R[rowB * ldc + col]; d3 += R[rowB * ldc + col + 1];
            }
            if (!(flags & 16)) {
                *(float2*)(C + rowA * ldc + col) = make_float2(d0, d1);
                *(float2*)(C + rowB * ldc + col) = make_float2(d2, d3);
            }
            if (flags & 8) {
                __nv_bfloat16 h0, l0, h1, l1, h2, l2, h3, l3;
                split_bf16(d0, h0, l0); split_bf16(d1, h1, l1);
                split_bf16(d2, h2, l2); split_bf16(d3, h3, l3);
                __nv_bfloat162 ph0; ph0.x = h0; ph0.y = h1;
                __nv_bfloat162 pl0; pl0.x = l0; pl0.y = l1;
                __nv_bfloat162 ph1; ph1.x = h2; ph1.y = h3;
                __nv_bfloat162 pl1; pl1.x = l2; pl1.y = l3;
                *(__nv_bfloat162*)(SH + rowA * ldc + col) = ph0;
                *(__nv_bfloat162*)(SL + rowA * ldc + col) = pl0;
                *(__nv_bfloat162*)(SH + rowB * ldc + col) = ph1;
                *(__nv_bfloat162*)(SL + rowB * ldc + col) = pl1;
            }
        }
    }
}

// ---------------------------------------------------------------------------
extern "C" void kernel_launch(void* const* d_in, const int* in_sizes, int n_in,
                              void* d_out, int out_size)
{
    (void)in_sizes; (void)n_in;
    const float* x      = (const float*)d_in[0];
    const float* qkv_w  = (const float*)d_in[1];
    const float* q2_w   = (const float*)d_in[2];
    const float* kv2_w  = (const float*)d_in[3];
    const float* proj_w = (const float*)d_in[4];
    const float* proj_b = (const float*)d_in[5];
    const float* ln1_g  = (const float*)d_in[6];
    const float* ln1_b  = (const float*)d_in[7];
    const float* ln2_g  = (const float*)d_in[8];
    const float* ln2_b  = (const float*)d_in[9];
    const float* fc1_w  = (const float*)d_in[10];
    const float* fc1_b  = (const float*)d_in[11];
    const float* fc2_w  = (const float*)d_in[12];
    const float* fc2_b  = (const float*)d_in[13];
    float* out = (float*)d_out;

    cudaFuncSetAttribute(mma_lg_kernel,
                         cudaFuncAttributeMaxDynamicSharedMemorySize, MMA_SMEM_BYTES);
    cudaFuncSetAttribute(mma_o_kernel,
                         cudaFuncAttributeMaxDynamicSharedMemorySize, MMAO_SMEM_BYTES);
    cudaFuncSetAttribute(mma_nt_kernel,
                         cudaFuncAttributeMaxDynamicSharedMemorySize, MMA_SMEM_BYTES);
    cudaFuncSetAttribute(mma_nt64_kernel,
                         cudaFuncAttributeMaxDynamicSharedMemorySize, MMA_SMEM_BYTES);

    // all six weight transpose-splits, one launch
    cvt_weights_kernel<<<540, 256>>>(qkv_w, kv2_w, q2_w, proj_w, fc1_w, fc2_w);

    pool_kernel<<<1536, 256>>>(x);
    // LN1 -> xn bf16 splits (XD region)
    ln_kernel<<<1024, 384>>>(OFF_TOK, ln1_g, ln1_b, OFF_XD, OFF_XD + 196608);

    // qkv mma: fp32 -> QKV, bf16 splits -> LG region
    mma_nt_kernel<<<dim3(9, 8), 256, MMA_SMEM_BYTES>>>(
        OFF_XD, OFF_XD + 196608, OFF_QKVWT, OFF_QKVWT + 221184,
        nullptr, 0, OFF_QKV, OFF_LG, OFF_LG + 589824, 384, 1152, 8);

    // qk[h] = q_h @ k_h^T  (6 heads in z)
    mma_nt64_kernel<<<dim3(8, 8, 6), 256, MMA_SMEM_BYTES>>>(
        OFF_LG, OFF_LG + 589824, 1152, 0, 64,
        OFF_LG, OFF_LG + 589824, 1152, 384, 64,
        OFF_QK, 1024, 1048576);

    // VW[h'] = v_h' @ kv2_w[h' slice]  (6 heads in z)
    mma_nt64_kernel<<<dim3(6, 8, 6), 256, MMA_SMEM_BYTES>>>(
        OFF_LG, OFF_LG + 589824, 1152, 768, 64,
        OFF_KV2WT, OFF_KV2WT + 147456, 384, 0, 64,
        OFF_VW, 768, 786432);

    ta_kernel<<<6144, 256>>>();
    // x_diag -> bf16 splits (XD region, xn splits now dead)
    xdiag_kernel<<<1024, 384>>>();

    // q2 = x_diag @ (SCALE*q2_w): splits only -> XN region
    mma_nt_kernel<<<dim3(3, 8), 256, MMA_SMEM_BYTES>>>(
        OFF_XD, OFF_XD + 196608, OFF_Q2WT, OFF_Q2WT + 73728,
        nullptr, 0, 0, OFF_XN, OFF_XN + 196608, 384, 384, 8 | 16);

    // VWk splits -> QKV/MLP regions; VWv transposed splits
    cvt_split_kernel<<<9216, 256>>>(OFF_VW, 768, 384, OFF_QKV, OFF_MLP);
    cvt_vwt_kernel<<<dim3(96, 6), 256>>>();

    int wout = (out_size >= 3145728) ? 1 : 0;

    // stage 2 in 3 groups of 2 heads
    for (int g = 0; g < 3; g++) {
        mma_lg_kernel<<<dim3(48, 8, 2), 256, MMA_SMEM_BYTES>>>(g);
        middle_kernel<<<dim3(1024, 2), 256>>>(g, out + 1572864, wout);
        mma_o_kernel<<<dim3(12, 8, 2), 256, MMAO_SMEM_BYTES>>>(g);
        oreduce_kernel<<<512, 256>>>(g);
    }

    // h1 = tok + (o @ proj_w + proj_b)
    mma_nt_kernel<<<dim3(3, 8), 256, MMA_SMEM_BYTES>>>(
        OFF_O, OFF_O + 196608, OFF_PROJWT, OFF_PROJWT + 73728,
        proj_b, OFF_TOK, OFF_H1, 0, 0, 384, 384, 1 | 2);

    // LN2 -> hn bf16 splits (XD region, xd splits now dead)
    ln_kernel<<<1024, 384>>>(OFF_H1, ln2_g, ln2_b, OFF_XD, OFF_XD + 196608);

    // fc1: bias+gelu, splits only -> QK region
    mma_nt_kernel<<<dim3(12, 8), 256, MMA_SMEM_BYTES>>>(
        OFF_XD, OFF_XD + 196608, OFF_FC1WT, OFF_FC1WT + 294912,
        fc1_b, 0, 0, OFF_QK + 589824, OFF_QK + 1376256, 384, 1536, 1 | 4 | 8 | 16);

    // fc2: bias + residual(H1) -> H2 fp32
    mma_nt_kernel<<<dim3(3, 8), 256, MMA_SMEM_BYTES>>>(
        OFF_QK + 589824, OFF_QK + 1376256, OFF_FC2WT, OFF_FC2WT + 294912,
        fc2_b, OFF_H1, OFF_H2, 0, 0, 1536, 384, 1 | 2);

    upsample_kernel<<<1536, 256>>>(out, out_size);
}

// round 16
// speedup vs baseline: 1.4130x; 1.0192x over previous
#include <cuda_runtime.h>
#include <cuda_bf16.h>
#include <cstdint>
#include <math.h>

// ---------------------------------------------------------------------------
// DeformationTrajectoryAttentionBlock — all big GEMMs on mma.sync bf16x3;
// fused split epilogues; batched weight cvt; cp.async double-buffered mma.
// B=1, F=4, H=6, D=384, G=16, S=256, N=1024, HD=64, IMG=32, MLP_HID=1536
// ---------------------------------------------------------------------------

#define SCALE 0.125f
#define LN_EPS 1e-5f
typedef unsigned long long ull;

#define OFF_TOK    0LL          // 1024*384 fp32
#define OFF_XN     393216LL     // q2 splits: hi bf16 @ +0, lo @ +196608
#define OFF_QKV    786432LL     // 1024*1152 fp32 ; later VWk-hi bf16
#define OFF_VW     1966080LL    // 6*1024*768 (6144 x 768) fp32
#define OFF_QK     6684672LL    // qk fp32 / Lg[hg=0]/AB ; later mlp splits
#define OFF_TA     12976128LL   // 1024*256*24
#define OFF_XD     19267584LL   // xn splits -> xd splits -> hn splits (bf16 hi/lo)
#define OFF_Q2     19660800LL   // (unused fp32 slot)
#define OFF_LG     20054016LL   // qkv splits bf16 -> Lg[hg=1]/AB
#define LG_STRIDE  13369344LL   // OFF_LG - OFF_QK
#define OFF_OPART  26345472LL   // 24 * 1024*64
#define OFF_O      27918336LL   // o splits: hi bf16 @ +0, lo @ +196608
#define OFF_H1     28311552LL
#define OFF_HN     28704768LL   // (unused fp32 slot)
#define OFF_MLP    29097984LL   // VWk-lo bf16
#define OFF_H2     30670848LL
#define OFF_VWTH   31064064LL   // VWv^T hi bf16 [6][64][6144]
#define OFF_VWTL   32243712LL   // VWv^T lo bf16
#define OFF_QKVWT  33423360LL   // qkv_w^T hi/lo (hi +0, lo +221184)
#define OFF_KV2WT  33865728LL   // kv2_w^T hi/lo (hi +0, lo +147456)
#define OFF_Q2WT   34160640LL   // SCALE*q2_w^T hi/lo (hi +0, lo +73728)
#define OFF_PROJWT 34308096LL   // proj_w^T hi/lo (hi +0, lo +73728)
#define OFF_FC1WT  34455552LL   // fc1_w^T hi/lo (hi +0, lo +294912)
#define OFF_FC2WT  35045376LL   // fc2_w^T hi/lo (hi +0, lo +294912)
#define SCRATCH_FLOATS 35635200LL

static __device__ float g_scratch[SCRATCH_FLOATS];

__device__ __forceinline__ uint32_t smem_to_u32(const void* smem_ptr)
{
    uint32_t addr;
    asm("{ .reg .u64 tmp; cvta.to.shared.u64 tmp, %1; cvt.u32.u64 %0, tmp; }"
        : "=r"(addr) : "l"(smem_ptr));
    return addr;
}
__device__ __forceinline__ void split_bf16(float v, __nv_bfloat16& hi, __nv_bfloat16& lo)
{
    hi = __float2bfloat16(v);
    lo = __float2bfloat16(v - __bfloat162float(hi));
}
__device__ __forceinline__ void cp_async16(uint32_t saddr, const void* gptr)
{
    asm volatile("cp.async.ca.shared.global [%0], [%1], 16;"
                 :: "r"(saddr), "l"(gptr));
}
#define CP_COMMIT() asm volatile("cp.async.commit_group;" ::: "memory")
#define CP_WAIT0()  asm volatile("cp.async.wait_group 0;" ::: "memory")
#define CP_WAIT1()  asm volatile("cp.async.wait_group 1;" ::: "memory")

// ---------------------------------------------------------------------------
__global__ void pool_kernel(const float* __restrict__ x)
{
    float* tok = g_scratch + OFF_TOK;
    int fd = blockIdx.x;
    int f = fd / 384;
    const float* xp = x + (size_t)fd * 1024;
    int t = threadIdx.x;
    int gy = t >> 4, gx = t & 15;
    const float* p = xp + (gy * 2) * 32 + gx * 2;
    float m = fmaxf(fmaxf(p[0], p[1]), fmaxf(p[32], p[33]));
    tok[(size_t)(f * 256 + t) * 384 + (fd % 384)] = m;
}

// ---------------------------------------------------------------------------
__global__ void ln_kernel(long long inOff, const float* __restrict__ g,
                          const float* __restrict__ b,
                          long long hiOff, long long loOff)
{
    const float* in = g_scratch + inOff;
    int n = blockIdx.x, t = threadIdx.x;
    float x = in[(size_t)n * 384 + t];
    __shared__ float red[12];
    __shared__ float mv[2];
    float s = x;
    #pragma unroll
    for (int o = 16; o; o >>= 1) s += __shfl_xor_sync(0xffffffffu, s, o);
    if ((t & 31) == 0) red[t >> 5] = s;
    __syncthreads();
    if (t == 0) { float tt = 0.f; for (int i = 0; i < 12; i++) tt += red[i]; mv[0] = tt * (1.0f / 384.0f); }
    __syncthreads();
    float mean = mv[0];
    float d = x - mean;
    s = d * d;
    #pragma unroll
    for (int o = 16; o; o >>= 1) s += __shfl_xor_sync(0xffffffffu, s, o);
    if ((t & 31) == 0) red[t >> 5] = s;
    __syncthreads();
    if (t == 0) { float tt = 0.f; for (int i = 0; i < 12; i++) tt += red[i]; mv[1] = rsqrtf(tt * (1.0f / 384.0f) + LN_EPS); }
    __syncthreads();
    float v = d * mv[1] * g[t] + b[t];
    __nv_bfloat16 hi, lo;
    split_bf16(v, hi, lo);
    ((__nv_bfloat16*)(g_scratch + hiOff))[(size_t)n * 384 + t] = hi;
    ((__nv_bfloat16*)(g_scratch + loOff))[(size_t)n * 384 + t] = lo;
}

// ---------------------------------------------------------------------------
__global__ void ta_kernel()
{
    const float* qk = g_scratch + OFF_QK;
    float* ta = g_scratch + OFF_TA;
    int b = blockIdx.x;
    int h = b >> 10, n = b & 1023;
    int s = threadIdx.x;
    const float* p = qk + ((size_t)b << 10) + s;
    float x0 = SCALE * p[0], x1 = SCALE * p[256], x2 = SCALE * p[512], x3 = SCALE * p[768];
    float m = fmaxf(fmaxf(x0, x1), fmaxf(x2, x3));
    float e0 = expf(x0 - m), e1 = expf(x1 - m), e2 = expf(x2 - m), e3 = expf(x3 - m);
    float inv = 1.0f / (e0 + e1 + e2 + e3);
    float* o = ta + ((size_t)(n * 256 + s)) * 24 + h * 4;
    o[0] = e0 * inv; o[1] = e1 * inv; o[2] = e2 * inv; o[3] = e3 * inv;
}

// ---------------------------------------------------------------------------
__global__ void xdiag_kernel()
{
    const float* ta = g_scratch + OFF_TA;
    const float* qkv = g_scratch + OFF_QKV;
    int n = blockIdx.x, c = threadIdx.x;
    int h = c >> 6;
    int s = n & 255;
    const float* tp = ta + ((size_t)(n * 256 + s)) * 24 + h * 4;
    float acc = 0.f;
    #pragma unroll
    for (int f = 0; f < 4; f++)
        acc += tp[f] * qkv[(size_t)(f * 256 + s) * 1152 + 768 + c];
    __nv_bfloat16 hi, lo;
    split_bf16(acc, hi, lo);
    ((__nv_bfloat16*)(g_scratch + OFF_XD))[(size_t)n * 384 + c] = hi;
    ((__nv_bfloat16*)(g_scratch + OFF_XD + 196608))[(size_t)n * 384 + c] = lo;
}

// ---------------------------------------------------------------------------
__global__ void __launch_bounds__(256) middle_kernel(int g, float* __restrict__ out_attn,
                                                     int write_out)
{
    int n = blockIdx.x;
    int hg = blockIdx.y;
    int s = threadIdx.x;
    __shared__ __align__(16) float sta[256][24];
    __shared__ float red[8];
    __shared__ float mv[2];

    const float4* tap = (const float4*)(g_scratch + OFF_TA + (size_t)n * 6144);
    float4* stp = (float4*)&sta[0][0];
    for (int idx = s; idx < 1536; idx += 256)
        stp[idx] = tap[idx];
    __syncthreads();

    float* lg = g_scratch + OFF_QK + (long long)hg * LG_STRIDE + (size_t)n * 6144;
    float logit = 0.f;
    #pragma unroll
    for (int j = 0; j < 24; j++)
        logit += sta[s][j] * lg[j * 256 + s];

    float m = logit;
    #pragma unroll
    for (int o = 16; o; o >>= 1) m = fmaxf(m, __shfl_xor_sync(0xffffffffu, m, o));
    if ((s & 31) == 0) red[s >> 5] = m;
    __syncthreads();
    if (s == 0) { float t = red[0]; for (int i = 1; i < 8; i++) t = fmaxf(t, red[i]); mv[0] = t; }
    __syncthreads();
    float e = expf(logit - mv[0]);
    float sum = e;
    #pragma unroll
    for (int o = 16; o; o >>= 1) sum += __shfl_xor_sync(0xffffffffu, sum, o);
    if ((s & 31) == 0) red[s >> 5] = sum;
    __syncthreads();
    if (s == 0) { float t = 0.f; for (int i = 0; i < 8; i++) t += red[i]; mv[1] = 1.0f / t; }
    __syncthreads();
    float sa = e * mv[1];
    if (write_out) out_attn[((size_t)(g * 2 + hg) * 1024 + n) * 256 + s] = sa;
    __nv_bfloat16* ab = (__nv_bfloat16*)lg;
    #pragma unroll
    for (int j = 0; j < 24; j++) {
        float v = sa * sta[s][j];
        __nv_bfloat16 hi, lo;
        split_bf16(v, hi, lo);
        ab[j * 256 + s] = hi;
        ab[6144 + j * 256 + s] = lo;
    }
}

// ---------------------------------------------------------------------------
__global__ void oreduce_kernel(int g)
{
    const float* opart = g_scratch + OFF_OPART;
    int i = blockIdx.x * 256 + threadIdx.x;       // < 131072
    int hg = i >> 16;
    int r = i & 65535;
    float sum = 0.f;
    #pragma unroll
    for (int zk = 0; zk < 12; zk++)
        sum += opart[(size_t)(zk * 2 + hg) * 65536 + r];
    __nv_bfloat16 hi, lo;
    split_bf16(sum, hi, lo);
    size_t idx = (size_t)(r >> 6) * 384 + (g * 2 + hg) * 64 + (r & 63);
    ((__nv_bfloat16*)(g_scratch + OFF_O))[idx] = hi;
    ((__nv_bfloat16*)(g_scratch + OFF_O + 196608))[idx] = lo;
}

// ---------------------------------------------------------------------------
__global__ void upsample_kernel(float* __restrict__ out, int out_size)
{
    const float* h2 = g_scratch + OFF_H2;
    int fd = blockIdx.x;
    int f = fd / 384, d = fd % 384;
    __shared__ float ch[256];
    int t = threadIdx.x;
    ch[t] = h2[(size_t)(f * 256 + t) * 384 + d];
    __syncthreads();
    #pragma unroll
    for (int p = 0; p < 4; p++) {
        int o = t + p * 256;
        int oy = o >> 5, ox = o & 31;
        float fy = 0.5f * oy - 0.25f;
        int iy0 = (int)floorf(fy);
        float wy = fy - (float)iy0;
        int iy0c = max(iy0, 0), iy1c = min(iy0 + 1, 15);
        float fx = 0.5f * ox - 0.25f;
        int ix0 = (int)floorf(fx);
        float wx = fx - (float)ix0;
        int ix0c = max(ix0, 0), ix1c = min(ix0 + 1, 15);
        float v00 = ch[iy0c * 16 + ix0c], v01 = ch[iy0c * 16 + ix1c];
        float v10 = ch[iy1c * 16 + ix0c], v11 = ch[iy1c * 16 + ix1c];
        float v = (1.f - wy) * ((1.f - wx) * v00 + wx * v01)
                + wy * ((1.f - wx) * v10 + wx * v11);
        long long oi = (long long)fd * 1024 + o;
        if (oi < (long long)out_size) out[oi] = v;
    }
}

// ---------------------------------------------------------------------------
__global__ void cvt_split_kernel(long long inOff, int inStride, int width,
                                 long long hiOff, long long loOff)
{
    long long i = (long long)blockIdx.x * 256 + threadIdx.x;
    int row = (int)(i / width);
    int col = (int)(i % width);
    float v = g_scratch[inOff + (long long)row * inStride + col];
    __nv_bfloat16 h, l;
    split_bf16(v, h, l);
    ((__nv_bfloat16*)(g_scratch + hiOff))[i] = h;
    ((__nv_bfloat16*)(g_scratch + loOff))[i] = l;
}

// ---------------------------------------------------------------------------
__global__ void cvt_weights_kernel(const float* __restrict__ qkv_w,
                                   const float* __restrict__ kv2_w,
                                   const float* __restrict__ q2_w,
                                   const float* __restrict__ proj_w,
                                   const float* __restrict__ fc1_w,
                                   const float* __restrict__ fc2_w)
{
    __shared__ float tile[64][65];
    int t = blockIdx.x;
    const float* W; int Kd, Nd; long long hiOff, loOff; float scale = 1.0f;
    if (t < 108)      {           W = qkv_w;  Kd = 384;  Nd = 1152;
                        hiOff = OFF_QKVWT;  loOff = OFF_QKVWT + 221184; }
    else if (t < 180) { t -= 108; W = kv2_w;  Kd = 384;  Nd = 768;
                        hiOff = OFF_KV2WT;  loOff = OFF_KV2WT + 147456; }
    else if (t < 216) { t -= 180; W = q2_w;   Kd = 384;  Nd = 384;
                        hiOff = OFF_Q2WT;   loOff = OFF_Q2WT + 73728;  scale = SCALE; }
    else if (t < 252) { t -= 216; W = proj_w; Kd = 384;  Nd = 384;
                        hiOff = OFF_PROJWT; loOff = OFF_PROJWT + 73728; }
    else if (t < 396) { t -= 252; W = fc1_w;  Kd = 384;  Nd = 1536;
                        hiOff = OFF_FC1WT;  loOff = OFF_FC1WT + 294912; }
    else              { t -= 396; W = fc2_w;  Kd = 1536; Nd = 384;
                        hiOff = OFF_FC2WT;  loOff = OFF_FC2WT + 294912; }
    int ktiles = Kd >> 6;
    int kt = (t % ktiles) * 64;
    int nt = (t / ktiles) * 64;
    int tid = threadIdx.x;
    for (int i = tid; i < 4096; i += 256) {
        int k = i >> 6, n = i & 63;
        tile[k][n] = W[(size_t)(kt + k) * Nd + nt + n] * scale;
    }
    __syncthreads();
    __nv_bfloat16* vh = (__nv_bfloat16*)(g_scratch + hiOff);
    __nv_bfloat16* vl = (__nv_bfloat16*)(g_scratch + loOff);
    for (int i = tid; i < 4096; i += 256) {
        int n = i >> 6, k = i & 63;
        float v = tile[k][n];
        __nv_bfloat16 hi, lo;
        split_bf16(v, hi, lo);
        size_t idx = (size_t)(nt + n) * Kd + kt + k;
        vh[idx] = hi;
        vl[idx] = lo;
    }
}

// ---------------------------------------------------------------------------
__global__ void cvt_vwt_kernel()
{
    __shared__ float tile[64][65];
    int kt = blockIdx.x * 64;
    int h = blockIdx.y;
    int tid = threadIdx.x;
    for (int i = tid; i < 4096; i += 256) {
        int k = i >> 6, n = i & 63;
        tile[k][n] = g_scratch[OFF_VW + (size_t)(kt + k) * 768 + 384 + h * 64 + n];
    }
    __syncthreads();
    __nv_bfloat16* vh = (__nv_bfloat16*)(g_scratch + OFF_VWTH);
    __nv_bfloat16* vl = (__nv_bfloat16*)(g_scratch + OFF_VWTL);
    for (int i = tid; i < 4096; i += 256) {
        int n = i >> 6, k = i & 63;
        float v = tile[k][n];
        __nv_bfloat16 hi, lo;
        split_bf16(v, hi, lo);
        size_t idx = ((size_t)h * 64 + n) * 6144 + kt + k;
        vh[idx] = hi;
        vl[idx] = lo;
    }
}

// ===========================================================================
// mma.sync helpers
// ===========================================================================
__device__ __forceinline__ void ldsm_x4(uint32_t* r, uint32_t addr)
{
    asm volatile("ldmatrix.sync.aligned.m8n8.x4.shared.b16 {%0,%1,%2,%3}, [%4];"
                 : "=r"(r[0]), "=r"(r[1]), "=r"(r[2]), "=r"(r[3]) : "r"(addr));
}
__device__ __forceinline__ void mma_bf16(float* d, const uint32_t* a, const uint32_t* b)
{
    asm volatile(
        "mma.sync.aligned.m16n8k16.row.col.f32.bf16.bf16.f32 "
        "{%0,%1,%2,%3}, {%4,%5,%6,%7}, {%8,%9}, {%0,%1,%2,%3};"
        : "+f"(d[0]), "+f"(d[1]), "+f"(d[2]), "+f"(d[3])
        : "r"(a[0]), "r"(a[1]), "r"(a[2]), "r"(a[3]), "r"(b[0]), "r"(b[1]));
}

#define MMA_SMEM_BYTES 73728
#define APAD 72

// ===========================================================================
// mma_lg (R10-proven): Lg tile (128 x 128) = q2_h @ VWk_h^T, K=64, x3 splits.
// ===========================================================================
__global__ void __launch_bounds__(256) mma_lg_kernel(int g)
{
    extern __shared__ __align__(16) char dsm[];
    __nv_bfloat16* Ah = (__nv_bfloat16*)dsm;
    __nv_bfloat16* Al = Ah + 128 * APAD;
    __nv_bfloat16* Bh = Al + 128 * APAD;
    __nv_bfloat16* Bl = Bh + 128 * APAD;

    int tid = threadIdx.x;
    int wid = tid >> 5, lid = tid & 31;
    int bn = blockIdx.x * 128;
    int bm = blockIdx.y * 128;
    int hg = blockIdx.z;
    int h = g * 2 + hg;

    const __nv_bfloat16* q2h = (const __nv_bfloat16*)(g_scratch + OFF_XN);
    const __nv_bfloat16* q2l = (const __nv_bfloat16*)(g_scratch + OFF_XN + 196608);
    const __nv_bfloat16* vwh = (const __nv_bfloat16*)(g_scratch + OFF_QKV);
    const __nv_bfloat16* vwl = (const __nv_bfloat16*)(g_scratch + OFF_MLP);

    {
        int r = tid >> 1, half = tid & 1;
        const uint4* sah = (const uint4*)(q2h + (size_t)(bm + r) * 384 + h * 64 + half * 32);
        const uint4* sal = (const uint4*)(q2l + (size_t)(bm + r) * 384 + h * 64 + half * 32);
        uint4* dah = (uint4*)(Ah + r * APAD + half * 32);
        uint4* dal = (uint4*)(Al + r * APAD + half * 32);
        #pragma unroll
        for (int i = 0; i < 4; i++) { dah[i] = sah[i]; dal[i] = sal[i]; }
        const uint4* sbh = (const uint4*)(vwh + (size_t)(bn + r) * 384 + h * 64 + half * 32);
        const uint4* sbl = (const uint4*)(vwl + (size_t)(bn + r) * 384 + h * 64 + half * 32);
        uint4* dbh = (uint4*)(Bh + r * APAD + half * 32);
        uint4* dbl = (uint4*)(Bl + r * APAD + half * 32);
        #pragma unroll
        for (int i = 0; i < 4; i++) { dbh[i] = sbh[i]; dbl[i] = sbl[i]; }
    }
    __syncthreads();

    int warp_m = wid & 3;
    int warp_n = wid >> 2;
    int m_base = warp_m * 32;
    int n_base = warp_n * 64;

    float acc[16][4];
    #pragma unroll
    for (int i = 0; i < 16; i++)
        #pragma unroll
        for (int j = 0; j < 4; j++) acc[i][j] = 0.f;

    int a_row = lid & 15;
    int a_colb = (lid >> 4) * 8;
    int b_row = (lid >> 4) * 8 + (lid & 7);
    int b_colb = ((lid >> 3) & 1) * 8;

    #pragma unroll
    for (int sp = 0; sp < 3; sp++) {
        const __nv_bfloat16* As = (sp == 2) ? Al : Ah;
        const __nv_bfloat16* Bs = (sp == 1) ? Bl : Bh;
        #pragma unroll
        for (int ks = 0; ks < 4; ks++) {
            int k0 = ks * 16;
            uint32_t afr[2][4];
            #pragma unroll
            for (int am = 0; am < 2; am++) {
                uint32_t addr = smem_to_u32(As + (size_t)(m_base + am * 16 + a_row) * APAD
                                            + k0 + a_colb);
                ldsm_x4(afr[am], addr);
            }
            uint32_t bfr[8][2];
            #pragma unroll
            for (int p = 0; p < 4; p++) {
                uint32_t r4[4];
                uint32_t addr = smem_to_u32(Bs + (size_t)(n_base + p * 16 + b_row) * APAD
                                            + k0 + b_colb);
                ldsm_x4(r4, addr);
                bfr[2 * p + 0][0] = r4[0]; bfr[2 * p + 0][1] = r4[1];
                bfr[2 * p + 1][0] = r4[2]; bfr[2 * p + 1][1] = r4[3];
            }
            #pragma unroll
            for (int am = 0; am < 2; am++)
                #pragma unroll
                for (int an = 0; an < 8; an++)
                    mma_bf16(acc[am * 8 + an], afr[am], bfr[an]);
        }
    }

    float* lg = g_scratch + OFF_QK + (long long)hg * LG_STRIDE;
    int gid = lid >> 2, tig = lid & 3;
    #pragma unroll
    for (int am = 0; am < 2; am++) {
        #pragma unroll
        for (int an = 0; an < 8; an++) {
            const float* d = acc[am * 8 + an];
            long long row0 = bm + m_base + am * 16 + gid;
            long long col = bn + n_base + an * 8 + tig * 2;
            *(float2*)(lg + row0 * 6144 + col) = make_float2(d[0], d[1]);
            *(float2*)(lg + (row0 + 8) * 6144 + col) = make_float2(d[2], d[3]);
        }
    }
}

// ===========================================================================
// mma_nt64 (R14-proven): K=64 NT mma with strided 64-col slices, x3 splits.
// ===========================================================================
__global__ void __launch_bounds__(256) mma_nt64_kernel(
    long long aHiOff, long long aLoOff, int lda, int aCol0, int aColStep,
    long long bHiOff, long long bLoOff, int ldb, int bCol0, int bColStep,
    long long cOff, int ldc, long long cZStride)
{
    extern __shared__ __align__(16) char dsm[];
    __nv_bfloat16* Ah = (__nv_bfloat16*)dsm;
    __nv_bfloat16* Al = Ah + 128 * APAD;
    __nv_bfloat16* Bh = Al + 128 * APAD;
    __nv_bfloat16* Bl = Bh + 128 * APAD;

    int tid = threadIdx.x;
    int wid = tid >> 5, lid = tid & 31;
    int bn = blockIdx.x * 128;
    int bm = blockIdx.y * 128;
    int z = blockIdx.z;

    const __nv_bfloat16* ah = (const __nv_bfloat16*)(g_scratch + aHiOff)
                              + aCol0 + z * aColStep;
    const __nv_bfloat16* al = (const __nv_bfloat16*)(g_scratch + aLoOff)
                              + aCol0 + z * aColStep;
    const __nv_bfloat16* bh = (const __nv_bfloat16*)(g_scratch + bHiOff)
                              + bCol0 + z * bColStep;
    const __nv_bfloat16* bl = (const __nv_bfloat16*)(g_scratch + bLoOff)
                              + bCol0 + z * bColStep;

    {
        int r = tid >> 1, half = tid & 1;
        const uint4* sah = (const uint4*)(ah + (size_t)(bm + r) * lda + half * 32);
        const uint4* sal = (const uint4*)(al + (size_t)(bm + r) * lda + half * 32);
        uint4* dah = (uint4*)(Ah + r * APAD + half * 32);
        uint4* dal = (uint4*)(Al + r * APAD + half * 32);
        #pragma unroll
        for (int i = 0; i < 4; i++) { dah[i] = sah[i]; dal[i] = sal[i]; }
        const uint4* sbh = (const uint4*)(bh + (size_t)(bn + r) * ldb + half * 32);
        const uint4* sbl = (const uint4*)(bl + (size_t)(bn + r) * ldb + half * 32);
        uint4* dbh = (uint4*)(Bh + r * APAD + half * 32);
        uint4* dbl = (uint4*)(Bl + r * APAD + half * 32);
        #pragma unroll
        for (int i = 0; i < 4; i++) { dbh[i] = sbh[i]; dbl[i] = sbl[i]; }
    }
    __syncthreads();

    int warp_m = wid & 3;
    int warp_n = wid >> 2;
    int m_base = warp_m * 32;
    int n_base = warp_n * 64;

    float acc[16][4];
    #pragma unroll
    for (int i = 0; i < 16; i++)
        #pragma unroll
        for (int j = 0; j < 4; j++) acc[i][j] = 0.f;

    int a_row = lid & 15;
    int a_colb = (lid >> 4) * 8;
    int b_row = (lid >> 4) * 8 + (lid & 7);
    int b_colb = ((lid >> 3) & 1) * 8;

    #pragma unroll
    for (int sp = 0; sp < 3; sp++) {
        const __nv_bfloat16* As = (sp == 2) ? Al : Ah;
        const __nv_bfloat16* Bs = (sp == 1) ? Bl : Bh;
        #pragma unroll
        for (int ks = 0; ks < 4; ks++) {
            int k0 = ks * 16;
            uint32_t afr[2][4];
            #pragma unroll
            for (int am = 0; am < 2; am++) {
                uint32_t addr = smem_to_u32(As + (size_t)(m_base + am * 16 + a_row) * APAD
                                            + k0 + a_colb);
                ldsm_x4(afr[am], addr);
            }
            uint32_t bfr[8][2];
            #pragma unroll
            for (int p = 0; p < 4; p++) {
                uint32_t r4[4];
                uint32_t addr = smem_to_u32(Bs + (size_t)(n_base + p * 16 + b_row) * APAD
                                            + k0 + b_colb);
                ldsm_x4(r4, addr);
                bfr[2 * p + 0][0] = r4[0]; bfr[2 * p + 0][1] = r4[1];
                bfr[2 * p + 1][0] = r4[2]; bfr[2 * p + 1][1] = r4[3];
            }
            #pragma unroll
            for (int am = 0; am < 2; am++)
                #pragma unroll
                for (int an = 0; an < 8; an++)
                    mma_bf16(acc[am * 8 + an], afr[am], bfr[an]);
        }
    }

    float* C = g_scratch + cOff + (long long)z * cZStride;
    int gid = lid >> 2, tig = lid & 3;
    #pragma unroll
    for (int am = 0; am < 2; am++) {
        #pragma unroll
        for (int an = 0; an < 8; an++) {
            const float* d = acc[am * 8 + an];
            long long row0 = bm + m_base + am * 16 + gid;
            long long col = bn + n_base + an * 8 + tig * 2;
            *(float2*)(C + row0 * ldc + col) = make_float2(d[0], d[1]);
            *(float2*)(C + (row0 + 8) * ldc + col) = make_float2(d[2], d[3]);
        }
    }
}

// ===========================================================================
// mma_o: o partials = AB(bf16 hi/lo) @ VWvT^T. cp.async double-buffered.
// smem: 2 buffers x (Ah 128x72, Al 128x72, Bh 64x72, Bl 64x72) = 110592 B.
// ===========================================================================
#define MMAO_SMEM_BYTES 110592
#define O_BUF 27648   // bf16 per buffer

__global__ void __launch_bounds__(256) mma_o_kernel(int g)
{
    extern __shared__ __align__(16) char dsm[];
    __nv_bfloat16* sb = (__nv_bfloat16*)dsm;

    int tid = threadIdx.x;
    int wid = tid >> 5, lid = tid & 31;
    int zk = blockIdx.x;
    int bm = blockIdx.y * 128;
    int hg = blockIdx.z;
    int h = g * 2 + hg;

    const __nv_bfloat16* ab = (const __nv_bfloat16*)(g_scratch + OFF_QK
                                                     + (long long)hg * LG_STRIDE);
    const __nv_bfloat16* vh = (const __nv_bfloat16*)(g_scratch + OFF_VWTH)
                              + (size_t)h * 64 * 6144;
    const __nv_bfloat16* vl = (const __nv_bfloat16*)(g_scratch + OFF_VWTL)
                              + (size_t)h * 64 * 6144;

    int warp_m = wid & 3;
    int warp_n = wid >> 2;
    int m_base = warp_m * 32;
    int n_base = warp_n * 32;

    float acc[8][4];
    #pragma unroll
    for (int i = 0; i < 8; i++)
        #pragma unroll
        for (int j = 0; j < 4; j++) acc[i][j] = 0.f;

    int a_row = lid & 15;
    int a_colb = (lid >> 4) * 8;
    int b_row = (lid >> 4) * 8 + (lid & 7);
    int b_colb = ((lid >> 3) & 1) * 8;

    int r2 = tid >> 1, half = tid & 1;

#define O_LOAD_CHUNK(buf, koff) do { \
    __nv_bfloat16* base_ = sb + (buf) * O_BUF; \
    uint32_t s0_ = smem_to_u32(base_ + r2 * APAD + half * 32); \
    uint32_t s1_ = smem_to_u32(base_ + 9216 + r2 * APAD + half * 32); \
    const __nv_bfloat16* g0_ = ab + (size_t)(bm + r2) * 12288 + (koff) + half * 32; \
    const __nv_bfloat16* g1_ = ab + (size_t)(bm + r2) * 12288 + 6144 + (koff) + half * 32; \
    _Pragma("unroll") \
    for (int i_ = 0; i_ < 4; i_++) { \
        cp_async16(s0_ + i_ * 16, g0_ + i_ * 8); \
        cp_async16(s1_ + i_ * 16, g1_ + i_ * 8); \
    } \
    if (tid < 128) { \
        uint32_t s2_ = smem_to_u32(base_ + 18432 + r2 * APAD + half * 32); \
        uint32_t s3_ = smem_to_u32(base_ + 23040 + r2 * APAD + half * 32); \
        const __nv_bfloat16* g2_ = vh + (size_t)r2 * 6144 + (koff) + half * 32; \
        const __nv_bfloat16* g3_ = vl + (size_t)r2 * 6144 + (koff) + half * 32; \
        _Pragma("unroll") \
        for (int i_ = 0; i_ < 4; i_++) { \
            cp_async16(s2_ + i_ * 16, g2_ + i_ * 8); \
            cp_async16(s3_ + i_ * 16, g3_ + i_ * 8); \
        } \
    } \
} while (0)

    O_LOAD_CHUNK(0, zk * 512);
    CP_COMMIT();

    for (int ch = 0; ch < 8; ch++) {
        int cur = ch & 1;
        if (ch + 1 < 8) {
            O_LOAD_CHUNK(1 - cur, zk * 512 + (ch + 1) * 64);
            CP_COMMIT();
            CP_WAIT1();
        } else {
            CP_WAIT0();
        }
        __syncthreads();

        const __nv_bfloat16* Ahc = sb + cur * O_BUF;
        const __nv_bfloat16* Alc = Ahc + 9216;
        const __nv_bfloat16* Bhc = Ahc + 18432;
        const __nv_bfloat16* Blc = Ahc + 23040;

        #pragma unroll
        for (int sp = 0; sp < 3; sp++) {
            const __nv_bfloat16* As = (sp == 2) ? Alc : Ahc;
            const __nv_bfloat16* Bs = (sp == 1) ? Blc : Bhc;
            #pragma unroll
            for (int ks = 0; ks < 4; ks++) {
                int k0 = ks * 16;
                uint32_t afr[2][4];
                #pragma unroll
                for (int am = 0; am < 2; am++) {
                    uint32_t addr = smem_to_u32(As + (size_t)(m_base + am * 16 + a_row) * APAD
                                                + k0 + a_colb);
                    ldsm_x4(afr[am], addr);
                }
                uint32_t bfr[4][2];
                #pragma unroll
                for (int p = 0; p < 2; p++) {
                    uint32_t r4[4];
                    uint32_t addr = smem_to_u32(Bs + (size_t)(n_base + p * 16 + b_row) * APAD
                                                + k0 + b_colb);
                    ldsm_x4(r4, addr);
                    bfr[2 * p + 0][0] = r4[0]; bfr[2 * p + 0][1] = r4[1];
                    bfr[2 * p + 1][0] = r4[2]; bfr[2 * p + 1][1] = r4[3];
                }
                #pragma unroll
                for (int am = 0; am < 2; am++)
                    #pragma unroll
                    for (int an = 0; an < 4; an++)
                        mma_bf16(acc[am * 4 + an], afr[am], bfr[an]);
            }
        }
        __syncthreads();
    }
#undef O_LOAD_CHUNK

    float* opart = g_scratch + OFF_OPART + (size_t)(zk * 2 + hg) * 65536;
    int gid = lid >> 2, tig = lid & 3;
    #pragma unroll
    for (int am = 0; am < 2; am++) {
        #pragma unroll
        for (int an = 0; an < 4; an++) {
            const float* d = acc[am * 4 + an];
            int row0 = bm + m_base + am * 16 + gid;
            int col = n_base + an * 8 + tig * 2;
            *(float2*)(opart + (size_t)row0 * 64 + col) = make_float2(d[0], d[1]);
            *(float2*)(opart + (size_t)(row0 + 8) * 64 + col) = make_float2(d[2], d[3]);
        }
    }
}

// ===========================================================================
// mma_nt: C[M x N] = A(hi/lo [M][K]) @ WT(hi/lo [N][K])^T, x3 splits,
// K chunked 64, cp.async double-buffered.
// flags: 1=bias 2=residual 4=gelu 8=write bf16 splits 16=skip fp32.
// smem: 2 buffers x 4 x 128x72 bf16 = 147456 B.
// ===========================================================================
#define MMANT_SMEM_BYTES 147456
#define NT_BUF 36864   // bf16 per buffer

__global__ void __launch_bounds__(256) mma_nt_kernel(
    long long aHiOff, long long aLoOff,
    long long bHiOff, long long bLoOff,
    const float* __restrict__ bias, long long rOff, long long cOff,
    long long sHiOff, long long sLoOff,
    int K, int ldc, int flags)
{
    extern __shared__ __align__(16) char dsm[];
    __nv_bfloat16* sb = (__nv_bfloat16*)dsm;

    int tid = threadIdx.x;
    int wid = tid >> 5, lid = tid & 31;
    int bn = blockIdx.x * 128;
    int bm = blockIdx.y * 128;

    const __nv_bfloat16* ah = (const __nv_bfloat16*)(g_scratch + aHiOff);
    const __nv_bfloat16* al = (const __nv_bfloat16*)(g_scratch + aLoOff);
    const __nv_bfloat16* bh = (const __nv_bfloat16*)(g_scratch + bHiOff);
    const __nv_bfloat16* bl = (const __nv_bfloat16*)(g_scratch + bLoOff);

    int warp_m = wid & 3;
    int warp_n = wid >> 2;
    int m_base = warp_m * 32;
    int n_base = warp_n * 64;

    float acc[16][4];
    #pragma unroll
    for (int i = 0; i < 16; i++)
        #pragma unroll
        for (int j = 0; j < 4; j++) acc[i][j] = 0.f;

    int a_row = lid & 15;
    int a_colb = (lid >> 4) * 8;
    int b_row = (lid >> 4) * 8 + (lid & 7);
    int b_colb = ((lid >> 3) & 1) * 8;

    int r2 = tid >> 1, half = tid & 1;
    int nch = K / 64;

#define NT_LOAD_CHUNK(buf, koff) do { \
    __nv_bfloat16* base_ = sb + (buf) * NT_BUF; \
    uint32_t s0_ = smem_to_u32(base_ + r2 * APAD + half * 32); \
    uint32_t s1_ = smem_to_u32(base_ + 9216 + r2 * APAD + half * 32); \
    uint32_t s2_ = smem_to_u32(base_ + 18432 + r2 * APAD + half * 32); \
    uint32_t s3_ = smem_to_u32(base_ + 27648 + r2 * APAD + half * 32); \
    const __nv_bfloat16* g0_ = ah + (size_t)(bm + r2) * K + (koff) + half * 32; \
    const __nv_bfloat16* g1_ = al + (size_t)(bm + r2) * K + (koff) + half * 32; \
    const __nv_bfloat16* g2_ = bh + (size_t)(bn + r2) * K + (koff) + half * 32; \
    const __nv_bfloat16* g3_ = bl + (size_t)(bn + r2) * K + (koff) + half * 32; \
    _Pragma("unroll") \
    for (int i_ = 0; i_ < 4; i_++) { \
        cp_async16(s0_ + i_ * 16, g0_ + i_ * 8); \
        cp_async16(s1_ + i_ * 16, g1_ + i_ * 8); \
        cp_async16(s2_ + i_ * 16, g2_ + i_ * 8); \
        cp_async16(s3_ + i_ * 16, g3_ + i_ * 8); \
    } \
} while (0)

    NT_LOAD_CHUNK(0, 0);
    CP_COMMIT();

    for (int ch = 0; ch < nch; ch++) {
        int cur = ch & 1;
        if (ch + 1 < nch) {
            NT_LOAD_CHUNK(1 - cur, (ch + 1) * 64);
            CP_COMMIT();
            CP_WAIT1();
        } else {
            CP_WAIT0();
        }
        __syncthreads();

        const __nv_bfloat16* Ahc = sb + cur * NT_BUF;
        const __nv_bfloat16* Alc = Ahc + 9216;
        const __nv_bfloat16* Bhc = Ahc + 18432;
        const __nv_bfloat16* Blc = Ahc + 27648;

        #pragma unroll
        for (int sp = 0; sp < 3; sp++) {
            const __nv_bfloat16* As = (sp == 2) ? Alc : Ahc;
            const __nv_bfloat16* Bs = (sp == 1) ? Blc : Bhc;
            #pragma unroll
            for (int ks = 0; ks < 4; ks++) {
                int k0 = ks * 16;
                uint32_t afr[2][4];
                #pragma unroll
                for (int am = 0; am < 2; am++) {
                    uint32_t addr = smem_to_u32(As + (size_t)(m_base + am * 16 + a_row) * APAD
                                                + k0 + a_colb);
                    ldsm_x4(afr[am], addr);
                }
                uint32_t bfr[8][2];
                #pragma unroll
                for (int p = 0; p < 4; p++) {
                    uint32_t r4[4];
                    uint32_t addr = smem_to_u32(Bs + (size_t)(n_base + p * 16 + b_row) * APAD
                                                + k0 + b_colb);
                    ldsm_x4(r4, addr);
                    bfr[2 * p + 0][0] = r4[0]; bfr[2 * p + 0][1] = r4[1];
                    bfr[2 * p + 1][0] = r4[2]; bfr[2 * p + 1][1] = r4[3];
                }
                #pragma unroll
                for (int am = 0; am < 2; am++)
                    #pragma unroll
                    for (int an = 0; an < 8; an++)
                        mma_bf16(acc[am * 8 + an], afr[am], bfr[an]);
            }
        }
        __syncthreads();
    }
#undef NT_LOAD_CHUNK

    float* C = g_scratch + cOff;
    const float* R = g_scratch + rOff;
    __nv_bfloat16* SH = (__nv_bfloat16*)(g_scratch + sHiOff);
    __nv_bfloat16* SL = (__nv_bfloat16*)(g_scratch + sLoOff);
    int gid = lid >> 2, tig = lid & 3;
    #pragma unroll
    for (int am = 0; am < 2; am++) {
        #pragma unroll
        for (int an = 0; an < 8; an++) {
            float d0 = acc[am * 8 + an][0], d1 = acc[am * 8 + an][1];
            float d2 = acc[am * 8 + an][2], d3 = acc[am * 8 + an][3];
            long long rowA = bm + m_base + am * 16 + gid;
            long long rowB = rowA + 8;
            long long col = bn + n_base + an * 8 + tig * 2;
            if (flags & 1) { float b0 = bias[col], b1 = bias[col + 1];
                             d0 += b0; d1 += b1; d2 += b0; d3 += b1; }
            if (flags & 4) {
                d0 = 0.5f * d0 * (1.0f + erff(d0 * 0.7071067811865476f));
                d1 = 0.5f * d1 * (1.0f + erff(d1 * 0.7071067811865476f));
                d2 = 0.5f * d2 * (1.0f + erff(d2 * 0.7071067811865476f));
                d3 = 0.5f * d3 * (1.0f + erff(d3 * 0.7071067811865476f));
            }
            if (flags & 2) {
                d0 += R[rowA * ldc + col]; d1 += R[rowA * ldc + col + 1];
                d2 += R[rowB * ldc + col]; d3 += R[rowB * ldc + col + 1];
            }
            if (!(flags & 16)) {
                *(float2*)(C + rowA * ldc + col) = make_float2(d0, d1);
                *(float2*)(C + rowB * ldc + col) = make_float2(d2, d3);
            }
            if (flags & 8) {
                __nv_bfloat16 h0, l0, h1, l1, h2, l2, h3, l3;
                split_bf16(d0, h0, l0); split_bf16(d1, h1, l1);
                split_bf16(d2, h2, l2); split_bf16(d3, h3, l3);
                __nv_bfloat162 ph0; ph0.x = h0; ph0.y = h1;
                __nv_bfloat162 pl0; pl0.x = l0; pl0.y = l1;
                __nv_bfloat162 ph1; ph1.x = h2; ph1.y = h3;
                __nv_bfloat162 pl1; pl1.x = l2; pl1.y = l3;
                *(__nv_bfloat162*)(SH + rowA * ldc + col) = ph0;
                *(__nv_bfloat162*)(SL + rowA * ldc + col) = pl0;
                *(__nv_bfloat162*)(SH + rowB * ldc + col) = ph1;
                *(__nv_bfloat162*)(SL + rowB * ldc + col) = pl1;
            }
        }
    }
}

// ---------------------------------------------------------------------------
extern "C" void kernel_launch(void* const* d_in, const int* in_sizes, int n_in,
                              void* d_out, int out_size)
{
    (void)in_sizes; (void)n_in;
    const float* x      = (const float*)d_in[0];
    const float* qkv_w  = (const float*)d_in[1];
    const float* q2_w   = (const float*)d_in[2];
    const float* kv2_w  = (const float*)d_in[3];
    const float* proj_w = (const float*)d_in[4];
    const float* proj_b = (const float*)d_in[5];
    const float* ln1_g  = (const float*)d_in[6];
    const float* ln1_b  = (const float*)d_in[7];
    const float* ln2_g  = (const float*)d_in[8];
    const float* ln2_b  = (const float*)d_in[9];
    const float* fc1_w  = (const float*)d_in[10];
    const float* fc1_b  = (const float*)d_in[11];
    const float* fc2_w  = (const float*)d_in[12];
    const float* fc2_b  = (const float*)d_in[13];
    float* out = (float*)d_out;

    cudaFuncSetAttribute(mma_lg_kernel,
                         cudaFuncAttributeMaxDynamicSharedMemorySize, MMA_SMEM_BYTES);
    cudaFuncSetAttribute(mma_o_kernel,
                         cudaFuncAttributeMaxDynamicSharedMemorySize, MMAO_SMEM_BYTES);
    cudaFuncSetAttribute(mma_nt_kernel,
                         cudaFuncAttributeMaxDynamicSharedMemorySize, MMANT_SMEM_BYTES);
    cudaFuncSetAttribute(mma_nt64_kernel,
                         cudaFuncAttributeMaxDynamicSharedMemorySize, MMA_SMEM_BYTES);

    // all six weight transpose-splits, one launch
    cvt_weights_kernel<<<540, 256>>>(qkv_w, kv2_w, q2_w, proj_w, fc1_w, fc2_w);

    pool_kernel<<<1536, 256>>>(x);
    // LN1 -> xn bf16 splits (XD region)
    ln_kernel<<<1024, 384>>>(OFF_TOK, ln1_g, ln1_b, OFF_XD, OFF_XD + 196608);

    // qkv mma: fp32 -> QKV, bf16 splits -> LG region
    mma_nt_kernel<<<dim3(9, 8), 256, MMANT_SMEM_BYTES>>>(
        OFF_XD, OFF_XD + 196608, OFF_QKVWT, OFF_QKVWT + 221184,
        nullptr, 0, OFF_QKV, OFF_LG, OFF_LG + 589824, 384, 1152, 8);

    // qk[h] = q_h @ k_h^T  (6 heads in z)
    mma_nt64_kernel<<<dim3(8, 8, 6), 256, MMA_SMEM_BYTES>>>(
        OFF_LG, OFF_LG + 589824, 1152, 0, 64,
        OFF_LG, OFF_LG + 589824, 1152, 384, 64,
        OFF_QK, 1024, 1048576);

    // VW[h'] = v_h' @ kv2_w[h' slice]  (6 heads in z)
    mma_nt64_kernel<<<dim3(6, 8, 6), 256, MMA_SMEM_BYTES>>>(
        OFF_LG, OFF_LG + 589824, 1152, 768, 64,
        OFF_KV2WT, OFF_KV2WT + 147456, 384, 0, 64,
        OFF_VW, 768, 786432);

    ta_kernel<<<6144, 256>>>();
    // x_diag -> bf16 splits (XD region, xn splits now dead)
    xdiag_kernel<<<1024, 384>>>();

    // q2 = x_diag @ (SCALE*q2_w): splits only -> XN region
    mma_nt_kernel<<<dim3(3, 8), 256, MMANT_SMEM_BYTES>>>(
        OFF_XD, OFF_XD + 196608, OFF_Q2WT, OFF_Q2WT + 73728,
        nullptr, 0, 0, OFF_XN, OFF_XN + 196608, 384, 384, 8 | 16);

    // VWk splits -> QKV/MLP regions; VWv transposed splits
    cvt_split_kernel<<<9216, 256>>>(OFF_VW, 768, 384, OFF_QKV, OFF_MLP);
    cvt_vwt_kernel<<<dim3(96, 6), 256>>>();

    int wout = (out_size >= 3145728) ? 1 : 0;

    // stage 2 in 3 groups of 2 heads
    for (int g = 0; g < 3; g++) {
        mma_lg_kernel<<<dim3(48, 8, 2), 256, MMA_SMEM_BYTES>>>(g);
        middle_kernel<<<dim3(1024, 2), 256>>>(g, out + 1572864, wout);
        mma_o_kernel<<<dim3(12, 8, 2), 256, MMAO_SMEM_BYTES>>>(g);
        oreduce_kernel<<<512, 256>>>(g);
    }

    // h1 = tok + (o @ proj_w + proj_b)
    mma_nt_kernel<<<dim3(3, 8), 256, MMANT_SMEM_BYTES>>>(
        OFF_O, OFF_O + 196608, OFF_PROJWT, OFF_PROJWT + 73728,
        proj_b, OFF_TOK, OFF_H1, 0, 0, 384, 384, 1 | 2);

    // LN2 -> hn bf16 splits (XD region, xd splits now dead)
    ln_kernel<<<1024, 384>>>(OFF_H1, ln2_g, ln2_b, OFF_XD, OFF_XD + 196608);

    // fc1: bias+gelu, splits only -> QK region
    mma_nt_kernel<<<dim3(12, 8), 256, MMANT_SMEM_BYTES>>>(
        OFF_XD, OFF_XD + 196608, OFF_FC1WT, OFF_FC1WT + 294912,
        fc1_b, 0, 0, OFF_QK + 589824, OFF_QK + 1376256, 384, 1536, 1 | 4 | 8 | 16);

    // fc2: bias + residual(H1) -> H2 fp32
    mma_nt_kernel<<<dim3(3, 8), 256, MMANT_SMEM_BYTES>>>(
        OFF_QK + 589824, OFF_QK + 1376256, OFF_FC2WT, OFF_FC2WT + 294912,
        fc2_b, OFF_H1, OFF_H2, 0, 0, 1536, 384, 1 | 2);

    upsample_kernel<<<1536, 256>>>(out, out_size);
}

// round 17
// speedup vs baseline: 1.4902x; 1.0546x over previous
#include <cuda_runtime.h>
#include <cuda_bf16.h>
#include <cstdint>
#include <math.h>

// ---------------------------------------------------------------------------
// DeformationTrajectoryAttentionBlock — all big GEMMs on mma.sync bf16x3;
// fused split epilogues; batched weight cvt; cp.async dbl-buffered mma;
// mma_nt with N=64 tiles for full SM coverage.
// B=1, F=4, H=6, D=384, G=16, S=256, N=1024, HD=64, IMG=32, MLP_HID=1536
// ---------------------------------------------------------------------------

#define SCALE 0.125f
#define LN_EPS 1e-5f
typedef unsigned long long ull;

#define OFF_TOK    0LL          // 1024*384 fp32
#define OFF_XN     393216LL     // q2 splits: hi bf16 @ +0, lo @ +196608
#define OFF_QKV    786432LL     // 1024*1152 fp32 ; later VWk-hi bf16
#define OFF_VW     1966080LL    // 6*1024*768 (6144 x 768) fp32
#define OFF_QK     6684672LL    // qk fp32 / Lg[hg=0]/AB ; later mlp splits
#define OFF_TA     12976128LL   // 1024*256*24
#define OFF_XD     19267584LL   // xn splits -> xd splits -> hn splits (bf16 hi/lo)
#define OFF_Q2     19660800LL   // (unused fp32 slot)
#define OFF_LG     20054016LL   // qkv splits bf16 -> Lg[hg=1]/AB
#define LG_STRIDE  13369344LL   // OFF_LG - OFF_QK
#define OFF_OPART  26345472LL   // 24 * 1024*64
#define OFF_O      27918336LL   // o splits: hi bf16 @ +0, lo @ +196608
#define OFF_H1     28311552LL
#define OFF_HN     28704768LL   // (unused fp32 slot)
#define OFF_MLP    29097984LL   // VWk-lo bf16
#define OFF_H2     30670848LL
#define OFF_VWTH   31064064LL   // VWv^T hi bf16 [6][64][6144]
#define OFF_VWTL   32243712LL   // VWv^T lo bf16
#define OFF_QKVWT  33423360LL   // qkv_w^T hi/lo (hi +0, lo +221184)
#define OFF_KV2WT  33865728LL   // kv2_w^T hi/lo (hi +0, lo +147456)
#define OFF_Q2WT   34160640LL   // SCALE*q2_w^T hi/lo (hi +0, lo +73728)
#define OFF_PROJWT 34308096LL   // proj_w^T hi/lo (hi +0, lo +73728)
#define OFF_FC1WT  34455552LL   // fc1_w^T hi/lo (hi +0, lo +294912)
#define OFF_FC2WT  35045376LL   // fc2_w^T hi/lo (hi +0, lo +294912)
#define SCRATCH_FLOATS 35635200LL

static __device__ float g_scratch[SCRATCH_FLOATS];

__device__ __forceinline__ uint32_t smem_to_u32(const void* smem_ptr)
{
    uint32_t addr;
    asm("{ .reg .u64 tmp; cvta.to.shared.u64 tmp, %1; cvt.u32.u64 %0, tmp; }"
        : "=r"(addr) : "l"(smem_ptr));
    return addr;
}
__device__ __forceinline__ void split_bf16(float v, __nv_bfloat16& hi, __nv_bfloat16& lo)
{
    hi = __float2bfloat16(v);
    lo = __float2bfloat16(v - __bfloat162float(hi));
}
__device__ __forceinline__ void cp_async16(uint32_t saddr, const void* gptr)
{
    asm volatile("cp.async.ca.shared.global [%0], [%1], 16;"
                 :: "r"(saddr), "l"(gptr));
}
#define CP_COMMIT() asm volatile("cp.async.commit_group;" ::: "memory")
#define CP_WAIT0()  asm volatile("cp.async.wait_group 0;" ::: "memory")
#define CP_WAIT1()  asm volatile("cp.async.wait_group 1;" ::: "memory")

// ---------------------------------------------------------------------------
__global__ void pool_kernel(const float* __restrict__ x)
{
    float* tok = g_scratch + OFF_TOK;
    int fd = blockIdx.x;
    int f = fd / 384;
    const float* xp = x + (size_t)fd * 1024;
    int t = threadIdx.x;
    int gy = t >> 4, gx = t & 15;
    const float* p = xp + (gy * 2) * 32 + gx * 2;
    float m = fmaxf(fmaxf(p[0], p[1]), fmaxf(p[32], p[33]));
    tok[(size_t)(f * 256 + t) * 384 + (fd % 384)] = m;
}

// ---------------------------------------------------------------------------
__global__ void ln_kernel(long long inOff, const float* __restrict__ g,
                          const float* __restrict__ b,
                          long long hiOff, long long loOff)
{
    const float* in = g_scratch + inOff;
    int n = blockIdx.x, t = threadIdx.x;
    float x = in[(size_t)n * 384 + t];
    __shared__ float red[12];
    __shared__ float mv[2];
    float s = x;
    #pragma unroll
    for (int o = 16; o; o >>= 1) s += __shfl_xor_sync(0xffffffffu, s, o);
    if ((t & 31) == 0) red[t >> 5] = s;
    __syncthreads();
    if (t == 0) { float tt = 0.f; for (int i = 0; i < 12; i++) tt += red[i]; mv[0] = tt * (1.0f / 384.0f); }
    __syncthreads();
    float mean = mv[0];
    float d = x - mean;
    s = d * d;
    #pragma unroll
    for (int o = 16; o; o >>= 1) s += __shfl_xor_sync(0xffffffffu, s, o);
    if ((t & 31) == 0) red[t >> 5] = s;
    __syncthreads();
    if (t == 0) { float tt = 0.f; for (int i = 0; i < 12; i++) tt += red[i]; mv[1] = rsqrtf(tt * (1.0f / 384.0f) + LN_EPS); }
    __syncthreads();
    float v = d * mv[1] * g[t] + b[t];
    __nv_bfloat16 hi, lo;
    split_bf16(v, hi, lo);
    ((__nv_bfloat16*)(g_scratch + hiOff))[(size_t)n * 384 + t] = hi;
    ((__nv_bfloat16*)(g_scratch + loOff))[(size_t)n * 384 + t] = lo;
}

// ---------------------------------------------------------------------------
__global__ void ta_kernel()
{
    const float* qk = g_scratch + OFF_QK;
    float* ta = g_scratch + OFF_TA;
    int b = blockIdx.x;
    int h = b >> 10, n = b & 1023;
    int s = threadIdx.x;
    const float* p = qk + ((size_t)b << 10) + s;
    float x0 = SCALE * p[0], x1 = SCALE * p[256], x2 = SCALE * p[512], x3 = SCALE * p[768];
    float m = fmaxf(fmaxf(x0, x1), fmaxf(x2, x3));
    float e0 = expf(x0 - m), e1 = expf(x1 - m), e2 = expf(x2 - m), e3 = expf(x3 - m);
    float inv = 1.0f / (e0 + e1 + e2 + e3);
    float* o = ta + ((size_t)(n * 256 + s)) * 24 + h * 4;
    o[0] = e0 * inv; o[1] = e1 * inv; o[2] = e2 * inv; o[3] = e3 * inv;
}

// ---------------------------------------------------------------------------
__global__ void xdiag_kernel()
{
    const float* ta = g_scratch + OFF_TA;
    const float* qkv = g_scratch + OFF_QKV;
    int n = blockIdx.x, c = threadIdx.x;
    int h = c >> 6;
    int s = n & 255;
    const float* tp = ta + ((size_t)(n * 256 + s)) * 24 + h * 4;
    float acc = 0.f;
    #pragma unroll
    for (int f = 0; f < 4; f++)
        acc += tp[f] * qkv[(size_t)(f * 256 + s) * 1152 + 768 + c];
    __nv_bfloat16 hi, lo;
    split_bf16(acc, hi, lo);
    ((__nv_bfloat16*)(g_scratch + OFF_XD))[(size_t)n * 384 + c] = hi;
    ((__nv_bfloat16*)(g_scratch + OFF_XD + 196608))[(size_t)n * 384 + c] = lo;
}

// ---------------------------------------------------------------------------
__global__ void __launch_bounds__(256) middle_kernel(int g, float* __restrict__ out_attn,
                                                     int write_out)
{
    int n = blockIdx.x;
    int hg = blockIdx.y;
    int s = threadIdx.x;
    __shared__ __align__(16) float sta[256][24];
    __shared__ float red[8];
    __shared__ float mv[2];

    const float4* tap = (const float4*)(g_scratch + OFF_TA + (size_t)n * 6144);
    float4* stp = (float4*)&sta[0][0];
    for (int idx = s; idx < 1536; idx += 256)
        stp[idx] = tap[idx];
    __syncthreads();

    float* lg = g_scratch + OFF_QK + (long long)hg * LG_STRIDE + (size_t)n * 6144;
    float logit = 0.f;
    #pragma unroll
    for (int j = 0; j < 24; j++)
        logit += sta[s][j] * lg[j * 256 + s];

    float m = logit;
    #pragma unroll
    for (int o = 16; o; o >>= 1) m = fmaxf(m, __shfl_xor_sync(0xffffffffu, m, o));
    if ((s & 31) == 0) red[s >> 5] = m;
    __syncthreads();
    if (s == 0) { float t = red[0]; for (int i = 1; i < 8; i++) t = fmaxf(t, red[i]); mv[0] = t; }
    __syncthreads();
    float e = expf(logit - mv[0]);
    float sum = e;
    #pragma unroll
    for (int o = 16; o; o >>= 1) sum += __shfl_xor_sync(0xffffffffu, sum, o);
    if ((s & 31) == 0) red[s >> 5] = sum;
    __syncthreads();
    if (s == 0) { float t = 0.f; for (int i = 0; i < 8; i++) t += red[i]; mv[1] = 1.0f / t; }
    __syncthreads();
    float sa = e * mv[1];
    if (write_out) out_attn[((size_t)(g * 2 + hg) * 1024 + n) * 256 + s] = sa;
    __nv_bfloat16* ab = (__nv_bfloat16*)lg;
    #pragma unroll
    for (int j = 0; j < 24; j++) {
        float v = sa * sta[s][j];
        __nv_bfloat16 hi, lo;
        split_bf16(v, hi, lo);
        ab[j * 256 + s] = hi;
        ab[6144 + j * 256 + s] = lo;
    }
}

// ---------------------------------------------------------------------------
__global__ void oreduce_kernel(int g)
{
    const float* opart = g_scratch + OFF_OPART;
    int i = blockIdx.x * 256 + threadIdx.x;       // < 131072
    int hg = i >> 16;
    int r = i & 65535;
    float sum = 0.f;
    #pragma unroll
    for (int zk = 0; zk < 12; zk++)
        sum += opart[(size_t)(zk * 2 + hg) * 65536 + r];
    __nv_bfloat16 hi, lo;
    split_bf16(sum, hi, lo);
    size_t idx = (size_t)(r >> 6) * 384 + (g * 2 + hg) * 64 + (r & 63);
    ((__nv_bfloat16*)(g_scratch + OFF_O))[idx] = hi;
    ((__nv_bfloat16*)(g_scratch + OFF_O + 196608))[idx] = lo;
}

// ---------------------------------------------------------------------------
__global__ void upsample_kernel(float* __restrict__ out, int out_size)
{
    const float* h2 = g_scratch + OFF_H2;
    int fd = blockIdx.x;
    int f = fd / 384, d = fd % 384;
    __shared__ float ch[256];
    int t = threadIdx.x;
    ch[t] = h2[(size_t)(f * 256 + t) * 384 + d];
    __syncthreads();
    #pragma unroll
    for (int p = 0; p < 4; p++) {
        int o = t + p * 256;
        int oy = o >> 5, ox = o & 31;
        float fy = 0.5f * oy - 0.25f;
        int iy0 = (int)floorf(fy);
        float wy = fy - (float)iy0;
        int iy0c = max(iy0, 0), iy1c = min(iy0 + 1, 15);
        float fx = 0.5f * ox - 0.25f;
        int ix0 = (int)floorf(fx);
        float wx = fx - (float)ix0;
        int ix0c = max(ix0, 0), ix1c = min(ix0 + 1, 15);
        float v00 = ch[iy0c * 16 + ix0c], v01 = ch[iy0c * 16 + ix1c];
        float v10 = ch[iy1c * 16 + ix0c], v11 = ch[iy1c * 16 + ix1c];
        float v = (1.f - wy) * ((1.f - wx) * v00 + wx * v01)
                + wy * ((1.f - wx) * v10 + wx * v11);
        long long oi = (long long)fd * 1024 + o;
        if (oi < (long long)out_size) out[oi] = v;
    }
}

// ---------------------------------------------------------------------------
__global__ void cvt_split_kernel(long long inOff, int inStride, int width,
                                 long long hiOff, long long loOff)
{
    long long i = (long long)blockIdx.x * 256 + threadIdx.x;
    int row = (int)(i / width);
    int col = (int)(i % width);
    float v = g_scratch[inOff + (long long)row * inStride + col];
    __nv_bfloat16 h, l;
    split_bf16(v, h, l);
    ((__nv_bfloat16*)(g_scratch + hiOff))[i] = h;
    ((__nv_bfloat16*)(g_scratch + loOff))[i] = l;
}

// ---------------------------------------------------------------------------
__global__ void cvt_weights_kernel(const float* __restrict__ qkv_w,
                                   const float* __restrict__ kv2_w,
                                   const float* __restrict__ q2_w,
                                   const float* __restrict__ proj_w,
                                   const float* __restrict__ fc1_w,
                                   const float* __restrict__ fc2_w)
{
    __shared__ float tile[64][65];
    int t = blockIdx.x;
    const float* W; int Kd, Nd; long long hiOff, loOff; float scale = 1.0f;
    if (t < 108)      {           W = qkv_w;  Kd = 384;  Nd = 1152;
                        hiOff = OFF_QKVWT;  loOff = OFF_QKVWT + 221184; }
    else if (t < 180) { t -= 108; W = kv2_w;  Kd = 384;  Nd = 768;
                        hiOff = OFF_KV2WT;  loOff = OFF_KV2WT + 147456; }
    else if (t < 216) { t -= 180; W = q2_w;   Kd = 384;  Nd = 384;
                        hiOff = OFF_Q2WT;   loOff = OFF_Q2WT + 73728;  scale = SCALE; }
    else if (t < 252) { t -= 216; W = proj_w; Kd = 384;  Nd = 384;
                        hiOff = OFF_PROJWT; loOff = OFF_PROJWT + 73728; }
    else if (t < 396) { t -= 252; W = fc1_w;  Kd = 384;  Nd = 1536;
                        hiOff = OFF_FC1WT;  loOff = OFF_FC1WT + 294912; }
    else              { t -= 396; W = fc2_w;  Kd = 1536; Nd = 384;
                        hiOff = OFF_FC2WT;  loOff = OFF_FC2WT + 294912; }
    int ktiles = Kd >> 6;
    int kt = (t % ktiles) * 64;
    int nt = (t / ktiles) * 64;
    int tid = threadIdx.x;
    for (int i = tid; i < 4096; i += 256) {
        int k = i >> 6, n = i & 63;
        tile[k][n] = W[(size_t)(kt + k) * Nd + nt + n] * scale;
    }
    __syncthreads();
    __nv_bfloat16* vh = (__nv_bfloat16*)(g_scratch + hiOff);
    __nv_bfloat16* vl = (__nv_bfloat16*)(g_scratch + loOff);
    for (int i = tid; i < 4096; i += 256) {
        int n = i >> 6, k = i & 63;
        float v = tile[k][n];
        __nv_bfloat16 hi, lo;
        split_bf16(v, hi, lo);
        size_t idx = (size_t)(nt + n) * Kd + kt + k;
        vh[idx] = hi;
        vl[idx] = lo;
    }
}

// ---------------------------------------------------------------------------
__global__ void cvt_vwt_kernel()
{
    __shared__ float tile[64][65];
    int kt = blockIdx.x * 64;
    int h = blockIdx.y;
    int tid = threadIdx.x;
    for (int i = tid; i < 4096; i += 256) {
        int k = i >> 6, n = i & 63;
        tile[k][n] = g_scratch[OFF_VW + (size_t)(kt + k) * 768 + 384 + h * 64 + n];
    }
    __syncthreads();
    __nv_bfloat16* vh = (__nv_bfloat16*)(g_scratch + OFF_VWTH);
    __nv_bfloat16* vl = (__nv_bfloat16*)(g_scratch + OFF_VWTL);
    for (int i = tid; i < 4096; i += 256) {
        int n = i >> 6, k = i & 63;
        float v = tile[k][n];
        __nv_bfloat16 hi, lo;
        split_bf16(v, hi, lo);
        size_t idx = ((size_t)h * 64 + n) * 6144 + kt + k;
        vh[idx] = hi;
        vl[idx] = lo;
    }
}

// ===========================================================================
// mma.sync helpers
// ===========================================================================
__device__ __forceinline__ void ldsm_x4(uint32_t* r, uint32_t addr)
{
    asm volatile("ldmatrix.sync.aligned.m8n8.x4.shared.b16 {%0,%1,%2,%3}, [%4];"
                 : "=r"(r[0]), "=r"(r[1]), "=r"(r[2]), "=r"(r[3]) : "r"(addr));
}
__device__ __forceinline__ void mma_bf16(float* d, const uint32_t* a, const uint32_t* b)
{
    asm volatile(
        "mma.sync.aligned.m16n8k16.row.col.f32.bf16.bf16.f32 "
        "{%0,%1,%2,%3}, {%4,%5,%6,%7}, {%8,%9}, {%0,%1,%2,%3};"
        : "+f"(d[0]), "+f"(d[1]), "+f"(d[2]), "+f"(d[3])
        : "r"(a[0]), "r"(a[1]), "r"(a[2]), "r"(a[3]), "r"(b[0]), "r"(b[1]));
}

#define MMA_SMEM_BYTES 73728
#define APAD 72

// ===========================================================================
// mma_lg (R10-proven): Lg tile (128 x 128) = q2_h @ VWk_h^T, K=64, x3 splits.
// ===========================================================================
__global__ void __launch_bounds__(256) mma_lg_kernel(int g)
{
    extern __shared__ __align__(16) char dsm[];
    __nv_bfloat16* Ah = (__nv_bfloat16*)dsm;
    __nv_bfloat16* Al = Ah + 128 * APAD;
    __nv_bfloat16* Bh = Al + 128 * APAD;
    __nv_bfloat16* Bl = Bh + 128 * APAD;

    int tid = threadIdx.x;
    int wid = tid >> 5, lid = tid & 31;
    int bn = blockIdx.x * 128;
    int bm = blockIdx.y * 128;
    int hg = blockIdx.z;
    int h = g * 2 + hg;

    const __nv_bfloat16* q2h = (const __nv_bfloat16*)(g_scratch + OFF_XN);
    const __nv_bfloat16* q2l = (const __nv_bfloat16*)(g_scratch + OFF_XN + 196608);
    const __nv_bfloat16* vwh = (const __nv_bfloat16*)(g_scratch + OFF_QKV);
    const __nv_bfloat16* vwl = (const __nv_bfloat16*)(g_scratch + OFF_MLP);

    {
        int r = tid >> 1, half = tid & 1;
        const uint4* sah = (const uint4*)(q2h + (size_t)(bm + r) * 384 + h * 64 + half * 32);
        const uint4* sal = (const uint4*)(q2l + (size_t)(bm + r) * 384 + h * 64 + half * 32);
        uint4* dah = (uint4*)(Ah + r * APAD + half * 32);
        uint4* dal = (uint4*)(Al + r * APAD + half * 32);
        #pragma unroll
        for (int i = 0; i < 4; i++) { dah[i] = sah[i]; dal[i] = sal[i]; }
        const uint4* sbh = (const uint4*)(vwh + (size_t)(bn + r) * 384 + h * 64 + half * 32);
        const uint4* sbl = (const uint4*)(vwl + (size_t)(bn + r) * 384 + h * 64 + half * 32);
        uint4* dbh = (uint4*)(Bh + r * APAD + half * 32);
        uint4* dbl = (uint4*)(Bl + r * APAD + half * 32);
        #pragma unroll
        for (int i = 0; i < 4; i++) { dbh[i] = sbh[i]; dbl[i] = sbl[i]; }
    }
    __syncthreads();

    int warp_m = wid & 3;
    int warp_n = wid >> 2;
    int m_base = warp_m * 32;
    int n_base = warp_n * 64;

    float acc[16][4];
    #pragma unroll
    for (int i = 0; i < 16; i++)
        #pragma unroll
        for (int j = 0; j < 4; j++) acc[i][j] = 0.f;

    int a_row = lid & 15;
    int a_colb = (lid >> 4) * 8;
    int b_row = (lid >> 4) * 8 + (lid & 7);
    int b_colb = ((lid >> 3) & 1) * 8;

    #pragma unroll
    for (int sp = 0; sp < 3; sp++) {
        const __nv_bfloat16* As = (sp == 2) ? Al : Ah;
        const __nv_bfloat16* Bs = (sp == 1) ? Bl : Bh;
        #pragma unroll
        for (int ks = 0; ks < 4; ks++) {
            int k0 = ks * 16;
            uint32_t afr[2][4];
            #pragma unroll
            for (int am = 0; am < 2; am++) {
                uint32_t addr = smem_to_u32(As + (size_t)(m_base + am * 16 + a_row) * APAD
                                            + k0 + a_colb);
                ldsm_x4(afr[am], addr);
            }
            uint32_t bfr[8][2];
            #pragma unroll
            for (int p = 0; p < 4; p++) {
                uint32_t r4[4];
                uint32_t addr = smem_to_u32(Bs + (size_t)(n_base + p * 16 + b_row) * APAD
                                            + k0 + b_colb);
                ldsm_x4(r4, addr);
                bfr[2 * p + 0][0] = r4[0]; bfr[2 * p + 0][1] = r4[1];
                bfr[2 * p + 1][0] = r4[2]; bfr[2 * p + 1][1] = r4[3];
            }
            #pragma unroll
            for (int am = 0; am < 2; am++)
                #pragma unroll
                for (int an = 0; an < 8; an++)
                    mma_bf16(acc[am * 8 + an], afr[am], bfr[an]);
        }
    }

    float* lg = g_scratch + OFF_QK + (long long)hg * LG_STRIDE;
    int gid = lid >> 2, tig = lid & 3;
    #pragma unroll
    for (int am = 0; am < 2; am++) {
        #pragma unroll
        for (int an = 0; an < 8; an++) {
            const float* d = acc[am * 8 + an];
            long long row0 = bm + m_base + am * 16 + gid;
            long long col = bn + n_base + an * 8 + tig * 2;
            *(float2*)(lg + row0 * 6144 + col) = make_float2(d[0], d[1]);
            *(float2*)(lg + (row0 + 8) * 6144 + col) = make_float2(d[2], d[3]);
        }
    }
}

// ===========================================================================
// mma_nt64 (R14-proven): K=64 NT mma with strided 64-col slices, x3 splits.
// ===========================================================================
__global__ void __launch_bounds__(256) mma_nt64_kernel(
    long long aHiOff, long long aLoOff, int lda, int aCol0, int aColStep,
    long long bHiOff, long long bLoOff, int ldb, int bCol0, int bColStep,
    long long cOff, int ldc, long long cZStride)
{
    extern __shared__ __align__(16) char dsm[];
    __nv_bfloat16* Ah = (__nv_bfloat16*)dsm;
    __nv_bfloat16* Al = Ah + 128 * APAD;
    __nv_bfloat16* Bh = Al + 128 * APAD;
    __nv_bfloat16* Bl = Bh + 128 * APAD;

    int tid = threadIdx.x;
    int wid = tid >> 5, lid = tid & 31;
    int bn = blockIdx.x * 128;
    int bm = blockIdx.y * 128;
    int z = blockIdx.z;

    const __nv_bfloat16* ah = (const __nv_bfloat16*)(g_scratch + aHiOff)
                              + aCol0 + z * aColStep;
    const __nv_bfloat16* al = (const __nv_bfloat16*)(g_scratch + aLoOff)
                              + aCol0 + z * aColStep;
    const __nv_bfloat16* bh = (const __nv_bfloat16*)(g_scratch + bHiOff)
                              + bCol0 + z * bColStep;
    const __nv_bfloat16* bl = (const __nv_bfloat16*)(g_scratch + bLoOff)
                              + bCol0 + z * bColStep;

    {
        int r = tid >> 1, half = tid & 1;
        const uint4* sah = (const uint4*)(ah + (size_t)(bm + r) * lda + half * 32);
        const uint4* sal = (const uint4*)(al + (size_t)(bm + r) * lda + half * 32);
        uint4* dah = (uint4*)(Ah + r * APAD + half * 32);
        uint4* dal = (uint4*)(Al + r * APAD + half * 32);
        #pragma unroll
        for (int i = 0; i < 4; i++) { dah[i] = sah[i]; dal[i] = sal[i]; }
        const uint4* sbh = (const uint4*)(bh + (size_t)(bn + r) * ldb + half * 32);
        const uint4* sbl = (const uint4*)(bl + (size_t)(bn + r) * ldb + half * 32);
        uint4* dbh = (uint4*)(Bh + r * APAD + half * 32);
        uint4* dbl = (uint4*)(Bl + r * APAD + half * 32);
        #pragma unroll
        for (int i = 0; i < 4; i++) { dbh[i] = sbh[i]; dbl[i] = sbl[i]; }
    }
    __syncthreads();

    int warp_m = wid & 3;
    int warp_n = wid >> 2;
    int m_base = warp_m * 32;
    int n_base = warp_n * 64;

    float acc[16][4];
    #pragma unroll
    for (int i = 0; i < 16; i++)
        #pragma unroll
        for (int j = 0; j < 4; j++) acc[i][j] = 0.f;

    int a_row = lid & 15;
    int a_colb = (lid >> 4) * 8;
    int b_row = (lid >> 4) * 8 + (lid & 7);
    int b_colb = ((lid >> 3) & 1) * 8;

    #pragma unroll
    for (int sp = 0; sp < 3; sp++) {
        const __nv_bfloat16* As = (sp == 2) ? Al : Ah;
        const __nv_bfloat16* Bs = (sp == 1) ? Bl : Bh;
        #pragma unroll
        for (int ks = 0; ks < 4; ks++) {
            int k0 = ks * 16;
            uint32_t afr[2][4];
            #pragma unroll
            for (int am = 0; am < 2; am++) {
                uint32_t addr = smem_to_u32(As + (size_t)(m_base + am * 16 + a_row) * APAD
                                            + k0 + a_colb);
                ldsm_x4(afr[am], addr);
            }
            uint32_t bfr[8][2];
            #pragma unroll
            for (int p = 0; p < 4; p++) {
                uint32_t r4[4];
                uint32_t addr = smem_to_u32(Bs + (size_t)(n_base + p * 16 + b_row) * APAD
                                            + k0 + b_colb);
                ldsm_x4(r4, addr);
                bfr[2 * p + 0][0] = r4[0]; bfr[2 * p + 0][1] = r4[1];
                bfr[2 * p + 1][0] = r4[2]; bfr[2 * p + 1][1] = r4[3];
            }
            #pragma unroll
            for (int am = 0; am < 2; am++)
                #pragma unroll
                for (int an = 0; an < 8; an++)
                    mma_bf16(acc[am * 8 + an], afr[am], bfr[an]);
        }
    }

    float* C = g_scratch + cOff + (long long)z * cZStride;
    int gid = lid >> 2, tig = lid & 3;
    #pragma unroll
    for (int am = 0; am < 2; am++) {
        #pragma unroll
        for (int an = 0; an < 8; an++) {
            const float* d = acc[am * 8 + an];
            long long row0 = bm + m_base + am * 16 + gid;
            long long col = bn + n_base + an * 8 + tig * 2;
            *(float2*)(C + row0 * ldc + col) = make_float2(d[0], d[1]);
            *(float2*)(C + (row0 + 8) * ldc + col) = make_float2(d[2], d[3]);
        }
    }
}

// ===========================================================================
// mma_o: o partials = AB(bf16 hi/lo) @ VWvT^T. cp.async double-buffered.
// ===========================================================================
#define MMAO_SMEM_BYTES 110592
#define O_BUF 27648   // bf16 per buffer

__global__ void __launch_bounds__(256) mma_o_kernel(int g)
{
    extern __shared__ __align__(16) char dsm[];
    __nv_bfloat16* sb = (__nv_bfloat16*)dsm;

    int tid = threadIdx.x;
    int wid = tid >> 5, lid = tid & 31;
    int zk = blockIdx.x;
    int bm = blockIdx.y * 128;
    int hg = blockIdx.z;
    int h = g * 2 + hg;

    const __nv_bfloat16* ab = (const __nv_bfloat16*)(g_scratch + OFF_QK
                                                     + (long long)hg * LG_STRIDE);
    const __nv_bfloat16* vh = (const __nv_bfloat16*)(g_scratch + OFF_VWTH)
                              + (size_t)h * 64 * 6144;
    const __nv_bfloat16* vl = (const __nv_bfloat16*)(g_scratch + OFF_VWTL)
                              + (size_t)h * 64 * 6144;

    int warp_m = wid & 3;
    int warp_n = wid >> 2;
    int m_base = warp_m * 32;
    int n_base = warp_n * 32;

    float acc[8][4];
    #pragma unroll
    for (int i = 0; i < 8; i++)
        #pragma unroll
        for (int j = 0; j < 4; j++) acc[i][j] = 0.f;

    int a_row = lid & 15;
    int a_colb = (lid >> 4) * 8;
    int b_row = (lid >> 4) * 8 + (lid & 7);
    int b_colb = ((lid >> 3) & 1) * 8;

    int r2 = tid >> 1, half = tid & 1;

#define O_LOAD_CHUNK(buf, koff) do { \
    __nv_bfloat16* base_ = sb + (buf) * O_BUF; \
    uint32_t s0_ = smem_to_u32(base_ + r2 * APAD + half * 32); \
    uint32_t s1_ = smem_to_u32(base_ + 9216 + r2 * APAD + half * 32); \
    const __nv_bfloat16* g0_ = ab + (size_t)(bm + r2) * 12288 + (koff) + half * 32; \
    const __nv_bfloat16* g1_ = ab + (size_t)(bm + r2) * 12288 + 6144 + (koff) + half * 32; \
    _Pragma("unroll") \
    for (int i_ = 0; i_ < 4; i_++) { \
        cp_async16(s0_ + i_ * 16, g0_ + i_ * 8); \
        cp_async16(s1_ + i_ * 16, g1_ + i_ * 8); \
    } \
    if (tid < 128) { \
        uint32_t s2_ = smem_to_u32(base_ + 18432 + r2 * APAD + half * 32); \
        uint32_t s3_ = smem_to_u32(base_ + 23040 + r2 * APAD + half * 32); \
        const __nv_bfloat16* g2_ = vh + (size_t)r2 * 6144 + (koff) + half * 32; \
        const __nv_bfloat16* g3_ = vl + (size_t)r2 * 6144 + (koff) + half * 32; \
        _Pragma("unroll") \
        for (int i_ = 0; i_ < 4; i_++) { \
            cp_async16(s2_ + i_ * 16, g2_ + i_ * 8); \
            cp_async16(s3_ + i_ * 16, g3_ + i_ * 8); \
        } \
    } \
} while (0)

    O_LOAD_CHUNK(0, zk * 512);
    CP_COMMIT();

    for (int ch = 0; ch < 8; ch++) {
        int cur = ch & 1;
        if (ch + 1 < 8) {
            O_LOAD_CHUNK(1 - cur, zk * 512 + (ch + 1) * 64);
            CP_COMMIT();
            CP_WAIT1();
        } else {
            CP_WAIT0();
        }
        __syncthreads();

        const __nv_bfloat16* Ahc = sb + cur * O_BUF;
        const __nv_bfloat16* Alc = Ahc + 9216;
        const __nv_bfloat16* Bhc = Ahc + 18432;
        const __nv_bfloat16* Blc = Ahc + 23040;

        #pragma unroll
        for (int sp = 0; sp < 3; sp++) {
            const __nv_bfloat16* As = (sp == 2) ? Alc : Ahc;
            const __nv_bfloat16* Bs = (sp == 1) ? Blc : Bhc;
            #pragma unroll
            for (int ks = 0; ks < 4; ks++) {
                int k0 = ks * 16;
                uint32_t afr[2][4];
                #pragma unroll
                for (int am = 0; am < 2; am++) {
                    uint32_t addr = smem_to_u32(As + (size_t)(m_base + am * 16 + a_row) * APAD
                                                + k0 + a_colb);
                    ldsm_x4(afr[am], addr);
                }
                uint32_t bfr[4][2];
                #pragma unroll
                for (int p = 0; p < 2; p++) {
                    uint32_t r4[4];
                    uint32_t addr = smem_to_u32(Bs + (size_t)(n_base + p * 16 + b_row) * APAD
                                                + k0 + b_colb);
                    ldsm_x4(r4, addr);
                    bfr[2 * p + 0][0] = r4[0]; bfr[2 * p + 0][1] = r4[1];
                    bfr[2 * p + 1][0] = r4[2]; bfr[2 * p + 1][1] = r4[3];
                }
                #pragma unroll
                for (int am = 0; am < 2; am++)
                    #pragma unroll
                    for (int an = 0; an < 4; an++)
                        mma_bf16(acc[am * 4 + an], afr[am], bfr[an]);
            }
        }
        __syncthreads();
    }
#undef O_LOAD_CHUNK

    float* opart = g_scratch + OFF_OPART + (size_t)(zk * 2 + hg) * 65536;
    int gid = lid >> 2, tig = lid & 3;
    #pragma unroll
    for (int am = 0; am < 2; am++) {
        #pragma unroll
        for (int an = 0; an < 4; an++) {
            const float* d = acc[am * 4 + an];
            int row0 = bm + m_base + am * 16 + gid;
            int col = n_base + an * 8 + tig * 2;
            *(float2*)(opart + (size_t)row0 * 64 + col) = make_float2(d[0], d[1]);
            *(float2*)(opart + (size_t)(row0 + 8) * 64 + col) = make_float2(d[2], d[3]);
        }
    }
}

// ===========================================================================
// mma_nt: C[M x 64-tile] = A(hi/lo [M][K]) @ WT(hi/lo [N][K])^T, x3 splits,
// K chunked 64, cp.async double-buffered. N-tile = 64 (grid.x = N/64).
// 8 warps as 4x2; warp tile 32x32 (mma_o fragment layout).
// flags: 1=bias 2=residual 4=gelu 8=write bf16 splits 16=skip fp32.
// smem: 2 buffers x (A 2x128x72 + B 2x64x72) bf16 = 110592 B.
// ===========================================================================
#define MMANT_SMEM_BYTES 110592
#define NT_BUF 27648   // bf16 per buffer

__global__ void __launch_bounds__(256) mma_nt_kernel(
    long long aHiOff, long long aLoOff,
    long long bHiOff, long long bLoOff,
    const float* __restrict__ bias, long long rOff, long long cOff,
    long long sHiOff, long long sLoOff,
    int K, int ldc, int flags)
{
    extern __shared__ __align__(16) char dsm[];
    __nv_bfloat16* sb = (__nv_bfloat16*)dsm;

    int tid = threadIdx.x;
    int wid = tid >> 5, lid = tid & 31;
    int bn = blockIdx.x * 64;
    int bm = blockIdx.y * 128;

    const __nv_bfloat16* ah = (const __nv_bfloat16*)(g_scratch + aHiOff);
    const __nv_bfloat16* al = (const __nv_bfloat16*)(g_scratch + aLoOff);
    const __nv_bfloat16* bh = (const __nv_bfloat16*)(g_scratch + bHiOff);
    const __nv_bfloat16* bl = (const __nv_bfloat16*)(g_scratch + bLoOff);

    int warp_m = wid & 3;
    int warp_n = wid >> 2;
    int m_base = warp_m * 32;
    int n_base = warp_n * 32;

    float acc[8][4];
    #pragma unroll
    for (int i = 0; i < 8; i++)
        #pragma unroll
        for (int j = 0; j < 4; j++) acc[i][j] = 0.f;

    int a_row = lid & 15;
    int a_colb = (lid >> 4) * 8;
    int b_row = (lid >> 4) * 8 + (lid & 7);
    int b_colb = ((lid >> 3) & 1) * 8;

    int r2 = tid >> 1, half = tid & 1;
    int nch = K / 64;

#define NT_LOAD_CHUNK(buf, koff) do { \
    __nv_bfloat16* base_ = sb + (buf) * NT_BUF; \
    uint32_t s0_ = smem_to_u32(base_ + r2 * APAD + half * 32); \
    uint32_t s1_ = smem_to_u32(base_ + 9216 + r2 * APAD + half * 32); \
    const __nv_bfloat16* g0_ = ah + (size_t)(bm + r2) * K + (koff) + half * 32; \
    const __nv_bfloat16* g1_ = al + (size_t)(bm + r2) * K + (koff) + half * 32; \
    _Pragma("unroll") \
    for (int i_ = 0; i_ < 4; i_++) { \
        cp_async16(s0_ + i_ * 16, g0_ + i_ * 8); \
        cp_async16(s1_ + i_ * 16, g1_ + i_ * 8); \
    } \
    if (tid < 128) { \
        uint32_t s2_ = smem_to_u32(base_ + 18432 + r2 * APAD + half * 32); \
        uint32_t s3_ = smem_to_u32(base_ + 23040 + r2 * APAD + half * 32); \
        const __nv_bfloat16* g2_ = bh + (size_t)(bn + r2) * K + (koff) + half * 32; \
        const __nv_bfloat16* g3_ = bl + (size_t)(bn + r2) * K + (koff) + half * 32; \
        _Pragma("unroll") \
        for (int i_ = 0; i_ < 4; i_++) { \
            cp_async16(s2_ + i_ * 16, g2_ + i_ * 8); \
            cp_async16(s3_ + i_ * 16, g3_ + i_ * 8); \
        } \
    } \
} while (0)

    NT_LOAD_CHUNK(0, 0);
    CP_COMMIT();

    for (int ch = 0; ch < nch; ch++) {
        int cur = ch & 1;
        if (ch + 1 < nch) {
            NT_LOAD_CHUNK(1 - cur, (ch + 1) * 64);
            CP_COMMIT();
            CP_WAIT1();
        } else {
            CP_WAIT0();
        }
        __syncthreads();

        const __nv_bfloat16* Ahc = sb + cur * NT_BUF;
        const __nv_bfloat16* Alc = Ahc + 9216;
        const __nv_bfloat16* Bhc = Ahc + 18432;
        const __nv_bfloat16* Blc = Ahc + 23040;

        #pragma unroll
        for (int sp = 0; sp < 3; sp++) {
            const __nv_bfloat16* As = (sp == 2) ? Alc : Ahc;
            const __nv_bfloat16* Bs = (sp == 1) ? Blc : Bhc;
            #pragma unroll
            for (int ks = 0; ks < 4; ks++) {
                int k0 = ks * 16;
                uint32_t afr[2][4];
                #pragma unroll
                for (int am = 0; am < 2; am++) {
                    uint32_t addr = smem_to_u32(As + (size_t)(m_base + am * 16 + a_row) * APAD
                                                + k0 + a_colb);
                    ldsm_x4(afr[am], addr);
                }
                uint32_t bfr[4][2];
                #pragma unroll
                for (int p = 0; p < 2; p++) {
                    uint32_t r4[4];
                    uint32_t addr = smem_to_u32(Bs + (size_t)(n_base + p * 16 + b_row) * APAD
                                                + k0 + b_colb);
                    ldsm_x4(r4, addr);
                    bfr[2 * p + 0][0] = r4[0]; bfr[2 * p + 0][1] = r4[1];
                    bfr[2 * p + 1][0] = r4[2]; bfr[2 * p + 1][1] = r4[3];
                }
                #pragma unroll
                for (int am = 0; am < 2; am++)
                    #pragma unroll
                    for (int an = 0; an < 4; an++)
                        mma_bf16(acc[am * 4 + an], afr[am], bfr[an]);
            }
        }
        __syncthreads();
    }
#undef NT_LOAD_CHUNK

    float* C = g_scratch + cOff;
    const float* R = g_scratch + rOff;
    __nv_bfloat16* SH = (__nv_bfloat16*)(g_scratch + sHiOff);
    __nv_bfloat16* SL = (__nv_bfloat16*)(g_scratch + sLoOff);
    int gid = lid >> 2, tig = lid & 3;
    #pragma unroll
    for (int am = 0; am < 2; am++) {
        #pragma unroll
        for (int an = 0; an < 4; an++) {
            float d0 = acc[am * 4 + an][0], d1 = acc[am * 4 + an][1];
            float d2 = acc[am * 4 + an][2], d3 = acc[am * 4 + an][3];
            long long rowA = bm + m_base + am * 16 + gid;
            long long rowB = rowA + 8;
            long long col = bn + n_base + an * 8 + tig * 2;
            if (flags & 1) { float b0 = bias[col], b1 = bias[col + 1];
                             d0 += b0; d1 += b1; d2 += b0; d3 += b1; }
            if (flags & 4) {
                d0 = 0.5f * d0 * (1.0f + erff(d0 * 0.7071067811865476f));
                d1 = 0.5f * d1 * (1.0f + erff(d1 * 0.7071067811865476f));
                d2 = 0.5f * d2 * (1.0f + erff(d2 * 0.7071067811865476f));
                d3 = 0.5f * d3 * (1.0f + erff(d3 * 0.7071067811865476f));
            }
            if (flags & 2) {
                d0 += R[rowA * ldc + col]; d1 += R[rowA * ldc + col + 1];
                d2 += R[rowB * ldc + col]; d3 += R[rowB * ldc + col + 1];
            }
            if (!(flags & 16)) {
                *(float2*)(C + rowA * ldc + col) = make_float2(d0, d1);
                *(float2*)(C + rowB * ldc + col) = make_float2(d2, d3);
            }
            if (flags & 8) {
                __nv_bfloat16 h0, l0, h1, l1, h2, l2, h3, l3;
                split_bf16(d0, h0, l0); split_bf16(d1, h1, l1);
                split_bf16(d2, h2, l2); split_bf16(d3, h3, l3);
                __nv_bfloat162 ph0; ph0.x = h0; ph0.y = h1;
                __nv_bfloat162 pl0; pl0.x = l0; pl0.y = l1;
                __nv_bfloat162 ph1; ph1.x = h2; ph1.y = h3;
                __nv_bfloat162 pl1; pl1.x = l2; pl1.y = l3;
                *(__nv_bfloat162*)(SH + rowA * ldc + col) = ph0;
                *(__nv_bfloat162*)(SL + rowA * ldc + col) = pl0;
                *(__nv_bfloat162*)(SH + rowB * ldc + col) = ph1;
                *(__nv_bfloat162*)(SL + rowB * ldc + col) = pl1;
            }
        }
    }
}

// ---------------------------------------------------------------------------
extern "C" void kernel_launch(void* const* d_in, const int* in_sizes, int n_in,
                              void* d_out, int out_size)
{
    (void)in_sizes; (void)n_in;
    const float* x      = (const float*)d_in[0];
    const float* qkv_w  = (const float*)d_in[1];
    const float* q2_w   = (const float*)d_in[2];
    const float* kv2_w  = (const float*)d_in[3];
    const float* proj_w = (const float*)d_in[4];
    const float* proj_b = (const float*)d_in[5];
    const float* ln1_g  = (const float*)d_in[6];
    const float* ln1_b  = (const float*)d_in[7];
    const float* ln2_g  = (const float*)d_in[8];
    const float* ln2_b  = (const float*)d_in[9];
    const float* fc1_w  = (const float*)d_in[10];
    const float* fc1_b  = (const float*)d_in[11];
    const float* fc2_w  = (const float*)d_in[12];
    const float* fc2_b  = (const float*)d_in[13];
    float* out = (float*)d_out;

    cudaFuncSetAttribute(mma_lg_kernel,
                         cudaFuncAttributeMaxDynamicSharedMemorySize, MMA_SMEM_BYTES);
    cudaFuncSetAttribute(mma_o_kernel,
                         cudaFuncAttributeMaxDynamicSharedMemorySize, MMAO_SMEM_BYTES);
    cudaFuncSetAttribute(mma_nt_kernel,
                         cudaFuncAttributeMaxDynamicSharedMemorySize, MMANT_SMEM_BYTES);
    cudaFuncSetAttribute(mma_nt64_kernel,
                         cudaFuncAttributeMaxDynamicSharedMemorySize, MMA_SMEM_BYTES);

    // all six weight transpose-splits, one launch
    cvt_weights_kernel<<<540, 256>>>(qkv_w, kv2_w, q2_w, proj_w, fc1_w, fc2_w);

    pool_kernel<<<1536, 256>>>(x);
    // LN1 -> xn bf16 splits (XD region)
    ln_kernel<<<1024, 384>>>(OFF_TOK, ln1_g, ln1_b, OFF_XD, OFF_XD + 196608);

    // qkv mma: fp32 -> QKV, bf16 splits -> LG region   (grid 18 x 8 = 144)
    mma_nt_kernel<<<dim3(18, 8), 256, MMANT_SMEM_BYTES>>>(
        OFF_XD, OFF_XD + 196608, OFF_QKVWT, OFF_QKVWT + 221184,
        nullptr, 0, OFF_QKV, OFF_LG, OFF_LG + 589824, 384, 1152, 8);

    // qk[h] = q_h @ k_h^T  (6 heads in z)
    mma_nt64_kernel<<<dim3(8, 8, 6), 256, MMA_SMEM_BYTES>>>(
        OFF_LG, OFF_LG + 589824, 1152, 0, 64,
        OFF_LG, OFF_LG + 589824, 1152, 384, 64,
        OFF_QK, 1024, 1048576);

    // VW[h'] = v_h' @ kv2_w[h' slice]  (6 heads in z)
    mma_nt64_kernel<<<dim3(6, 8, 6), 256, MMA_SMEM_BYTES>>>(
        OFF_LG, OFF_LG + 589824, 1152, 768, 64,
        OFF_KV2WT, OFF_KV2WT + 147456, 384, 0, 64,
        OFF_VW, 768, 786432);

    ta_kernel<<<6144, 256>>>();
    // x_diag -> bf16 splits (XD region, xn splits now dead)
    xdiag_kernel<<<1024, 384>>>();

    // q2 = x_diag @ (SCALE*q2_w): splits only -> XN region (grid 6 x 8)
    mma_nt_kernel<<<dim3(6, 8), 256, MMANT_SMEM_BYTES>>>(
        OFF_XD, OFF_XD + 196608, OFF_Q2WT, OFF_Q2WT + 73728,
        nullptr, 0, 0, OFF_XN, OFF_XN + 196608, 384, 384, 8 | 16);

    // VWk splits -> QKV/MLP regions; VWv transposed splits
    cvt_split_kernel<<<9216, 256>>>(OFF_VW, 768, 384, OFF_QKV, OFF_MLP);
    cvt_vwt_kernel<<<dim3(96, 6), 256>>>();

    int wout = (out_size >= 3145728) ? 1 : 0;

    // stage 2 in 3 groups of 2 heads
    for (int g = 0; g < 3; g++) {
        mma_lg_kernel<<<dim3(48, 8, 2), 256, MMA_SMEM_BYTES>>>(g);
        middle_kernel<<<dim3(1024, 2), 256>>>(g, out + 1572864, wout);
        mma_o_kernel<<<dim3(12, 8, 2), 256, MMAO_SMEM_BYTES>>>(g);
        oreduce_kernel<<<512, 256>>>(g);
    }

    // h1 = tok + (o @ proj_w + proj_b)   (grid 6 x 8)
    mma_nt_kernel<<<dim3(6, 8), 256, MMANT_SMEM_BYTES>>>(
        OFF_O, OFF_O + 196608, OFF_PROJWT, OFF_PROJWT + 73728,
        proj_b, OFF_TOK, OFF_H1, 0, 0, 384, 384, 1 | 2);

    // LN2 -> hn bf16 splits (XD region, xd splits now dead)
    ln_kernel<<<1024, 384>>>(OFF_H1, ln2_g, ln2_b, OFF_XD, OFF_XD + 196608);

    // fc1: bias+gelu, splits only -> QK region   (grid 24 x 8 = 192)
    mma_nt_kernel<<<dim3(24, 8), 256, MMANT_SMEM_BYTES>>>(
        OFF_XD, OFF_XD + 196608, OFF_FC1WT, OFF_FC1WT + 294912,
        fc1_b, 0, 0, OFF_QK + 589824, OFF_QK + 1376256, 384, 1536, 1 | 4 | 8 | 16);

    // fc2: bias + residual(H1) -> H2 fp32   (grid 6 x 8)
    mma_nt_kernel<<<dim3(6, 8), 256, MMANT_SMEM_BYTES>>>(
        OFF_QK + 589824, OFF_QK + 1376256, OFF_FC2WT, OFF_FC2WT + 294912,
        fc2_b, OFF_H1, OFF_H2, 0, 0, 1536, 384, 1 | 2);

    upsample_kernel<<<1536, 256>>>(out, out_size);
}